// round 8
// baseline (speedup 1.0000x reference)
#include <cuda_runtime.h>
#include <math.h>
#include <stdint.h>

#define LAYERS 6
#define BATCH  4
#define SEQ    512
#define DIM    1024
#define HEADS  16
#define DHEAD  64
#define FFN    4096
#define TOKENS (BATCH*SEQ)          // 2048
#define ID     (HEADS*DHEAD)        // 1024

// ---------------- scratch (allocation-guard safe) ----------------
__device__ float g_h  [TOKENS*DIM];
__device__ float g_qkv[TOKENS*3*ID];
__device__ float g_o  [TOKENS*ID];
__device__ float g_a  [(size_t)TOKENS*FFN];

// ---------------- small PTX helpers ----------------
__device__ __forceinline__ uint32_t smem_u32(const void* p) {
    uint32_t a;
    asm("{ .reg .u64 t; cvta.to.shared.u64 t, %1; cvt.u32.u64 %0, t; }" : "=r"(a) : "l"(p));
    return a;
}
__device__ __forceinline__ void cp16(uint32_t dst, const void* src) {
    asm volatile("cp.async.cg.shared.global [%0], [%1], 16;" :: "r"(dst), "l"(src));
}
__device__ __forceinline__ void cp_commit() {
    asm volatile("cp.async.commit_group;" ::: "memory");
}
template<int N> __device__ __forceinline__ void cp_wait() {
    asm volatile("cp.async.wait_group %0;" :: "n"(N) : "memory");
}
__device__ __forceinline__ uint32_t f2tf(float x) {
    uint32_t u; asm("cvt.rna.tf32.f32 %0, %1;" : "=r"(u) : "f"(x)); return u;
}
__device__ __forceinline__ float tf32r(float x) { return __uint_as_float(f2tf(x)); }
__device__ __forceinline__ void mma_tf32(float* d, const uint32_t* a, const uint32_t* b) {
    asm volatile(
        "mma.sync.aligned.m16n8k8.row.col.f32.tf32.tf32.f32 "
        "{%0,%1,%2,%3}, {%4,%5,%6,%7}, {%8,%9}, {%0,%1,%2,%3};"
        : "+f"(d[0]), "+f"(d[1]), "+f"(d[2]), "+f"(d[3])
        : "r"(a[0]), "r"(a[1]), "r"(a[2]), "r"(a[3]), "r"(b[0]), "r"(b[1]));
}

// ---------------- LayerNorm ----------------
__global__ __launch_bounds__(256) void ln_kernel(
    const float* __restrict__ x, const float* __restrict__ scale,
    const float* __restrict__ bias, float* __restrict__ out)
{
    __shared__ float wsum[8], wsq[8];
    int row = blockIdx.x, t = threadIdx.x;
    const float4* xr = (const float4*)(x + (size_t)row * DIM);
    float4 v = xr[t];
    float s  = v.x + v.y + v.z + v.w;
    float ss = v.x*v.x + v.y*v.y + v.z*v.z + v.w*v.w;
    #pragma unroll
    for (int o = 16; o; o >>= 1) {
        s  += __shfl_xor_sync(0xffffffffu, s,  o);
        ss += __shfl_xor_sync(0xffffffffu, ss, o);
    }
    if ((t & 31) == 0) { wsum[t >> 5] = s; wsq[t >> 5] = ss; }
    __syncthreads();
    float S = 0.f, SS = 0.f;
    #pragma unroll
    for (int i = 0; i < 8; i++) { S += wsum[i]; SS += wsq[i]; }
    float mean = S * (1.0f / DIM);
    float var  = SS * (1.0f / DIM) - mean * mean;
    float rstd = rsqrtf(var + 1e-5f);
    float4 sc = ((const float4*)scale)[t];
    float4 bi = ((const float4*)bias)[t];
    float4 o4;
    o4.x = (v.x - mean) * rstd * sc.x + bi.x;
    o4.y = (v.y - mean) * rstd * sc.y + bi.y;
    o4.z = (v.z - mean) * rstd * sc.z + bi.z;
    o4.w = (v.w - mean) * rstd * sc.w + bi.w;
    ((float4*)(out + (size_t)row * DIM))[t] = o4;
}

// ---------------- tf32 mma.sync GEMM (BM=BN=128, 3 stages, 2 CTA/SM) ----------------
// C[M,N] = A[M,K] @ B[K,N]
// EPI 0: C = acc
// EPI 1 (SPLITK>1): atomicAdd(C, acc [+bias if z==0]); C pre-holds residual
// EPI 2: C = gelu(acc + bias)
#define STAGES 3
#define APAD 20
#define BPAD 136
#define A_ST (128*APAD)
#define B_ST (16*BPAD)
#define ST_FLOATS (A_ST + B_ST)          // 4736
#define GEMM_SMEM (STAGES * ST_FLOATS * 4)   // 56832 B

__device__ __forceinline__ float gelu_exact(float v) {
    return 0.5f * v * (1.0f + erff(v * 0.70710678118654752f));
}

template<int EPI, int SPLITK>
__global__ __launch_bounds__(256, 2)
void tc_gemm(const float* __restrict__ A, const float* __restrict__ B,
             const float* __restrict__ bias, const float* __restrict__ resid,
             float* __restrict__ C, int N, int K)
{
    extern __shared__ float smf[];
    const uint32_t sb = smem_u32(smf);
    const int tid  = threadIdx.x;
    const int lane = tid & 31, wid = tid >> 5;
    const int wm = wid & 1, wn = wid >> 1;
    const int m0 = blockIdx.y * 128;
    const int n0 = blockIdx.x * 128;
    const int Klocal = K / SPLITK;
    const int kbase  = blockIdx.z * Klocal;

    auto fill = [&](int s, int k0) {
        uint32_t ab = sb + (uint32_t)(s * ST_FLOATS) * 4;
        uint32_t bb = ab + A_ST * 4;
        #pragma unroll
        for (int it = 0; it < 2; it++) {              // A: 128 rows x 16
            int idx = it * 256 + tid;
            int r = idx >> 2, sg = idx & 3;
            cp16(ab + (uint32_t)(r * APAD + sg * 4) * 4,
                 A + (size_t)(m0 + r) * K + kbase + k0 + sg * 4);
        }
        #pragma unroll
        for (int it = 0; it < 2; it++) {              // B: 16 rows x 128
            int idx = it * 256 + tid;
            int kk = idx >> 5, sg = idx & 31;
            cp16(bb + (uint32_t)(kk * BPAD + sg * 4) * 4,
                 B + (size_t)(kbase + k0 + kk) * N + n0 + sg * 4);
        }
    };

    float acc[4][4][4];
    #pragma unroll
    for (int i = 0; i < 4; i++)
        #pragma unroll
        for (int j = 0; j < 4; j++)
            #pragma unroll
            for (int q = 0; q < 4; q++) acc[i][j][q] = 0.f;

    const int NK = Klocal >> 4;

    fill(0, 0);  cp_commit();
    fill(1, 16); cp_commit();

    const int fr = lane >> 2, fc = lane & 3;
    int us = 0, fs = 2;

    for (int i = 0; i < NK; i++) {
        cp_wait<1>();
        __syncthreads();
        if (i + 2 < NK) fill(fs, (i + 2) * 16);
        cp_commit();

        const float* As = smf + us * ST_FLOATS;
        const float* Bs = As + A_ST;

        #pragma unroll
        for (int ks = 0; ks < 2; ks++) {
            uint32_t af[4][4], bf[4][2];
            #pragma unroll
            for (int mt = 0; mt < 4; mt++) {
                const float* ap = As + (wm * 64 + mt * 16 + fr) * APAD + ks * 8 + fc;
                af[mt][0] = f2tf(ap[0]);
                af[mt][1] = f2tf(ap[8 * APAD]);
                af[mt][2] = f2tf(ap[4]);
                af[mt][3] = f2tf(ap[8 * APAD + 4]);
            }
            #pragma unroll
            for (int nt = 0; nt < 4; nt++) {
                const float* bp = Bs + (ks * 8 + fc) * BPAD + wn * 32 + nt * 8 + fr;
                bf[nt][0] = f2tf(bp[0]);
                bf[nt][1] = f2tf(bp[4 * BPAD]);
            }
            #pragma unroll
            for (int mt = 0; mt < 4; mt++)
                #pragma unroll
                for (int nt = 0; nt < 4; nt++)
                    mma_tf32(acc[mt][nt], af[mt], bf[nt]);
        }
        __syncthreads();
        us = (us + 1 == STAGES) ? 0 : us + 1;
        fs = (fs + 1 == STAGES) ? 0 : fs + 1;
    }

    // ---- epilogue ----
    #pragma unroll
    for (int mt = 0; mt < 4; mt++) {
        int row = m0 + wm * 64 + mt * 16 + fr;
        #pragma unroll
        for (int nt = 0; nt < 4; nt++) {
            int col = n0 + wn * 32 + nt * 8 + fc * 2;
            float* d = acc[mt][nt];
            size_t i0 = (size_t)row * N + col;
            size_t i1 = (size_t)(row + 8) * N + col;
            if (SPLITK > 1) {
                float bx = 0.f, by = 0.f;
                if (blockIdx.z == 0) { bx = bias[col]; by = bias[col + 1]; }
                atomicAdd(C + i0,     d[0] + bx);
                atomicAdd(C + i0 + 1, d[1] + by);
                atomicAdd(C + i1,     d[2] + bx);
                atomicAdd(C + i1 + 1, d[3] + by);
            } else {
                float o0 = d[0], o1 = d[1], o2 = d[2], o3 = d[3];
                if (EPI == 1) {
                    float bx = bias[col], by = bias[col + 1];
                    o0 += bx + resid[i0]; o1 += by + resid[i0 + 1];
                    o2 += bx + resid[i1]; o3 += by + resid[i1 + 1];
                }
                if (EPI == 2) {
                    float bx = bias[col], by = bias[col + 1];
                    o0 = gelu_exact(o0 + bx); o1 = gelu_exact(o1 + by);
                    o2 = gelu_exact(o2 + bx); o3 = gelu_exact(o3 + by);
                }
                *(float2*)(C + i0) = make_float2(o0, o1);
                *(float2*)(C + i1) = make_float2(o2, o3);
            }
        }
    }
}

// ---------------- Flash attention with tf32 mma.sync (validated R6) ----------------
#define FA_PAD 72
#define FA_TILE (64*FA_PAD)
#define FA_SMEM (6*FA_TILE*4)      // 110592 B

__global__ __launch_bounds__(128) void fattn_kernel(
    const float* __restrict__ qkv, float* __restrict__ o)
{
    extern __shared__ float sm[];
    float* Qs = sm;                       // [64][72]
    float* Ps = Qs + FA_TILE;             // [64][72]
    float* Ks = Ps + FA_TILE;             // [2][64][72]
    float* Vs = Ks + 2*FA_TILE;           // [2][64][72]
    const uint32_t sb = smem_u32(sm);
    const uint32_t Qb = sb;
    const uint32_t Kb = sb + (uint32_t)(2*FA_TILE)*4;
    const uint32_t Vb = sb + (uint32_t)(4*FA_TILE)*4;

    const int tid = threadIdx.x, lane = tid & 31, w = tid >> 5;
    const int fr = lane >> 2, fc = lane & 3;
    const int bh = blockIdx.y;
    const int b = bh >> 4, h = bh & 15;
    const int q0 = blockIdx.x * 64;

    const float* qbase = qkv + (size_t)(b * SEQ) * (3 * ID) + h * DHEAD;
    const float* kbase = qbase + ID;
    const float* vbase = qbase + 2 * ID;

    #pragma unroll
    for (int it = 0; it < 8; it++) {
        int idx = it * 128 + tid;
        int r = idx >> 4, s4 = idx & 15;
        cp16(Qb + (uint32_t)(r * FA_PAD + s4 * 4) * 4,
             qbase + (size_t)(q0 + r) * 3072 + s4 * 4);
    }
    auto fillKV = [&](int c, int buf) {
        #pragma unroll
        for (int it = 0; it < 8; it++) {
            int idx = it * 128 + tid;
            int r = idx >> 4, s4 = idx & 15;
            cp16(Kb + (uint32_t)((buf * 64 + r) * FA_PAD + s4 * 4) * 4,
                 kbase + (size_t)(c * 64 + r) * 3072 + s4 * 4);
            cp16(Vb + (uint32_t)((buf * 64 + r) * FA_PAD + s4 * 4) * 4,
                 vbase + (size_t)(c * 64 + r) * 3072 + s4 * 4);
        }
    };
    fillKV(0, 0); cp_commit();

    float accO[8][4];
    #pragma unroll
    for (int nt = 0; nt < 8; nt++)
        #pragma unroll
        for (int q = 0; q < 4; q++) accO[nt][q] = 0.f;
    float M0 = -1e30f, M1 = -1e30f, L0 = 0.f, L1 = 0.f;

    const float* Prow0 = Ps + (w * 16 + fr) * FA_PAD;
    const int prow0_off = (w * 16 + fr) * FA_PAD;

    for (int c = 0; c < SEQ / 64; c++) {
        cp_wait<0>();
        __syncthreads();
        if (c + 1 < SEQ / 64) { fillKV(c + 1, (c + 1) & 1); cp_commit(); }

        const float* Kc = Ks + (c & 1) * FA_TILE;
        const float* Vc = Vs + (c & 1) * FA_TILE;

        float sacc[8][4];
        #pragma unroll
        for (int nt = 0; nt < 8; nt++)
            #pragma unroll
            for (int q = 0; q < 4; q++) sacc[nt][q] = 0.f;
        #pragma unroll
        for (int ks = 0; ks < 8; ks++) {
            uint32_t af[4];
            const float* qp = Qs + (w * 16 + fr) * FA_PAD + ks * 8 + fc;
            af[0] = f2tf(qp[0]);
            af[1] = f2tf(qp[8 * FA_PAD]);
            af[2] = f2tf(qp[4]);
            af[3] = f2tf(qp[8 * FA_PAD + 4]);
            #pragma unroll
            for (int nt = 0; nt < 8; nt++) {
                const float* kp = Kc + (nt * 8 + fr) * FA_PAD + ks * 8 + fc;
                uint32_t bf[2] = { f2tf(kp[0]), f2tf(kp[4]) };
                mma_tf32(sacc[nt], af, bf);
            }
        }

        float mx0 = -1e30f, mx1 = -1e30f;
        #pragma unroll
        for (int nt = 0; nt < 8; nt++) {
            sacc[nt][0] *= 0.125f; sacc[nt][1] *= 0.125f;
            sacc[nt][2] *= 0.125f; sacc[nt][3] *= 0.125f;
            mx0 = fmaxf(mx0, fmaxf(sacc[nt][0], sacc[nt][1]));
            mx1 = fmaxf(mx1, fmaxf(sacc[nt][2], sacc[nt][3]));
        }
        mx0 = fmaxf(mx0, __shfl_xor_sync(0xffffffffu, mx0, 1));
        mx0 = fmaxf(mx0, __shfl_xor_sync(0xffffffffu, mx0, 2));
        mx1 = fmaxf(mx1, __shfl_xor_sync(0xffffffffu, mx1, 1));
        mx1 = fmaxf(mx1, __shfl_xor_sync(0xffffffffu, mx1, 2));
        float Mn0 = fmaxf(M0, mx0), Mn1 = fmaxf(M1, mx1);
        float a0 = __expf(M0 - Mn0), a1 = __expf(M1 - Mn1);
        float s0 = 0.f, s1 = 0.f;
        #pragma unroll
        for (int nt = 0; nt < 8; nt++) {
            float p0 = __expf(sacc[nt][0] - Mn0), p1 = __expf(sacc[nt][1] - Mn0);
            float p2 = __expf(sacc[nt][2] - Mn1), p3 = __expf(sacc[nt][3] - Mn1);
            s0 += p0 + p1; s1 += p2 + p3;
            *(float2*)(Ps + prow0_off + nt * 8 + 2 * fc) =
                make_float2(tf32r(p0), tf32r(p1));
            *(float2*)(Ps + prow0_off + 8 * FA_PAD + nt * 8 + 2 * fc) =
                make_float2(tf32r(p2), tf32r(p3));
            accO[nt][0] *= a0; accO[nt][1] *= a0;
            accO[nt][2] *= a1; accO[nt][3] *= a1;
        }
        s0 += __shfl_xor_sync(0xffffffffu, s0, 1);
        s0 += __shfl_xor_sync(0xffffffffu, s0, 2);
        s1 += __shfl_xor_sync(0xffffffffu, s1, 1);
        s1 += __shfl_xor_sync(0xffffffffu, s1, 2);
        L0 = L0 * a0 + s0; L1 = L1 * a1 + s1;
        M0 = Mn0; M1 = Mn1;
        __syncwarp();

        #pragma unroll
        for (int ks = 0; ks < 8; ks++) {
            uint32_t af[4];
            const float* pp = Prow0 + ks * 8 + fc;
            af[0] = __float_as_uint(pp[0]);
            af[1] = __float_as_uint(pp[8 * FA_PAD]);
            af[2] = __float_as_uint(pp[4]);
            af[3] = __float_as_uint(pp[8 * FA_PAD + 4]);
            #pragma unroll
            for (int nt = 0; nt < 8; nt++) {
                const float* vp = Vc + (ks * 8 + fc) * FA_PAD + nt * 8 + fr;
                uint32_t bf[2] = { f2tf(vp[0]), f2tf(vp[4 * FA_PAD]) };
                mma_tf32(accO[nt], af, bf);
            }
        }
    }

    float inv0 = 1.0f / L0, inv1 = 1.0f / L1;
    size_t t0 = (size_t)(b * SEQ + q0 + w * 16 + fr);
    #pragma unroll
    for (int nt = 0; nt < 8; nt++) {
        int col = h * DHEAD + nt * 8 + 2 * fc;
        *(float2*)(o + t0 * ID + col) =
            make_float2(accO[nt][0] * inv0, accO[nt][1] * inv0);
        *(float2*)(o + (t0 + 8) * ID + col) =
            make_float2(accO[nt][2] * inv1, accO[nt][3] * inv1);
    }
}

// ---------------- driver ----------------
extern "C" void kernel_launch(void* const* d_in, const int* in_sizes, int n_in,
                              void* d_out, int out_size)
{
    const float* x_in = (const float*)d_in[0];
    const float* ln1s = (const float*)d_in[1];
    const float* ln1b = (const float*)d_in[2];
    const float* wqkv = (const float*)d_in[3];
    const float* wout = (const float*)d_in[4];
    const float* bout = (const float*)d_in[5];
    const float* ln2s = (const float*)d_in[6];
    const float* ln2b = (const float*)d_in[7];
    const float* w1   = (const float*)d_in[8];
    const float* b1   = (const float*)d_in[9];
    const float* w2   = (const float*)d_in[10];
    const float* b2   = (const float*)d_in[11];
    float* x = (float*)d_out;

    void* p;
    cudaGetSymbolAddress(&p, g_h);   float* gh   = (float*)p;
    cudaGetSymbolAddress(&p, g_qkv); float* gqkv = (float*)p;
    cudaGetSymbolAddress(&p, g_o);   float* go   = (float*)p;
    cudaGetSymbolAddress(&p, g_a);   float* ga   = (float*)p;

    cudaFuncSetAttribute(tc_gemm<0,1>, cudaFuncAttributeMaxDynamicSharedMemorySize, GEMM_SMEM);
    cudaFuncSetAttribute(tc_gemm<2,1>, cudaFuncAttributeMaxDynamicSharedMemorySize, GEMM_SMEM);
    cudaFuncSetAttribute(tc_gemm<1,2>, cudaFuncAttributeMaxDynamicSharedMemorySize, GEMM_SMEM);
    cudaFuncSetAttribute(fattn_kernel, cudaFuncAttributeMaxDynamicSharedMemorySize, FA_SMEM);

    cudaMemcpyAsync(x, x_in, (size_t)TOKENS * DIM * sizeof(float),
                    cudaMemcpyDeviceToDevice);

    for (int l = 0; l < LAYERS; l++) {
        const float* l1s = ln1s + l * DIM;
        const float* l1b = ln1b + l * DIM;
        const float* wq  = wqkv + (size_t)l * DIM * (3 * ID);
        const float* wo  = wout + (size_t)l * ID * DIM;
        const float* bo  = bout + l * DIM;
        const float* l2s = ln2s + l * DIM;
        const float* l2b = ln2b + l * DIM;
        const float* w1l = w1 + (size_t)l * DIM * FFN;
        const float* b1l = b1 + l * FFN;
        const float* w2l = w2 + (size_t)l * FFN * DIM;
        const float* b2l = b2 + l * DIM;

        // h = LN1(x)
        ln_kernel<<<TOKENS, 256>>>(x, l1s, l1b, gh);
        // qkv = h @ wqkv
        tc_gemm<0,1><<<dim3(3 * ID / 128, TOKENS / 128, 1), 256, GEMM_SMEM>>>(
            gh, wq, nullptr, nullptr, gqkv, 3 * ID, DIM);
        // attention (tf32 flash)
        fattn_kernel<<<dim3(SEQ / 64, BATCH * HEADS), 128, FA_SMEM>>>(gqkv, go);
        // x += o @ wo + bo   (split-K=2, atomic into residual-holding x)
        tc_gemm<1,2><<<dim3(DIM / 128, TOKENS / 128, 2), 256, GEMM_SMEM>>>(
            go, wo, bo, nullptr, x, DIM, ID);
        // h = LN2(x)
        ln_kernel<<<TOKENS, 256>>>(x, l2s, l2b, gh);
        // a = gelu(h @ w1 + b1)
        tc_gemm<2,1><<<dim3(FFN / 128, TOKENS / 128, 1), 256, GEMM_SMEM>>>(
            gh, w1l, b1l, nullptr, ga, FFN, DIM);
        // x += a @ w2 + b2   (split-K=2, atomic)
        tc_gemm<1,2><<<dim3(DIM / 128, TOKENS / 128, 2), 256, GEMM_SMEM>>>(
            ga, w2l, b2l, nullptr, x, DIM, FFN);
    }
}

// round 9
// speedup vs baseline: 1.3948x; 1.3948x over previous
#include <cuda_runtime.h>
#include <math.h>
#include <stdint.h>

#define LAYERS 6
#define BATCH  4
#define SEQ    512
#define DIM    1024
#define HEADS  16
#define DHEAD  64
#define FFN    4096
#define TOKENS (BATCH*SEQ)          // 2048
#define ID     (HEADS*DHEAD)        // 1024

// ---------------- scratch (allocation-guard safe) ----------------
__device__ float g_h  [TOKENS*DIM];
__device__ float g_qkv[TOKENS*3*ID];
__device__ float g_o  [TOKENS*ID];
__device__ float g_a  [(size_t)TOKENS*FFN];

// ---------------- small PTX helpers ----------------
__device__ __forceinline__ uint32_t smem_u32(const void* p) {
    uint32_t a;
    asm("{ .reg .u64 t; cvta.to.shared.u64 t, %1; cvt.u32.u64 %0, t; }" : "=r"(a) : "l"(p));
    return a;
}
__device__ __forceinline__ void cp16(uint32_t dst, const void* src) {
    asm volatile("cp.async.cg.shared.global [%0], [%1], 16;" :: "r"(dst), "l"(src));
}
__device__ __forceinline__ void cp_commit() {
    asm volatile("cp.async.commit_group;" ::: "memory");
}
template<int N> __device__ __forceinline__ void cp_wait() {
    asm volatile("cp.async.wait_group %0;" :: "n"(N) : "memory");
}
__device__ __forceinline__ uint32_t f2tf(float x) {
    uint32_t u; asm("cvt.rna.tf32.f32 %0, %1;" : "=r"(u) : "f"(x)); return u;
}
__device__ __forceinline__ float tf32r(float x) { return __uint_as_float(f2tf(x)); }
__device__ __forceinline__ void mma_tf32(float* d, const uint32_t* a, const uint32_t* b) {
    asm volatile(
        "mma.sync.aligned.m16n8k8.row.col.f32.tf32.tf32.f32 "
        "{%0,%1,%2,%3}, {%4,%5,%6,%7}, {%8,%9}, {%0,%1,%2,%3};"
        : "+f"(d[0]), "+f"(d[1]), "+f"(d[2]), "+f"(d[3])
        : "r"(a[0]), "r"(a[1]), "r"(a[2]), "r"(a[3]), "r"(b[0]), "r"(b[1]));
}

// ---------------- LayerNorm ----------------
__global__ __launch_bounds__(256) void ln_kernel(
    const float* __restrict__ x, const float* __restrict__ scale,
    const float* __restrict__ bias, float* __restrict__ out)
{
    __shared__ float wsum[8], wsq[8];
    int row = blockIdx.x, t = threadIdx.x;
    const float4* xr = (const float4*)(x + (size_t)row * DIM);
    float4 v = xr[t];
    float s  = v.x + v.y + v.z + v.w;
    float ss = v.x*v.x + v.y*v.y + v.z*v.z + v.w*v.w;
    #pragma unroll
    for (int o = 16; o; o >>= 1) {
        s  += __shfl_xor_sync(0xffffffffu, s,  o);
        ss += __shfl_xor_sync(0xffffffffu, ss, o);
    }
    if ((t & 31) == 0) { wsum[t >> 5] = s; wsq[t >> 5] = ss; }
    __syncthreads();
    float S = 0.f, SS = 0.f;
    #pragma unroll
    for (int i = 0; i < 8; i++) { S += wsum[i]; SS += wsq[i]; }
    float mean = S * (1.0f / DIM);
    float var  = SS * (1.0f / DIM) - mean * mean;
    float rstd = rsqrtf(var + 1e-5f);
    float4 sc = ((const float4*)scale)[t];
    float4 bi = ((const float4*)bias)[t];
    float4 o4;
    o4.x = (v.x - mean) * rstd * sc.x + bi.x;
    o4.y = (v.y - mean) * rstd * sc.y + bi.y;
    o4.z = (v.z - mean) * rstd * sc.z + bi.z;
    o4.w = (v.w - mean) * rstd * sc.w + bi.w;
    ((float4*)(out + (size_t)row * DIM))[t] = o4;
}

// ---------------- tf32 mma.sync GEMM, BM=128 (R6-validated) ----------------
#define STAGES 4
#define APAD 20

__device__ __forceinline__ float gelu_exact(float v) {
    return 0.5f * v * (1.0f + erff(v * 0.70710678118654752f));
}

template<int BN, int EPI>
__global__ __launch_bounds__(256)
void tc_gemm(const float* __restrict__ A, const float* __restrict__ B,
             const float* __restrict__ bias, const float* __restrict__ resid,
             float* __restrict__ C, int N, int K)
{
    constexpr int BPAD = BN + 8;
    constexpr int A_ST = 128 * APAD;
    constexpr int B_ST = 16 * BPAD;
    constexpr int ST   = A_ST + B_ST;
    constexpr int WN   = BN / 4;
    constexpr int NT   = WN / 8;
    constexpr int BIT  = BN / 64;

    extern __shared__ float smf[];
    const uint32_t sb = smem_u32(smf);
    const int tid  = threadIdx.x;
    const int lane = tid & 31, wid = tid >> 5;
    const int wm = wid & 1, wn = wid >> 1;
    const int m0 = blockIdx.y * 128;
    const int n0 = blockIdx.x * BN;

    auto fill = [&](int s, int k0) {
        uint32_t ab = sb + (uint32_t)(s * ST) * 4;
        uint32_t bb = ab + A_ST * 4;
        #pragma unroll
        for (int it = 0; it < 2; it++) {
            int idx = it * 256 + tid;
            int r = idx >> 2, sg = idx & 3;
            cp16(ab + (uint32_t)(r * APAD + sg * 4) * 4,
                 A + (size_t)(m0 + r) * K + k0 + sg * 4);
        }
        #pragma unroll
        for (int it = 0; it < BIT; it++) {
            int idx = it * 256 + tid;
            int kk = idx / (BN / 4), sg = idx % (BN / 4);
            cp16(bb + (uint32_t)(kk * BPAD + sg * 4) * 4,
                 B + (size_t)(k0 + kk) * N + n0 + sg * 4);
        }
    };

    float acc[4][NT][4];
    #pragma unroll
    for (int i = 0; i < 4; i++)
        #pragma unroll
        for (int j = 0; j < NT; j++)
            #pragma unroll
            for (int q = 0; q < 4; q++) acc[i][j][q] = 0.f;

    const int NK = K >> 4;

    #pragma unroll
    for (int p = 0; p < STAGES - 1; p++) { fill(p, p * 16); cp_commit(); }

    const int fr = lane >> 2, fc = lane & 3;

    for (int i = 0; i < NK; i++) {
        cp_wait<STAGES - 2>();
        __syncthreads();
        if (i + STAGES - 1 < NK) fill((i + STAGES - 1) & (STAGES - 1), (i + STAGES - 1) * 16);
        cp_commit();

        const float* As = smf + (i & (STAGES - 1)) * ST;
        const float* Bs = As + A_ST;

        #pragma unroll
        for (int ks = 0; ks < 2; ks++) {
            uint32_t af[4][4], bf[NT][2];
            #pragma unroll
            for (int mt = 0; mt < 4; mt++) {
                const float* ap = As + (wm * 64 + mt * 16 + fr) * APAD + ks * 8 + fc;
                af[mt][0] = f2tf(ap[0]);
                af[mt][1] = f2tf(ap[8 * APAD]);
                af[mt][2] = f2tf(ap[4]);
                af[mt][3] = f2tf(ap[8 * APAD + 4]);
            }
            #pragma unroll
            for (int nt = 0; nt < NT; nt++) {
                const float* bp = Bs + (ks * 8 + fc) * BPAD + wn * WN + nt * 8 + fr;
                bf[nt][0] = f2tf(bp[0]);
                bf[nt][1] = f2tf(bp[4 * BPAD]);
            }
            #pragma unroll
            for (int mt = 0; mt < 4; mt++)
                #pragma unroll
                for (int nt = 0; nt < NT; nt++)
                    mma_tf32(acc[mt][nt], af[mt], bf[nt]);
        }
        __syncthreads();
    }

    #pragma unroll
    for (int mt = 0; mt < 4; mt++) {
        int row = m0 + wm * 64 + mt * 16 + fr;
        #pragma unroll
        for (int nt = 0; nt < NT; nt++) {
            int col = n0 + wn * WN + nt * 8 + fc * 2;
            float* d = acc[mt][nt];
            size_t i0 = (size_t)row * N + col;
            size_t i1 = (size_t)(row + 8) * N + col;
            float o0 = d[0], o1 = d[1], o2 = d[2], o3 = d[3];
            if (EPI == 1) {
                float bx = bias[col], by = bias[col + 1];
                o0 += bx + resid[i0]; o1 += by + resid[i0 + 1];
                o2 += bx + resid[i1]; o3 += by + resid[i1 + 1];
            }
            if (EPI == 2) {
                float bx = bias[col], by = bias[col + 1];
                o0 = gelu_exact(o0 + bx); o1 = gelu_exact(o1 + by);
                o2 = gelu_exact(o2 + bx); o3 = gelu_exact(o3 + by);
            }
            *(float2*)(C + i0) = make_float2(o0, o1);
            *(float2*)(C + i1) = make_float2(o2, o3);
        }
    }
}

// ---------------- BM=64/BN=128 GEMM, 2 CTA/SM (for N=1024 GEMMs) ----------------
// grid (N/128, M/64) = (8, 32) = 256 CTAs. 8 warps as 2x4, warp tile 32x32.
// EPI 1: C = acc + bias + resid  (in-place safe)
#define G64_BPAD 136
#define G64_A_ST (64*APAD)                       // 1280
#define G64_B_ST (16*G64_BPAD)                   // 2176
#define G64_ST   (G64_A_ST + G64_B_ST)           // 3456
#define G64_SMEM (STAGES * G64_ST * 4)           // 55296 B

__global__ __launch_bounds__(256, 2)
void tc_gemm64(const float* __restrict__ A, const float* __restrict__ B,
               const float* __restrict__ bias, const float* __restrict__ resid,
               float* __restrict__ C, int N, int K)
{
    extern __shared__ float smf[];
    const uint32_t sb = smem_u32(smf);
    const int tid  = threadIdx.x;
    const int lane = tid & 31, wid = tid >> 5;
    const int wm = wid & 1, wn = wid >> 1;
    const int m0 = blockIdx.y * 64;
    const int n0 = blockIdx.x * 128;

    auto fill = [&](int s, int k0) {
        uint32_t ab = sb + (uint32_t)(s * G64_ST) * 4;
        uint32_t bb = ab + G64_A_ST * 4;
        {   // A: 64 rows x 16 cols = 256 float4
            int r = tid >> 2, sg = tid & 3;
            cp16(ab + (uint32_t)(r * APAD + sg * 4) * 4,
                 A + (size_t)(m0 + r) * K + k0 + sg * 4);
        }
        #pragma unroll
        for (int it = 0; it < 2; it++) {        // B: 16 rows x 128 cols
            int idx = it * 256 + tid;
            int kk = idx >> 5, sg = idx & 31;
            cp16(bb + (uint32_t)(kk * G64_BPAD + sg * 4) * 4,
                 B + (size_t)(k0 + kk) * N + n0 + sg * 4);
        }
    };

    float acc[2][4][4];
    #pragma unroll
    for (int i = 0; i < 2; i++)
        #pragma unroll
        for (int j = 0; j < 4; j++)
            #pragma unroll
            for (int q = 0; q < 4; q++) acc[i][j][q] = 0.f;

    const int NK = K >> 4;

    #pragma unroll
    for (int p = 0; p < STAGES - 1; p++) { fill(p, p * 16); cp_commit(); }

    const int fr = lane >> 2, fc = lane & 3;

    for (int i = 0; i < NK; i++) {
        cp_wait<STAGES - 2>();
        __syncthreads();
        if (i + STAGES - 1 < NK) fill((i + STAGES - 1) & (STAGES - 1), (i + STAGES - 1) * 16);
        cp_commit();

        const float* As = smf + (i & (STAGES - 1)) * G64_ST;
        const float* Bs = As + G64_A_ST;

        #pragma unroll
        for (int ks = 0; ks < 2; ks++) {
            uint32_t af[2][4], bf[4][2];
            #pragma unroll
            for (int mt = 0; mt < 2; mt++) {
                const float* ap = As + (wm * 32 + mt * 16 + fr) * APAD + ks * 8 + fc;
                af[mt][0] = f2tf(ap[0]);
                af[mt][1] = f2tf(ap[8 * APAD]);
                af[mt][2] = f2tf(ap[4]);
                af[mt][3] = f2tf(ap[8 * APAD + 4]);
            }
            #pragma unroll
            for (int nt = 0; nt < 4; nt++) {
                const float* bp = Bs + (ks * 8 + fc) * G64_BPAD + wn * 32 + nt * 8 + fr;
                bf[nt][0] = f2tf(bp[0]);
                bf[nt][1] = f2tf(bp[4 * G64_BPAD]);
            }
            #pragma unroll
            for (int mt = 0; mt < 2; mt++)
                #pragma unroll
                for (int nt = 0; nt < 4; nt++)
                    mma_tf32(acc[mt][nt], af[mt], bf[nt]);
        }
        __syncthreads();
    }

    #pragma unroll
    for (int mt = 0; mt < 2; mt++) {
        int row = m0 + wm * 32 + mt * 16 + fr;
        #pragma unroll
        for (int nt = 0; nt < 4; nt++) {
            int col = n0 + wn * 32 + nt * 8 + fc * 2;
            float* d = acc[mt][nt];
            size_t i0 = (size_t)row * N + col;
            size_t i1 = (size_t)(row + 8) * N + col;
            float bx = bias[col], by = bias[col + 1];
            float o0 = d[0] + bx + resid[i0];
            float o1 = d[1] + by + resid[i0 + 1];
            float o2 = d[2] + bx + resid[i1];
            float o3 = d[3] + by + resid[i1 + 1];
            *(float2*)(C + i0) = make_float2(o0, o1);
            *(float2*)(C + i1) = make_float2(o2, o3);
        }
    }
}

// ---------------- Flash attention with tf32 mma.sync (validated R6) ----------------
#define FA_PAD 72
#define FA_TILE (64*FA_PAD)
#define FA_SMEM (6*FA_TILE*4)      // 110592 B

__global__ __launch_bounds__(128) void fattn_kernel(
    const float* __restrict__ qkv, float* __restrict__ o)
{
    extern __shared__ float sm[];
    float* Qs = sm;                       // [64][72]
    float* Ps = Qs + FA_TILE;             // [64][72]
    float* Ks = Ps + FA_TILE;             // [2][64][72]
    float* Vs = Ks + 2*FA_TILE;           // [2][64][72]
    const uint32_t sb = smem_u32(sm);
    const uint32_t Qb = sb;
    const uint32_t Kb = sb + (uint32_t)(2*FA_TILE)*4;
    const uint32_t Vb = sb + (uint32_t)(4*FA_TILE)*4;

    const int tid = threadIdx.x, lane = tid & 31, w = tid >> 5;
    const int fr = lane >> 2, fc = lane & 3;
    const int bh = blockIdx.y;
    const int b = bh >> 4, h = bh & 15;
    const int q0 = blockIdx.x * 64;

    const float* qbase = qkv + (size_t)(b * SEQ) * (3 * ID) + h * DHEAD;
    const float* kbase = qbase + ID;
    const float* vbase = qbase + 2 * ID;

    #pragma unroll
    for (int it = 0; it < 8; it++) {
        int idx = it * 128 + tid;
        int r = idx >> 4, s4 = idx & 15;
        cp16(Qb + (uint32_t)(r * FA_PAD + s4 * 4) * 4,
             qbase + (size_t)(q0 + r) * 3072 + s4 * 4);
    }
    auto fillKV = [&](int c, int buf) {
        #pragma unroll
        for (int it = 0; it < 8; it++) {
            int idx = it * 128 + tid;
            int r = idx >> 4, s4 = idx & 15;
            cp16(Kb + (uint32_t)((buf * 64 + r) * FA_PAD + s4 * 4) * 4,
                 kbase + (size_t)(c * 64 + r) * 3072 + s4 * 4);
            cp16(Vb + (uint32_t)((buf * 64 + r) * FA_PAD + s4 * 4) * 4,
                 vbase + (size_t)(c * 64 + r) * 3072 + s4 * 4);
        }
    };
    fillKV(0, 0); cp_commit();

    float accO[8][4];
    #pragma unroll
    for (int nt = 0; nt < 8; nt++)
        #pragma unroll
        for (int q = 0; q < 4; q++) accO[nt][q] = 0.f;
    float M0 = -1e30f, M1 = -1e30f, L0 = 0.f, L1 = 0.f;

    const float* Prow0 = Ps + (w * 16 + fr) * FA_PAD;
    const int prow0_off = (w * 16 + fr) * FA_PAD;

    for (int c = 0; c < SEQ / 64; c++) {
        cp_wait<0>();
        __syncthreads();
        if (c + 1 < SEQ / 64) { fillKV(c + 1, (c + 1) & 1); cp_commit(); }

        const float* Kc = Ks + (c & 1) * FA_TILE;
        const float* Vc = Vs + (c & 1) * FA_TILE;

        float sacc[8][4];
        #pragma unroll
        for (int nt = 0; nt < 8; nt++)
            #pragma unroll
            for (int q = 0; q < 4; q++) sacc[nt][q] = 0.f;
        #pragma unroll
        for (int ks = 0; ks < 8; ks++) {
            uint32_t af[4];
            const float* qp = Qs + (w * 16 + fr) * FA_PAD + ks * 8 + fc;
            af[0] = f2tf(qp[0]);
            af[1] = f2tf(qp[8 * FA_PAD]);
            af[2] = f2tf(qp[4]);
            af[3] = f2tf(qp[8 * FA_PAD + 4]);
            #pragma unroll
            for (int nt = 0; nt < 8; nt++) {
                const float* kp = Kc + (nt * 8 + fr) * FA_PAD + ks * 8 + fc;
                uint32_t bf[2] = { f2tf(kp[0]), f2tf(kp[4]) };
                mma_tf32(sacc[nt], af, bf);
            }
        }

        float mx0 = -1e30f, mx1 = -1e30f;
        #pragma unroll
        for (int nt = 0; nt < 8; nt++) {
            sacc[nt][0] *= 0.125f; sacc[nt][1] *= 0.125f;
            sacc[nt][2] *= 0.125f; sacc[nt][3] *= 0.125f;
            mx0 = fmaxf(mx0, fmaxf(sacc[nt][0], sacc[nt][1]));
            mx1 = fmaxf(mx1, fmaxf(sacc[nt][2], sacc[nt][3]));
        }
        mx0 = fmaxf(mx0, __shfl_xor_sync(0xffffffffu, mx0, 1));
        mx0 = fmaxf(mx0, __shfl_xor_sync(0xffffffffu, mx0, 2));
        mx1 = fmaxf(mx1, __shfl_xor_sync(0xffffffffu, mx1, 1));
        mx1 = fmaxf(mx1, __shfl_xor_sync(0xffffffffu, mx1, 2));
        float Mn0 = fmaxf(M0, mx0), Mn1 = fmaxf(M1, mx1);
        float a0 = __expf(M0 - Mn0), a1 = __expf(M1 - Mn1);
        float s0 = 0.f, s1 = 0.f;
        #pragma unroll
        for (int nt = 0; nt < 8; nt++) {
            float p0 = __expf(sacc[nt][0] - Mn0), p1 = __expf(sacc[nt][1] - Mn0);
            float p2 = __expf(sacc[nt][2] - Mn1), p3 = __expf(sacc[nt][3] - Mn1);
            s0 += p0 + p1; s1 += p2 + p3;
            *(float2*)(Ps + prow0_off + nt * 8 + 2 * fc) =
                make_float2(tf32r(p0), tf32r(p1));
            *(float2*)(Ps + prow0_off + 8 * FA_PAD + nt * 8 + 2 * fc) =
                make_float2(tf32r(p2), tf32r(p3));
            accO[nt][0] *= a0; accO[nt][1] *= a0;
            accO[nt][2] *= a1; accO[nt][3] *= a1;
        }
        s0 += __shfl_xor_sync(0xffffffffu, s0, 1);
        s0 += __shfl_xor_sync(0xffffffffu, s0, 2);
        s1 += __shfl_xor_sync(0xffffffffu, s1, 1);
        s1 += __shfl_xor_sync(0xffffffffu, s1, 2);
        L0 = L0 * a0 + s0; L1 = L1 * a1 + s1;
        M0 = Mn0; M1 = Mn1;
        __syncwarp();

        #pragma unroll
        for (int ks = 0; ks < 8; ks++) {
            uint32_t af[4];
            const float* pp = Prow0 + ks * 8 + fc;
            af[0] = __float_as_uint(pp[0]);
            af[1] = __float_as_uint(pp[8 * FA_PAD]);
            af[2] = __float_as_uint(pp[4]);
            af[3] = __float_as_uint(pp[8 * FA_PAD + 4]);
            #pragma unroll
            for (int nt = 0; nt < 8; nt++) {
                const float* vp = Vc + (ks * 8 + fc) * FA_PAD + nt * 8 + fr;
                uint32_t bf[2] = { f2tf(vp[0]), f2tf(vp[4 * FA_PAD]) };
                mma_tf32(accO[nt], af, bf);
            }
        }
    }

    float inv0 = 1.0f / L0, inv1 = 1.0f / L1;
    size_t t0 = (size_t)(b * SEQ + q0 + w * 16 + fr);
    #pragma unroll
    for (int nt = 0; nt < 8; nt++) {
        int col = h * DHEAD + nt * 8 + 2 * fc;
        *(float2*)(o + t0 * ID + col) =
            make_float2(accO[nt][0] * inv0, accO[nt][1] * inv0);
        *(float2*)(o + (t0 + 8) * ID + col) =
            make_float2(accO[nt][2] * inv1, accO[nt][3] * inv1);
    }
}

// ---------------- driver ----------------
extern "C" void kernel_launch(void* const* d_in, const int* in_sizes, int n_in,
                              void* d_out, int out_size)
{
    const float* x_in = (const float*)d_in[0];
    const float* ln1s = (const float*)d_in[1];
    const float* ln1b = (const float*)d_in[2];
    const float* wqkv = (const float*)d_in[3];
    const float* wout = (const float*)d_in[4];
    const float* bout = (const float*)d_in[5];
    const float* ln2s = (const float*)d_in[6];
    const float* ln2b = (const float*)d_in[7];
    const float* w1   = (const float*)d_in[8];
    const float* b1   = (const float*)d_in[9];
    const float* w2   = (const float*)d_in[10];
    const float* b2   = (const float*)d_in[11];
    float* x = (float*)d_out;

    void* p;
    cudaGetSymbolAddress(&p, g_h);   float* gh   = (float*)p;
    cudaGetSymbolAddress(&p, g_qkv); float* gqkv = (float*)p;
    cudaGetSymbolAddress(&p, g_o);   float* go   = (float*)p;
    cudaGetSymbolAddress(&p, g_a);   float* ga   = (float*)p;

    const int SM256 = STAGES * (128*APAD + 16*(256+8)) * 4;   // 108544
    cudaFuncSetAttribute(tc_gemm<256,0>, cudaFuncAttributeMaxDynamicSharedMemorySize, SM256);
    cudaFuncSetAttribute(tc_gemm<256,2>, cudaFuncAttributeMaxDynamicSharedMemorySize, SM256);
    cudaFuncSetAttribute(tc_gemm64, cudaFuncAttributeMaxDynamicSharedMemorySize, G64_SMEM);
    cudaFuncSetAttribute(fattn_kernel, cudaFuncAttributeMaxDynamicSharedMemorySize, FA_SMEM);

    cudaMemcpyAsync(x, x_in, (size_t)TOKENS * DIM * sizeof(float),
                    cudaMemcpyDeviceToDevice);

    for (int l = 0; l < LAYERS; l++) {
        const float* l1s = ln1s + l * DIM;
        const float* l1b = ln1b + l * DIM;
        const float* wq  = wqkv + (size_t)l * DIM * (3 * ID);
        const float* wo  = wout + (size_t)l * ID * DIM;
        const float* bo  = bout + l * DIM;
        const float* l2s = ln2s + l * DIM;
        const float* l2b = ln2b + l * DIM;
        const float* w1l = w1 + (size_t)l * DIM * FFN;
        const float* b1l = b1 + l * FFN;
        const float* w2l = w2 + (size_t)l * FFN * DIM;
        const float* b2l = b2 + l * DIM;

        // h = LN1(x)
        ln_kernel<<<TOKENS, 256>>>(x, l1s, l1b, gh);
        // qkv = h @ wqkv
        tc_gemm<256,0><<<dim3(3 * ID / 256, TOKENS / 128), 256, SM256>>>(
            gh, wq, nullptr, nullptr, gqkv, 3 * ID, DIM);
        // attention (tf32 flash)
        fattn_kernel<<<dim3(SEQ / 64, BATCH * HEADS), 128, FA_SMEM>>>(gqkv, go);
        // x = x + o @ wo + bo   (BM=64, 256 CTAs, 2/SM)
        tc_gemm64<<<dim3(DIM / 128, TOKENS / 64), 256, G64_SMEM>>>(
            go, wo, bo, x, x, DIM, ID);
        // h = LN2(x)
        ln_kernel<<<TOKENS, 256>>>(x, l2s, l2b, gh);
        // a = gelu(h @ w1 + b1)
        tc_gemm<256,2><<<dim3(FFN / 256, TOKENS / 128), 256, SM256>>>(
            gh, w1l, b1l, nullptr, ga, FFN, DIM);
        // x = x + a @ w2 + b2   (BM=64, 256 CTAs, 2/SM)
        tc_gemm64<<<dim3(DIM / 128, TOKENS / 64), 256, G64_SMEM>>>(
            ga, w2l, b2l, x, x, DIM, FFN);
    }
}

// round 10
// speedup vs baseline: 1.4647x; 1.0501x over previous
#include <cuda_runtime.h>
#include <math.h>
#include <stdint.h>

#define LAYERS 6
#define BATCH  4
#define SEQ    512
#define DIM    1024
#define HEADS  16
#define DHEAD  64
#define FFN    4096
#define TOKENS (BATCH*SEQ)          // 2048
#define ID     (HEADS*DHEAD)        // 1024

// ---------------- scratch (allocation-guard safe) ----------------
__device__ float g_h  [TOKENS*DIM];
__device__ float g_qkv[TOKENS*3*ID];
__device__ float g_o  [TOKENS*ID];
__device__ float g_a  [(size_t)TOKENS*FFN];

// ---------------- small PTX helpers ----------------
__device__ __forceinline__ uint32_t smem_u32(const void* p) {
    uint32_t a;
    asm("{ .reg .u64 t; cvta.to.shared.u64 t, %1; cvt.u32.u64 %0, t; }" : "=r"(a) : "l"(p));
    return a;
}
__device__ __forceinline__ void cp16(uint32_t dst, const void* src) {
    asm volatile("cp.async.cg.shared.global [%0], [%1], 16;" :: "r"(dst), "l"(src));
}
__device__ __forceinline__ void cp_commit() {
    asm volatile("cp.async.commit_group;" ::: "memory");
}
template<int N> __device__ __forceinline__ void cp_wait() {
    asm volatile("cp.async.wait_group %0;" :: "n"(N) : "memory");
}
__device__ __forceinline__ uint32_t f2tf(float x) {
    uint32_t u; asm("cvt.rna.tf32.f32 %0, %1;" : "=r"(u) : "f"(x)); return u;
}
__device__ __forceinline__ float tf32r(float x) { return __uint_as_float(f2tf(x)); }
__device__ __forceinline__ void mma_tf32(float* d, const uint32_t* a, const uint32_t* b) {
    asm volatile(
        "mma.sync.aligned.m16n8k8.row.col.f32.tf32.tf32.f32 "
        "{%0,%1,%2,%3}, {%4,%5,%6,%7}, {%8,%9}, {%0,%1,%2,%3};"
        : "+f"(d[0]), "+f"(d[1]), "+f"(d[2]), "+f"(d[3])
        : "r"(a[0]), "r"(a[1]), "r"(a[2]), "r"(a[3]), "r"(b[0]), "r"(b[1]));
}

// ---------------- LayerNorm ----------------
__global__ __launch_bounds__(256) void ln_kernel(
    const float* __restrict__ x, const float* __restrict__ scale,
    const float* __restrict__ bias, float* __restrict__ out)
{
    __shared__ float wsum[8], wsq[8];
    int row = blockIdx.x, t = threadIdx.x;
    const float4* xr = (const float4*)(x + (size_t)row * DIM);
    float4 v = xr[t];
    float s  = v.x + v.y + v.z + v.w;
    float ss = v.x*v.x + v.y*v.y + v.z*v.z + v.w*v.w;
    #pragma unroll
    for (int o = 16; o; o >>= 1) {
        s  += __shfl_xor_sync(0xffffffffu, s,  o);
        ss += __shfl_xor_sync(0xffffffffu, ss, o);
    }
    if ((t & 31) == 0) { wsum[t >> 5] = s; wsq[t >> 5] = ss; }
    __syncthreads();
    float S = 0.f, SS = 0.f;
    #pragma unroll
    for (int i = 0; i < 8; i++) { S += wsum[i]; SS += wsq[i]; }
    float mean = S * (1.0f / DIM);
    float var  = SS * (1.0f / DIM) - mean * mean;
    float rstd = rsqrtf(var + 1e-5f);
    float4 sc = ((const float4*)scale)[t];
    float4 bi = ((const float4*)bias)[t];
    float4 o4;
    o4.x = (v.x - mean) * rstd * sc.x + bi.x;
    o4.y = (v.y - mean) * rstd * sc.y + bi.y;
    o4.z = (v.z - mean) * rstd * sc.z + bi.z;
    o4.w = (v.w - mean) * rstd * sc.w + bi.w;
    ((float4*)(out + (size_t)row * DIM))[t] = o4;
}

__device__ __forceinline__ float gelu_exact(float v) {
    return 0.5f * v * (1.0f + erff(v * 0.70710678118654752f));
}

// ---------------- BM=128/BN=256 GEMM, BK=32, 3 stages, 1 sync/iter ----------------
#define STAGES 3
#define APAD 36                      // 32 + 4 : fr*36+fc mod 32 bijective
#define T256_A_ST (128*APAD)         // 4608
#define T256_BPAD 264                // 256+8 : fc*264+fr mod 32 bijective
#define T256_B_ST (32*T256_BPAD)     // 8448
#define T256_ST   (T256_A_ST + T256_B_ST)   // 13056
#define T256_SMEM (STAGES * T256_ST * 4)    // 156672 B

template<int EPI>   // 0: C=acc ; 2: C=gelu(acc+bias)
__global__ __launch_bounds__(256)
void tc_gemm256(const float* __restrict__ A, const float* __restrict__ B,
                const float* __restrict__ bias, float* __restrict__ C,
                int N, int K)
{
    extern __shared__ float smf[];
    const uint32_t sb = smem_u32(smf);
    const int tid  = threadIdx.x;
    const int lane = tid & 31, wid = tid >> 5;
    const int wm = wid & 1, wn = wid >> 1;
    const int m0 = blockIdx.y * 128;
    const int n0 = blockIdx.x * 256;

    auto fill = [&](int s, int k0) {
        uint32_t ab = sb + (uint32_t)(s * T256_ST) * 4;
        uint32_t bb = ab + T256_A_ST * 4;
        #pragma unroll
        for (int it = 0; it < 4; it++) {              // A: 128 x 32
            int idx = it * 256 + tid;
            int r = idx >> 3, sg = idx & 7;
            cp16(ab + (uint32_t)(r * APAD + sg * 4) * 4,
                 A + (size_t)(m0 + r) * K + k0 + sg * 4);
        }
        #pragma unroll
        for (int it = 0; it < 8; it++) {              // B: 32 x 256
            int idx = it * 256 + tid;
            int kk = idx >> 6, sg = idx & 63;
            cp16(bb + (uint32_t)(kk * T256_BPAD + sg * 4) * 4,
                 B + (size_t)(k0 + kk) * N + n0 + sg * 4);
        }
    };

    float acc[4][8][4];
    #pragma unroll
    for (int i = 0; i < 4; i++)
        #pragma unroll
        for (int j = 0; j < 8; j++)
            #pragma unroll
            for (int q = 0; q < 4; q++) acc[i][j][q] = 0.f;

    const int NK = K >> 5;

    fill(0, 0);  cp_commit();
    fill(1, 32); cp_commit();

    const int fr = lane >> 2, fc = lane & 3;
    int rs = 0, fs = 2;

    for (int i = 0; i < NK; i++) {
        cp_wait<1>();
        __syncthreads();
        if (i + 2 < NK) fill(fs, (i + 2) * 32);
        cp_commit();

        const float* As = smf + rs * T256_ST;
        const float* Bs = As + T256_A_ST;

        #pragma unroll
        for (int ks = 0; ks < 4; ks++) {
            uint32_t af[4][4], bf[8][2];
            #pragma unroll
            for (int mt = 0; mt < 4; mt++) {
                const float* ap = As + (wm * 64 + mt * 16 + fr) * APAD + ks * 8 + fc;
                af[mt][0] = f2tf(ap[0]);
                af[mt][1] = f2tf(ap[8 * APAD]);
                af[mt][2] = f2tf(ap[4]);
                af[mt][3] = f2tf(ap[8 * APAD + 4]);
            }
            #pragma unroll
            for (int nt = 0; nt < 8; nt++) {
                const float* bp = Bs + (ks * 8 + fc) * T256_BPAD + wn * 64 + nt * 8 + fr;
                bf[nt][0] = f2tf(bp[0]);
                bf[nt][1] = f2tf(bp[4 * T256_BPAD]);
            }
            #pragma unroll
            for (int mt = 0; mt < 4; mt++)
                #pragma unroll
                for (int nt = 0; nt < 8; nt++)
                    mma_tf32(acc[mt][nt], af[mt], bf[nt]);
        }
        rs = (rs + 1 == STAGES) ? 0 : rs + 1;
        fs = (fs + 1 == STAGES) ? 0 : fs + 1;
    }

    #pragma unroll
    for (int mt = 0; mt < 4; mt++) {
        int row = m0 + wm * 64 + mt * 16 + fr;
        #pragma unroll
        for (int nt = 0; nt < 8; nt++) {
            int col = n0 + wn * 64 + nt * 8 + fc * 2;
            float* d = acc[mt][nt];
            size_t i0 = (size_t)row * N + col;
            size_t i1 = (size_t)(row + 8) * N + col;
            float o0 = d[0], o1 = d[1], o2 = d[2], o3 = d[3];
            if (EPI == 2) {
                float bx = bias[col], by = bias[col + 1];
                o0 = gelu_exact(o0 + bx); o1 = gelu_exact(o1 + by);
                o2 = gelu_exact(o2 + bx); o3 = gelu_exact(o3 + by);
            }
            *(float2*)(C + i0) = make_float2(o0, o1);
            *(float2*)(C + i1) = make_float2(o2, o3);
        }
    }
}

// ---------------- BM=64/BN=128 GEMM, BK=32, 3 stages, 2 CTA/SM ----------------
// EPI: C = acc + bias + resid (in-place safe)
#define G64_A_ST (64*APAD)                   // 2304
#define G64_BPAD 136
#define G64_B_ST (32*G64_BPAD)               // 4352
#define G64_ST   (G64_A_ST + G64_B_ST)       // 6656
#define G64_SMEM (STAGES * G64_ST * 4)       // 79872 B

__global__ __launch_bounds__(256, 2)
void tc_gemm64(const float* __restrict__ A, const float* __restrict__ B,
               const float* __restrict__ bias, const float* __restrict__ resid,
               float* __restrict__ C, int N, int K)
{
    extern __shared__ float smf[];
    const uint32_t sb = smem_u32(smf);
    const int tid  = threadIdx.x;
    const int lane = tid & 31, wid = tid >> 5;
    const int wm = wid & 1, wn = wid >> 1;
    const int m0 = blockIdx.y * 64;
    const int n0 = blockIdx.x * 128;

    auto fill = [&](int s, int k0) {
        uint32_t ab = sb + (uint32_t)(s * G64_ST) * 4;
        uint32_t bb = ab + G64_A_ST * 4;
        #pragma unroll
        for (int it = 0; it < 2; it++) {              // A: 64 x 32
            int idx = it * 256 + tid;
            int r = idx >> 3, sg = idx & 7;
            cp16(ab + (uint32_t)(r * APAD + sg * 4) * 4,
                 A + (size_t)(m0 + r) * K + k0 + sg * 4);
        }
        #pragma unroll
        for (int it = 0; it < 4; it++) {              // B: 32 x 128
            int idx = it * 256 + tid;
            int kk = idx >> 5, sg = idx & 31;
            cp16(bb + (uint32_t)(kk * G64_BPAD + sg * 4) * 4,
                 B + (size_t)(k0 + kk) * N + n0 + sg * 4);
        }
    };

    float acc[2][4][4];
    #pragma unroll
    for (int i = 0; i < 2; i++)
        #pragma unroll
        for (int j = 0; j < 4; j++)
            #pragma unroll
            for (int q = 0; q < 4; q++) acc[i][j][q] = 0.f;

    const int NK = K >> 5;

    fill(0, 0);  cp_commit();
    fill(1, 32); cp_commit();

    const int fr = lane >> 2, fc = lane & 3;
    int rs = 0, fs = 2;

    for (int i = 0; i < NK; i++) {
        cp_wait<1>();
        __syncthreads();
        if (i + 2 < NK) fill(fs, (i + 2) * 32);
        cp_commit();

        const float* As = smf + rs * G64_ST;
        const float* Bs = As + G64_A_ST;

        #pragma unroll
        for (int ks = 0; ks < 4; ks++) {
            uint32_t af[2][4], bf[4][2];
            #pragma unroll
            for (int mt = 0; mt < 2; mt++) {
                const float* ap = As + (wm * 32 + mt * 16 + fr) * APAD + ks * 8 + fc;
                af[mt][0] = f2tf(ap[0]);
                af[mt][1] = f2tf(ap[8 * APAD]);
                af[mt][2] = f2tf(ap[4]);
                af[mt][3] = f2tf(ap[8 * APAD + 4]);
            }
            #pragma unroll
            for (int nt = 0; nt < 4; nt++) {
                const float* bp = Bs + (ks * 8 + fc) * G64_BPAD + wn * 32 + nt * 8 + fr;
                bf[nt][0] = f2tf(bp[0]);
                bf[nt][1] = f2tf(bp[4 * G64_BPAD]);
            }
            #pragma unroll
            for (int mt = 0; mt < 2; mt++)
                #pragma unroll
                for (int nt = 0; nt < 4; nt++)
                    mma_tf32(acc[mt][nt], af[mt], bf[nt]);
        }
        rs = (rs + 1 == STAGES) ? 0 : rs + 1;
        fs = (fs + 1 == STAGES) ? 0 : fs + 1;
    }

    #pragma unroll
    for (int mt = 0; mt < 2; mt++) {
        int row = m0 + wm * 32 + mt * 16 + fr;
        #pragma unroll
        for (int nt = 0; nt < 4; nt++) {
            int col = n0 + wn * 32 + nt * 8 + fc * 2;
            float* d = acc[mt][nt];
            size_t i0 = (size_t)row * N + col;
            size_t i1 = (size_t)(row + 8) * N + col;
            float bx = bias[col], by = bias[col + 1];
            float o0 = d[0] + bx + resid[i0];
            float o1 = d[1] + by + resid[i0 + 1];
            float o2 = d[2] + bx + resid[i1];
            float o3 = d[3] + by + resid[i1 + 1];
            *(float2*)(C + i0) = make_float2(o0, o1);
            *(float2*)(C + i1) = make_float2(o2, o3);
        }
    }
}

// ---------------- Flash attention with tf32 mma.sync (validated R6) ----------------
#define FA_PAD 72
#define FA_TILE (64*FA_PAD)
#define FA_SMEM (6*FA_TILE*4)      // 110592 B

__global__ __launch_bounds__(128) void fattn_kernel(
    const float* __restrict__ qkv, float* __restrict__ o)
{
    extern __shared__ float sm[];
    float* Qs = sm;                       // [64][72]
    float* Ps = Qs + FA_TILE;             // [64][72]
    float* Ks = Ps + FA_TILE;             // [2][64][72]
    float* Vs = Ks + 2*FA_TILE;           // [2][64][72]
    const uint32_t sb = smem_u32(sm);
    const uint32_t Qb = sb;
    const uint32_t Kb = sb + (uint32_t)(2*FA_TILE)*4;
    const uint32_t Vb = sb + (uint32_t)(4*FA_TILE)*4;

    const int tid = threadIdx.x, lane = tid & 31, w = tid >> 5;
    const int fr = lane >> 2, fc = lane & 3;
    const int bh = blockIdx.y;
    const int b = bh >> 4, h = bh & 15;
    const int q0 = blockIdx.x * 64;

    const float* qbase = qkv + (size_t)(b * SEQ) * (3 * ID) + h * DHEAD;
    const float* kbase = qbase + ID;
    const float* vbase = qbase + 2 * ID;

    #pragma unroll
    for (int it = 0; it < 8; it++) {
        int idx = it * 128 + tid;
        int r = idx >> 4, s4 = idx & 15;
        cp16(Qb + (uint32_t)(r * FA_PAD + s4 * 4) * 4,
             qbase + (size_t)(q0 + r) * 3072 + s4 * 4);
    }
    auto fillKV = [&](int c, int buf) {
        #pragma unroll
        for (int it = 0; it < 8; it++) {
            int idx = it * 128 + tid;
            int r = idx >> 4, s4 = idx & 15;
            cp16(Kb + (uint32_t)((buf * 64 + r) * FA_PAD + s4 * 4) * 4,
                 kbase + (size_t)(c * 64 + r) * 3072 + s4 * 4);
            cp16(Vb + (uint32_t)((buf * 64 + r) * FA_PAD + s4 * 4) * 4,
                 vbase + (size_t)(c * 64 + r) * 3072 + s4 * 4);
        }
    };
    fillKV(0, 0); cp_commit();

    float accO[8][4];
    #pragma unroll
    for (int nt = 0; nt < 8; nt++)
        #pragma unroll
        for (int q = 0; q < 4; q++) accO[nt][q] = 0.f;
    float M0 = -1e30f, M1 = -1e30f, L0 = 0.f, L1 = 0.f;

    const float* Prow0 = Ps + (w * 16 + fr) * FA_PAD;
    const int prow0_off = (w * 16 + fr) * FA_PAD;

    for (int c = 0; c < SEQ / 64; c++) {
        cp_wait<0>();
        __syncthreads();
        if (c + 1 < SEQ / 64) { fillKV(c + 1, (c + 1) & 1); cp_commit(); }

        const float* Kc = Ks + (c & 1) * FA_TILE;
        const float* Vc = Vs + (c & 1) * FA_TILE;

        float sacc[8][4];
        #pragma unroll
        for (int nt = 0; nt < 8; nt++)
            #pragma unroll
            for (int q = 0; q < 4; q++) sacc[nt][q] = 0.f;
        #pragma unroll
        for (int ks = 0; ks < 8; ks++) {
            uint32_t af[4];
            const float* qp = Qs + (w * 16 + fr) * FA_PAD + ks * 8 + fc;
            af[0] = f2tf(qp[0]);
            af[1] = f2tf(qp[8 * FA_PAD]);
            af[2] = f2tf(qp[4]);
            af[3] = f2tf(qp[8 * FA_PAD + 4]);
            #pragma unroll
            for (int nt = 0; nt < 8; nt++) {
                const float* kp = Kc + (nt * 8 + fr) * FA_PAD + ks * 8 + fc;
                uint32_t bf[2] = { f2tf(kp[0]), f2tf(kp[4]) };
                mma_tf32(sacc[nt], af, bf);
            }
        }

        float mx0 = -1e30f, mx1 = -1e30f;
        #pragma unroll
        for (int nt = 0; nt < 8; nt++) {
            sacc[nt][0] *= 0.125f; sacc[nt][1] *= 0.125f;
            sacc[nt][2] *= 0.125f; sacc[nt][3] *= 0.125f;
            mx0 = fmaxf(mx0, fmaxf(sacc[nt][0], sacc[nt][1]));
            mx1 = fmaxf(mx1, fmaxf(sacc[nt][2], sacc[nt][3]));
        }
        mx0 = fmaxf(mx0, __shfl_xor_sync(0xffffffffu, mx0, 1));
        mx0 = fmaxf(mx0, __shfl_xor_sync(0xffffffffu, mx0, 2));
        mx1 = fmaxf(mx1, __shfl_xor_sync(0xffffffffu, mx1, 1));
        mx1 = fmaxf(mx1, __shfl_xor_sync(0xffffffffu, mx1, 2));
        float Mn0 = fmaxf(M0, mx0), Mn1 = fmaxf(M1, mx1);
        float a0 = __expf(M0 - Mn0), a1 = __expf(M1 - Mn1);
        float s0 = 0.f, s1 = 0.f;
        #pragma unroll
        for (int nt = 0; nt < 8; nt++) {
            float p0 = __expf(sacc[nt][0] - Mn0), p1 = __expf(sacc[nt][1] - Mn0);
            float p2 = __expf(sacc[nt][2] - Mn1), p3 = __expf(sacc[nt][3] - Mn1);
            s0 += p0 + p1; s1 += p2 + p3;
            *(float2*)(Ps + prow0_off + nt * 8 + 2 * fc) =
                make_float2(tf32r(p0), tf32r(p1));
            *(float2*)(Ps + prow0_off + 8 * FA_PAD + nt * 8 + 2 * fc) =
                make_float2(tf32r(p2), tf32r(p3));
            accO[nt][0] *= a0; accO[nt][1] *= a0;
            accO[nt][2] *= a1; accO[nt][3] *= a1;
        }
        s0 += __shfl_xor_sync(0xffffffffu, s0, 1);
        s0 += __shfl_xor_sync(0xffffffffu, s0, 2);
        s1 += __shfl_xor_sync(0xffffffffu, s1, 1);
        s1 += __shfl_xor_sync(0xffffffffu, s1, 2);
        L0 = L0 * a0 + s0; L1 = L1 * a1 + s1;
        M0 = Mn0; M1 = Mn1;
        __syncwarp();

        #pragma unroll
        for (int ks = 0; ks < 8; ks++) {
            uint32_t af[4];
            const float* pp = Prow0 + ks * 8 + fc;
            af[0] = __float_as_uint(pp[0]);
            af[1] = __float_as_uint(pp[8 * FA_PAD]);
            af[2] = __float_as_uint(pp[4]);
            af[3] = __float_as_uint(pp[8 * FA_PAD + 4]);
            #pragma unroll
            for (int nt = 0; nt < 8; nt++) {
                const float* vp = Vc + (ks * 8 + fc) * FA_PAD + nt * 8 + fr;
                uint32_t bf[2] = { f2tf(vp[0]), f2tf(vp[4 * FA_PAD]) };
                mma_tf32(accO[nt], af, bf);
            }
        }
    }

    float inv0 = 1.0f / L0, inv1 = 1.0f / L1;
    size_t t0 = (size_t)(b * SEQ + q0 + w * 16 + fr);
    #pragma unroll
    for (int nt = 0; nt < 8; nt++) {
        int col = h * DHEAD + nt * 8 + 2 * fc;
        *(float2*)(o + t0 * ID + col) =
            make_float2(accO[nt][0] * inv0, accO[nt][1] * inv0);
        *(float2*)(o + (t0 + 8) * ID + col) =
            make_float2(accO[nt][2] * inv1, accO[nt][3] * inv1);
    }
}

// ---------------- driver ----------------
extern "C" void kernel_launch(void* const* d_in, const int* in_sizes, int n_in,
                              void* d_out, int out_size)
{
    const float* x_in = (const float*)d_in[0];
    const float* ln1s = (const float*)d_in[1];
    const float* ln1b = (const float*)d_in[2];
    const float* wqkv = (const float*)d_in[3];
    const float* wout = (const float*)d_in[4];
    const float* bout = (const float*)d_in[5];
    const float* ln2s = (const float*)d_in[6];
    const float* ln2b = (const float*)d_in[7];
    const float* w1   = (const float*)d_in[8];
    const float* b1   = (const float*)d_in[9];
    const float* w2   = (const float*)d_in[10];
    const float* b2   = (const float*)d_in[11];
    float* x = (float*)d_out;

    void* p;
    cudaGetSymbolAddress(&p, g_h);   float* gh   = (float*)p;
    cudaGetSymbolAddress(&p, g_qkv); float* gqkv = (float*)p;
    cudaGetSymbolAddress(&p, g_o);   float* go   = (float*)p;
    cudaGetSymbolAddress(&p, g_a);   float* ga   = (float*)p;

    cudaFuncSetAttribute(tc_gemm256<0>, cudaFuncAttributeMaxDynamicSharedMemorySize, T256_SMEM);
    cudaFuncSetAttribute(tc_gemm256<2>, cudaFuncAttributeMaxDynamicSharedMemorySize, T256_SMEM);
    cudaFuncSetAttribute(tc_gemm64, cudaFuncAttributeMaxDynamicSharedMemorySize, G64_SMEM);
    cudaFuncSetAttribute(fattn_kernel, cudaFuncAttributeMaxDynamicSharedMemorySize, FA_SMEM);

    cudaMemcpyAsync(x, x_in, (size_t)TOKENS * DIM * sizeof(float),
                    cudaMemcpyDeviceToDevice);

    for (int l = 0; l < LAYERS; l++) {
        const float* l1s = ln1s + l * DIM;
        const float* l1b = ln1b + l * DIM;
        const float* wq  = wqkv + (size_t)l * DIM * (3 * ID);
        const float* wo  = wout + (size_t)l * ID * DIM;
        const float* bo  = bout + l * DIM;
        const float* l2s = ln2s + l * DIM;
        const float* l2b = ln2b + l * DIM;
        const float* w1l = w1 + (size_t)l * DIM * FFN;
        const float* b1l = b1 + l * FFN;
        const float* w2l = w2 + (size_t)l * FFN * DIM;
        const float* b2l = b2 + l * DIM;

        // h = LN1(x)
        ln_kernel<<<TOKENS, 256>>>(x, l1s, l1b, gh);
        // qkv = h @ wqkv
        tc_gemm256<0><<<dim3(3 * ID / 256, TOKENS / 128), 256, T256_SMEM>>>(
            gh, wq, nullptr, gqkv, 3 * ID, DIM);
        // attention (tf32 flash)
        fattn_kernel<<<dim3(SEQ / 64, BATCH * HEADS), 128, FA_SMEM>>>(gqkv, go);
        // x = x + o @ wo + bo
        tc_gemm64<<<dim3(DIM / 128, TOKENS / 64), 256, G64_SMEM>>>(
            go, wo, bo, x, x, DIM, ID);
        // h = LN2(x)
        ln_kernel<<<TOKENS, 256>>>(x, l2s, l2b, gh);
        // a = gelu(h @ w1 + b1)
        tc_gemm256<2><<<dim3(FFN / 256, TOKENS / 128), 256, T256_SMEM>>>(
            gh, w1l, b1l, ga, FFN, DIM);
        // x = x + a @ w2 + b2
        tc_gemm64<<<dim3(DIM / 128, TOKENS / 64), 256, G64_SMEM>>>(
            ga, w2l, b2l, x, x, DIM, FFN);
    }
}

// round 11
// speedup vs baseline: 1.5630x; 1.0672x over previous
#include <cuda_runtime.h>
#include <math.h>
#include <stdint.h>

#define LAYERS 6
#define BATCH  4
#define SEQ    512
#define DIM    1024
#define HEADS  16
#define DHEAD  64
#define FFN    4096
#define TOKENS (BATCH*SEQ)          // 2048
#define ID     (HEADS*DHEAD)        // 1024

#define W_QKV_FLOATS ((size_t)LAYERS*DIM*3*ID)
#define W_OUT_FLOATS ((size_t)LAYERS*ID*DIM)
#define W_1_FLOATS   ((size_t)LAYERS*DIM*FFN)
#define W_2_FLOATS   ((size_t)LAYERS*FFN*DIM)

// ---------------- scratch (allocation-guard safe) ----------------
__device__ float g_h  [TOKENS*DIM];
__device__ float g_qkv[TOKENS*3*ID];
__device__ float g_o  [TOKENS*ID];
__device__ float g_a  [(size_t)TOKENS*FFN];
__device__ float g_wr [W_QKV_FLOATS + W_OUT_FLOATS + W_1_FLOATS + W_2_FLOATS];

// ---------------- small PTX helpers ----------------
__device__ __forceinline__ uint32_t smem_u32(const void* p) {
    uint32_t a;
    asm("{ .reg .u64 t; cvta.to.shared.u64 t, %1; cvt.u32.u64 %0, t; }" : "=r"(a) : "l"(p));
    return a;
}
__device__ __forceinline__ void cp16(uint32_t dst, const void* src) {
    asm volatile("cp.async.cg.shared.global [%0], [%1], 16;" :: "r"(dst), "l"(src));
}
__device__ __forceinline__ void cp_commit() {
    asm volatile("cp.async.commit_group;" ::: "memory");
}
template<int N> __device__ __forceinline__ void cp_wait() {
    asm volatile("cp.async.wait_group %0;" :: "n"(N) : "memory");
}
__device__ __forceinline__ uint32_t f2tf(float x) {
    uint32_t u; asm("cvt.rna.tf32.f32 %0, %1;" : "=r"(u) : "f"(x)); return u;
}
__device__ __forceinline__ float tf32r(float x) { return __uint_as_float(f2tf(x)); }
__device__ __forceinline__ void mma_tf32(float* d, const uint32_t* a, const uint32_t* b) {
    asm volatile(
        "mma.sync.aligned.m16n8k8.row.col.f32.tf32.tf32.f32 "
        "{%0,%1,%2,%3}, {%4,%5,%6,%7}, {%8,%9}, {%0,%1,%2,%3};"
        : "+f"(d[0]), "+f"(d[1]), "+f"(d[2]), "+f"(d[3])
        : "r"(a[0]), "r"(a[1]), "r"(a[2]), "r"(a[3]), "r"(b[0]), "r"(b[1]));
}

// ---------------- weight rounding ----------------
__global__ __launch_bounds__(256) void round_kernel(
    const float* __restrict__ in, float* __restrict__ out, int n4)
{
    int i = blockIdx.x * 256 + threadIdx.x;
    int stride = gridDim.x * 256;
    for (; i < n4; i += stride) {
        float4 v = ((const float4*)in)[i];
        v.x = tf32r(v.x); v.y = tf32r(v.y); v.z = tf32r(v.z); v.w = tf32r(v.w);
        ((float4*)out)[i] = v;
    }
}

// ---------------- LayerNorm (tf32-rounded output) ----------------
__global__ __launch_bounds__(256) void ln_kernel(
    const float* __restrict__ x, const float* __restrict__ scale,
    const float* __restrict__ bias, float* __restrict__ out)
{
    __shared__ float wsum[8], wsq[8];
    int row = blockIdx.x, t = threadIdx.x;
    const float4* xr = (const float4*)(x + (size_t)row * DIM);
    float4 v = xr[t];
    float s  = v.x + v.y + v.z + v.w;
    float ss = v.x*v.x + v.y*v.y + v.z*v.z + v.w*v.w;
    #pragma unroll
    for (int o = 16; o; o >>= 1) {
        s  += __shfl_xor_sync(0xffffffffu, s,  o);
        ss += __shfl_xor_sync(0xffffffffu, ss, o);
    }
    if ((t & 31) == 0) { wsum[t >> 5] = s; wsq[t >> 5] = ss; }
    __syncthreads();
    float S = 0.f, SS = 0.f;
    #pragma unroll
    for (int i = 0; i < 8; i++) { S += wsum[i]; SS += wsq[i]; }
    float mean = S * (1.0f / DIM);
    float var  = SS * (1.0f / DIM) - mean * mean;
    float rstd = rsqrtf(var + 1e-5f);
    float4 sc = ((const float4*)scale)[t];
    float4 bi = ((const float4*)bias)[t];
    float4 o4;
    o4.x = tf32r((v.x - mean) * rstd * sc.x + bi.x);
    o4.y = tf32r((v.y - mean) * rstd * sc.y + bi.y);
    o4.z = tf32r((v.z - mean) * rstd * sc.z + bi.z);
    o4.w = tf32r((v.w - mean) * rstd * sc.w + bi.w);
    ((float4*)(out + (size_t)row * DIM))[t] = o4;
}

__device__ __forceinline__ float gelu_exact(float v) {
    return 0.5f * v * (1.0f + erff(v * 0.70710678118654752f));
}

// ---------------- BM=128/BN=256 GEMM, BK=32, 3 stages, zero in-loop cvt ------
#define STAGES 3
#define APAD 36
#define T256_A_ST (128*APAD)
#define T256_BPAD 264
#define T256_B_ST (32*T256_BPAD)
#define T256_ST   (T256_A_ST + T256_B_ST)
#define T256_SMEM (STAGES * T256_ST * 4)    // 156672 B

template<int EPI>   // 0: C=tf32r(acc) ; 2: C=tf32r(gelu(acc+bias))
__global__ __launch_bounds__(256)
void tc_gemm256(const float* __restrict__ A, const float* __restrict__ B,
                const float* __restrict__ bias, float* __restrict__ C,
                int N, int K)
{
    extern __shared__ float smf[];
    const uint32_t sb = smem_u32(smf);
    const int tid  = threadIdx.x;
    const int lane = tid & 31, wid = tid >> 5;
    const int wm = wid & 1, wn = wid >> 1;
    const int m0 = blockIdx.y * 128;
    const int n0 = blockIdx.x * 256;

    auto fill = [&](int s, int k0) {
        uint32_t ab = sb + (uint32_t)(s * T256_ST) * 4;
        uint32_t bb = ab + T256_A_ST * 4;
        #pragma unroll
        for (int it = 0; it < 4; it++) {
            int idx = it * 256 + tid;
            int r = idx >> 3, sg = idx & 7;
            cp16(ab + (uint32_t)(r * APAD + sg * 4) * 4,
                 A + (size_t)(m0 + r) * K + k0 + sg * 4);
        }
        #pragma unroll
        for (int it = 0; it < 8; it++) {
            int idx = it * 256 + tid;
            int kk = idx >> 6, sg = idx & 63;
            cp16(bb + (uint32_t)(kk * T256_BPAD + sg * 4) * 4,
                 B + (size_t)(k0 + kk) * N + n0 + sg * 4);
        }
    };

    float acc[4][8][4];
    #pragma unroll
    for (int i = 0; i < 4; i++)
        #pragma unroll
        for (int j = 0; j < 8; j++)
            #pragma unroll
            for (int q = 0; q < 4; q++) acc[i][j][q] = 0.f;

    const int NK = K >> 5;

    fill(0, 0);  cp_commit();
    fill(1, 32); cp_commit();

    const int fr = lane >> 2, fc = lane & 3;
    int rs = 0, fs = 2;

    for (int i = 0; i < NK; i++) {
        cp_wait<1>();
        __syncthreads();
        if (i + 2 < NK) fill(fs, (i + 2) * 32);
        cp_commit();

        const float* As = smf + rs * T256_ST;
        const float* Bs = As + T256_A_ST;

        #pragma unroll
        for (int ks = 0; ks < 4; ks++) {
            uint32_t af[4][4], bf[8][2];
            #pragma unroll
            for (int mt = 0; mt < 4; mt++) {
                const float* ap = As + (wm * 64 + mt * 16 + fr) * APAD + ks * 8 + fc;
                af[mt][0] = __float_as_uint(ap[0]);
                af[mt][1] = __float_as_uint(ap[8 * APAD]);
                af[mt][2] = __float_as_uint(ap[4]);
                af[mt][3] = __float_as_uint(ap[8 * APAD + 4]);
            }
            #pragma unroll
            for (int nt = 0; nt < 8; nt++) {
                const float* bp = Bs + (ks * 8 + fc) * T256_BPAD + wn * 64 + nt * 8 + fr;
                bf[nt][0] = __float_as_uint(bp[0]);
                bf[nt][1] = __float_as_uint(bp[4 * T256_BPAD]);
            }
            #pragma unroll
            for (int mt = 0; mt < 4; mt++)
                #pragma unroll
                for (int nt = 0; nt < 8; nt++)
                    mma_tf32(acc[mt][nt], af[mt], bf[nt]);
        }
        rs = (rs + 1 == STAGES) ? 0 : rs + 1;
        fs = (fs + 1 == STAGES) ? 0 : fs + 1;
    }

    #pragma unroll
    for (int mt = 0; mt < 4; mt++) {
        int row = m0 + wm * 64 + mt * 16 + fr;
        #pragma unroll
        for (int nt = 0; nt < 8; nt++) {
            int col = n0 + wn * 64 + nt * 8 + fc * 2;
            float* d = acc[mt][nt];
            size_t i0 = (size_t)row * N + col;
            size_t i1 = (size_t)(row + 8) * N + col;
            float o0 = d[0], o1 = d[1], o2 = d[2], o3 = d[3];
            if (EPI == 0) {
                o0 = tf32r(o0); o1 = tf32r(o1); o2 = tf32r(o2); o3 = tf32r(o3);
            }
            if (EPI == 2) {
                float bx = bias[col], by = bias[col + 1];
                o0 = tf32r(gelu_exact(o0 + bx)); o1 = tf32r(gelu_exact(o1 + by));
                o2 = tf32r(gelu_exact(o2 + bx)); o3 = tf32r(gelu_exact(o3 + by));
            }
            *(float2*)(C + i0) = make_float2(o0, o1);
            *(float2*)(C + i1) = make_float2(o2, o3);
        }
    }
}

// ---------------- BM=64/BN=128 GEMM, BK=32, 2 CTA/SM, zero in-loop cvt -------
#define G64_A_ST (64*APAD)
#define G64_BPAD 136
#define G64_B_ST (32*G64_BPAD)
#define G64_ST   (G64_A_ST + G64_B_ST)
#define G64_SMEM (STAGES * G64_ST * 4)       // 79872 B

__global__ __launch_bounds__(256, 2)
void tc_gemm64(const float* __restrict__ A, const float* __restrict__ B,
               const float* __restrict__ bias, const float* __restrict__ resid,
               float* __restrict__ C, int N, int K)
{
    extern __shared__ float smf[];
    const uint32_t sb = smem_u32(smf);
    const int tid  = threadIdx.x;
    const int lane = tid & 31, wid = tid >> 5;
    const int wm = wid & 1, wn = wid >> 1;
    const int m0 = blockIdx.y * 64;
    const int n0 = blockIdx.x * 128;

    auto fill = [&](int s, int k0) {
        uint32_t ab = sb + (uint32_t)(s * G64_ST) * 4;
        uint32_t bb = ab + G64_A_ST * 4;
        #pragma unroll
        for (int it = 0; it < 2; it++) {
            int idx = it * 256 + tid;
            int r = idx >> 3, sg = idx & 7;
            cp16(ab + (uint32_t)(r * APAD + sg * 4) * 4,
                 A + (size_t)(m0 + r) * K + k0 + sg * 4);
        }
        #pragma unroll
        for (int it = 0; it < 4; it++) {
            int idx = it * 256 + tid;
            int kk = idx >> 5, sg = idx & 31;
            cp16(bb + (uint32_t)(kk * G64_BPAD + sg * 4) * 4,
                 B + (size_t)(k0 + kk) * N + n0 + sg * 4);
        }
    };

    float acc[2][4][4];
    #pragma unroll
    for (int i = 0; i < 2; i++)
        #pragma unroll
        for (int j = 0; j < 4; j++)
            #pragma unroll
            for (int q = 0; q < 4; q++) acc[i][j][q] = 0.f;

    const int NK = K >> 5;

    fill(0, 0);  cp_commit();
    fill(1, 32); cp_commit();

    const int fr = lane >> 2, fc = lane & 3;
    int rs = 0, fs = 2;

    for (int i = 0; i < NK; i++) {
        cp_wait<1>();
        __syncthreads();
        if (i + 2 < NK) fill(fs, (i + 2) * 32);
        cp_commit();

        const float* As = smf + rs * G64_ST;
        const float* Bs = As + G64_A_ST;

        #pragma unroll
        for (int ks = 0; ks < 4; ks++) {
            uint32_t af[2][4], bf[4][2];
            #pragma unroll
            for (int mt = 0; mt < 2; mt++) {
                const float* ap = As + (wm * 32 + mt * 16 + fr) * APAD + ks * 8 + fc;
                af[mt][0] = __float_as_uint(ap[0]);
                af[mt][1] = __float_as_uint(ap[8 * APAD]);
                af[mt][2] = __float_as_uint(ap[4]);
                af[mt][3] = __float_as_uint(ap[8 * APAD + 4]);
            }
            #pragma unroll
            for (int nt = 0; nt < 4; nt++) {
                const float* bp = Bs + (ks * 8 + fc) * G64_BPAD + wn * 32 + nt * 8 + fr;
                bf[nt][0] = __float_as_uint(bp[0]);
                bf[nt][1] = __float_as_uint(bp[4 * G64_BPAD]);
            }
            #pragma unroll
            for (int mt = 0; mt < 2; mt++)
                #pragma unroll
                for (int nt = 0; nt < 4; nt++)
                    mma_tf32(acc[mt][nt], af[mt], bf[nt]);
        }
        rs = (rs + 1 == STAGES) ? 0 : rs + 1;
        fs = (fs + 1 == STAGES) ? 0 : fs + 1;
    }

    #pragma unroll
    for (int mt = 0; mt < 2; mt++) {
        int row = m0 + wm * 32 + mt * 16 + fr;
        #pragma unroll
        for (int nt = 0; nt < 4; nt++) {
            int col = n0 + wn * 32 + nt * 8 + fc * 2;
            float* d = acc[mt][nt];
            size_t i0 = (size_t)row * N + col;
            size_t i1 = (size_t)(row + 8) * N + col;
            float bx = bias[col], by = bias[col + 1];
            float o0 = d[0] + bx + resid[i0];
            float o1 = d[1] + by + resid[i0 + 1];
            float o2 = d[2] + bx + resid[i1];
            float o3 = d[3] + by + resid[i1 + 1];
            *(float2*)(C + i0) = make_float2(o0, o1);
            *(float2*)(C + i1) = make_float2(o2, o3);
        }
    }
}

// ---------------- Flash attention (qkv pre-rounded -> zero in-loop cvt) ------
#define FA_PAD 72
#define FA_TILE (64*FA_PAD)
#define FA_SMEM (6*FA_TILE*4)      // 110592 B

__global__ __launch_bounds__(128) void fattn_kernel(
    const float* __restrict__ qkv, float* __restrict__ o)
{
    extern __shared__ float sm[];
    float* Qs = sm;
    float* Ps = Qs + FA_TILE;
    float* Ks = Ps + FA_TILE;
    float* Vs = Ks + 2*FA_TILE;
    const uint32_t sb = smem_u32(sm);
    const uint32_t Qb = sb;
    const uint32_t Kb = sb + (uint32_t)(2*FA_TILE)*4;
    const uint32_t Vb = sb + (uint32_t)(4*FA_TILE)*4;

    const int tid = threadIdx.x, lane = tid & 31, w = tid >> 5;
    const int fr = lane >> 2, fc = lane & 3;
    const int bh = blockIdx.y;
    const int b = bh >> 4, h = bh & 15;
    const int q0 = blockIdx.x * 64;

    const float* qbase = qkv + (size_t)(b * SEQ) * (3 * ID) + h * DHEAD;
    const float* kbase = qbase + ID;
    const float* vbase = qbase + 2 * ID;

    #pragma unroll
    for (int it = 0; it < 8; it++) {
        int idx = it * 128 + tid;
        int r = idx >> 4, s4 = idx & 15;
        cp16(Qb + (uint32_t)(r * FA_PAD + s4 * 4) * 4,
             qbase + (size_t)(q0 + r) * 3072 + s4 * 4);
    }
    auto fillKV = [&](int c, int buf) {
        #pragma unroll
        for (int it = 0; it < 8; it++) {
            int idx = it * 128 + tid;
            int r = idx >> 4, s4 = idx & 15;
            cp16(Kb + (uint32_t)((buf * 64 + r) * FA_PAD + s4 * 4) * 4,
                 kbase + (size_t)(c * 64 + r) * 3072 + s4 * 4);
            cp16(Vb + (uint32_t)((buf * 64 + r) * FA_PAD + s4 * 4) * 4,
                 vbase + (size_t)(c * 64 + r) * 3072 + s4 * 4);
        }
    };
    fillKV(0, 0); cp_commit();

    float accO[8][4];
    #pragma unroll
    for (int nt = 0; nt < 8; nt++)
        #pragma unroll
        for (int q = 0; q < 4; q++) accO[nt][q] = 0.f;
    float M0 = -1e30f, M1 = -1e30f, L0 = 0.f, L1 = 0.f;

    const float* Prow0 = Ps + (w * 16 + fr) * FA_PAD;
    const int prow0_off = (w * 16 + fr) * FA_PAD;

    for (int c = 0; c < SEQ / 64; c++) {
        cp_wait<0>();
        __syncthreads();
        if (c + 1 < SEQ / 64) { fillKV(c + 1, (c + 1) & 1); cp_commit(); }

        const float* Kc = Ks + (c & 1) * FA_TILE;
        const float* Vc = Vs + (c & 1) * FA_TILE;

        float sacc[8][4];
        #pragma unroll
        for (int nt = 0; nt < 8; nt++)
            #pragma unroll
            for (int q = 0; q < 4; q++) sacc[nt][q] = 0.f;
        #pragma unroll
        for (int ks = 0; ks < 8; ks++) {
            uint32_t af[4];
            const float* qp = Qs + (w * 16 + fr) * FA_PAD + ks * 8 + fc;
            af[0] = __float_as_uint(qp[0]);
            af[1] = __float_as_uint(qp[8 * FA_PAD]);
            af[2] = __float_as_uint(qp[4]);
            af[3] = __float_as_uint(qp[8 * FA_PAD + 4]);
            #pragma unroll
            for (int nt = 0; nt < 8; nt++) {
                const float* kp = Kc + (nt * 8 + fr) * FA_PAD + ks * 8 + fc;
                uint32_t bf[2] = { __float_as_uint(kp[0]), __float_as_uint(kp[4]) };
                mma_tf32(sacc[nt], af, bf);
            }
        }

        float mx0 = -1e30f, mx1 = -1e30f;
        #pragma unroll
        for (int nt = 0; nt < 8; nt++) {
            sacc[nt][0] *= 0.125f; sacc[nt][1] *= 0.125f;
            sacc[nt][2] *= 0.125f; sacc[nt][3] *= 0.125f;
            mx0 = fmaxf(mx0, fmaxf(sacc[nt][0], sacc[nt][1]));
            mx1 = fmaxf(mx1, fmaxf(sacc[nt][2], sacc[nt][3]));
        }
        mx0 = fmaxf(mx0, __shfl_xor_sync(0xffffffffu, mx0, 1));
        mx0 = fmaxf(mx0, __shfl_xor_sync(0xffffffffu, mx0, 2));
        mx1 = fmaxf(mx1, __shfl_xor_sync(0xffffffffu, mx1, 1));
        mx1 = fmaxf(mx1, __shfl_xor_sync(0xffffffffu, mx1, 2));
        float Mn0 = fmaxf(M0, mx0), Mn1 = fmaxf(M1, mx1);
        float a0 = __expf(M0 - Mn0), a1 = __expf(M1 - Mn1);
        float s0 = 0.f, s1 = 0.f;
        #pragma unroll
        for (int nt = 0; nt < 8; nt++) {
            float p0 = __expf(sacc[nt][0] - Mn0), p1 = __expf(sacc[nt][1] - Mn0);
            float p2 = __expf(sacc[nt][2] - Mn1), p3 = __expf(sacc[nt][3] - Mn1);
            s0 += p0 + p1; s1 += p2 + p3;
            *(float2*)(Ps + prow0_off + nt * 8 + 2 * fc) =
                make_float2(tf32r(p0), tf32r(p1));
            *(float2*)(Ps + prow0_off + 8 * FA_PAD + nt * 8 + 2 * fc) =
                make_float2(tf32r(p2), tf32r(p3));
            accO[nt][0] *= a0; accO[nt][1] *= a0;
            accO[nt][2] *= a1; accO[nt][3] *= a1;
        }
        s0 += __shfl_xor_sync(0xffffffffu, s0, 1);
        s0 += __shfl_xor_sync(0xffffffffu, s0, 2);
        s1 += __shfl_xor_sync(0xffffffffu, s1, 1);
        s1 += __shfl_xor_sync(0xffffffffu, s1, 2);
        L0 = L0 * a0 + s0; L1 = L1 * a1 + s1;
        M0 = Mn0; M1 = Mn1;
        __syncwarp();

        #pragma unroll
        for (int ks = 0; ks < 8; ks++) {
            uint32_t af[4];
            const float* pp = Prow0 + ks * 8 + fc;
            af[0] = __float_as_uint(pp[0]);
            af[1] = __float_as_uint(pp[8 * FA_PAD]);
            af[2] = __float_as_uint(pp[4]);
            af[3] = __float_as_uint(pp[8 * FA_PAD + 4]);
            #pragma unroll
            for (int nt = 0; nt < 8; nt++) {
                const float* vp = Vc + (ks * 8 + fc) * FA_PAD + nt * 8 + fr;
                uint32_t bf[2] = { __float_as_uint(vp[0]), __float_as_uint(vp[4 * FA_PAD]) };
                mma_tf32(accO[nt], af, bf);
            }
        }
    }

    float inv0 = 1.0f / L0, inv1 = 1.0f / L1;
    size_t t0 = (size_t)(b * SEQ + q0 + w * 16 + fr);
    #pragma unroll
    for (int nt = 0; nt < 8; nt++) {
        int col = h * DHEAD + nt * 8 + 2 * fc;
        *(float2*)(o + t0 * ID + col) =
            make_float2(tf32r(accO[nt][0] * inv0), tf32r(accO[nt][1] * inv0));
        *(float2*)(o + (t0 + 8) * ID + col) =
            make_float2(tf32r(accO[nt][2] * inv1), tf32r(accO[nt][3] * inv1));
    }
}

// ---------------- driver ----------------
extern "C" void kernel_launch(void* const* d_in, const int* in_sizes, int n_in,
                              void* d_out, int out_size)
{
    const float* x_in = (const float*)d_in[0];
    const float* ln1s = (const float*)d_in[1];
    const float* ln1b = (const float*)d_in[2];
    const float* wqkv = (const float*)d_in[3];
    const float* wout = (const float*)d_in[4];
    const float* bout = (const float*)d_in[5];
    const float* ln2s = (const float*)d_in[6];
    const float* ln2b = (const float*)d_in[7];
    const float* w1   = (const float*)d_in[8];
    const float* b1   = (const float*)d_in[9];
    const float* w2   = (const float*)d_in[10];
    const float* b2   = (const float*)d_in[11];
    float* x = (float*)d_out;

    void* p;
    cudaGetSymbolAddress(&p, g_h);   float* gh   = (float*)p;
    cudaGetSymbolAddress(&p, g_qkv); float* gqkv = (float*)p;
    cudaGetSymbolAddress(&p, g_o);   float* go   = (float*)p;
    cudaGetSymbolAddress(&p, g_a);   float* ga   = (float*)p;
    cudaGetSymbolAddress(&p, g_wr);  float* gwr  = (float*)p;

    float* rw_qkv = gwr;
    float* rw_out = rw_qkv + W_QKV_FLOATS;
    float* rw_1   = rw_out + W_OUT_FLOATS;
    float* rw_2   = rw_1   + W_1_FLOATS;

    cudaFuncSetAttribute(tc_gemm256<0>, cudaFuncAttributeMaxDynamicSharedMemorySize, T256_SMEM);
    cudaFuncSetAttribute(tc_gemm256<2>, cudaFuncAttributeMaxDynamicSharedMemorySize, T256_SMEM);
    cudaFuncSetAttribute(tc_gemm64, cudaFuncAttributeMaxDynamicSharedMemorySize, G64_SMEM);
    cudaFuncSetAttribute(fattn_kernel, cudaFuncAttributeMaxDynamicSharedMemorySize, FA_SMEM);

    // pre-round all weights to tf32 (idempotent; ~100us, DRAM-bound)
    round_kernel<<<2048, 256>>>(wqkv, rw_qkv, (int)(W_QKV_FLOATS / 4));
    round_kernel<<<2048, 256>>>(wout, rw_out, (int)(W_OUT_FLOATS / 4));
    round_kernel<<<2048, 256>>>(w1,   rw_1,   (int)(W_1_FLOATS   / 4));
    round_kernel<<<2048, 256>>>(w2,   rw_2,   (int)(W_2_FLOATS   / 4));

    cudaMemcpyAsync(x, x_in, (size_t)TOKENS * DIM * sizeof(float),
                    cudaMemcpyDeviceToDevice);

    for (int l = 0; l < LAYERS; l++) {
        const float* l1s = ln1s + l * DIM;
        const float* l1b = ln1b + l * DIM;
        const float* wq  = rw_qkv + (size_t)l * DIM * (3 * ID);
        const float* wo  = rw_out + (size_t)l * ID * DIM;
        const float* bo  = bout + l * DIM;
        const float* l2s = ln2s + l * DIM;
        const float* l2b = ln2b + l * DIM;
        const float* w1l = rw_1 + (size_t)l * DIM * FFN;
        const float* b1l = b1 + l * FFN;
        const float* w2l = rw_2 + (size_t)l * FFN * DIM;
        const float* b2l = b2 + l * DIM;

        // h = LN1(x)  (tf32-rounded)
        ln_kernel<<<TOKENS, 256>>>(x, l1s, l1b, gh);
        // qkv = tf32r(h @ wqkv)
        tc_gemm256<0><<<dim3(3 * ID / 256, TOKENS / 128), 256, T256_SMEM>>>(
            gh, wq, nullptr, gqkv, 3 * ID, DIM);
        // attention (tf32 flash; output rounded)
        fattn_kernel<<<dim3(SEQ / 64, BATCH * HEADS), 128, FA_SMEM>>>(gqkv, go);
        // x = x + o @ wo + bo
        tc_gemm64<<<dim3(DIM / 128, TOKENS / 64), 256, G64_SMEM>>>(
            go, wo, bo, x, x, DIM, ID);
        // h = LN2(x)  (tf32-rounded)
        ln_kernel<<<TOKENS, 256>>>(x, l2s, l2b, gh);
        // a = tf32r(gelu(h @ w1 + b1))
        tc_gemm256<2><<<dim3(FFN / 256, TOKENS / 128), 256, T256_SMEM>>>(
            gh, w1l, b1l, ga, FFN, DIM);
        // x = x + a @ w2 + b2
        tc_gemm64<<<dim3(DIM / 128, TOKENS / 64), 256, G64_SMEM>>>(
            ga, w2l, b2l, x, x, DIM, FFN);
    }
}

// round 12
// speedup vs baseline: 1.5953x; 1.0207x over previous
#include <cuda_runtime.h>
#include <math.h>
#include <stdint.h>

#define LAYERS 6
#define BATCH  4
#define SEQ    512
#define DIM    1024
#define HEADS  16
#define DHEAD  64
#define FFN    4096
#define TOKENS (BATCH*SEQ)          // 2048
#define ID     (HEADS*DHEAD)        // 1024

#define W_QKV_FLOATS ((size_t)LAYERS*DIM*3*ID)
#define W_OUT_FLOATS ((size_t)LAYERS*ID*DIM)
#define W_1_FLOATS   ((size_t)LAYERS*DIM*FFN)
#define W_2_FLOATS   ((size_t)LAYERS*FFN*DIM)

// ---------------- scratch (allocation-guard safe) ----------------
__device__ float g_h  [TOKENS*DIM];
__device__ float g_qkv[TOKENS*3*ID];
__device__ float g_o  [TOKENS*ID];
__device__ float g_a  [(size_t)TOKENS*FFN];
__device__ float g_wr [W_QKV_FLOATS + W_OUT_FLOATS + W_1_FLOATS + W_2_FLOATS];

// ---------------- small PTX helpers ----------------
__device__ __forceinline__ uint32_t smem_u32(const void* p) {
    uint32_t a;
    asm("{ .reg .u64 t; cvta.to.shared.u64 t, %1; cvt.u32.u64 %0, t; }" : "=r"(a) : "l"(p));
    return a;
}
__device__ __forceinline__ void cp16(uint32_t dst, const void* src) {
    asm volatile("cp.async.cg.shared.global [%0], [%1], 16;" :: "r"(dst), "l"(src));
}
__device__ __forceinline__ void cp_commit() {
    asm volatile("cp.async.commit_group;" ::: "memory");
}
template<int N> __device__ __forceinline__ void cp_wait() {
    asm volatile("cp.async.wait_group %0;" :: "n"(N) : "memory");
}
__device__ __forceinline__ uint32_t f2tf(float x) {
    uint32_t u; asm("cvt.rna.tf32.f32 %0, %1;" : "=r"(u) : "f"(x)); return u;
}
__device__ __forceinline__ float tf32r(float x) { return __uint_as_float(f2tf(x)); }
__device__ __forceinline__ void mma_tf32(float* d, const uint32_t* a, const uint32_t* b) {
    asm volatile(
        "mma.sync.aligned.m16n8k8.row.col.f32.tf32.tf32.f32 "
        "{%0,%1,%2,%3}, {%4,%5,%6,%7}, {%8,%9}, {%0,%1,%2,%3};"
        : "+f"(d[0]), "+f"(d[1]), "+f"(d[2]), "+f"(d[3])
        : "r"(a[0]), "r"(a[1]), "r"(a[2]), "r"(a[3]), "r"(b[0]), "r"(b[1]));
}

// ---------------- weight rounding ----------------
__global__ __launch_bounds__(256) void round_kernel(
    const float* __restrict__ in, float* __restrict__ out, int n4)
{
    int i = blockIdx.x * 256 + threadIdx.x;
    int stride = gridDim.x * 256;
    for (; i < n4; i += stride) {
        float4 v = ((const float4*)in)[i];
        v.x = tf32r(v.x); v.y = tf32r(v.y); v.z = tf32r(v.z); v.w = tf32r(v.w);
        ((float4*)out)[i] = v;
    }
}

// ---------------- LayerNorm (tf32-rounded output) ----------------
__global__ __launch_bounds__(256) void ln_kernel(
    const float* __restrict__ x, const float* __restrict__ scale,
    const float* __restrict__ bias, float* __restrict__ out)
{
    __shared__ float wsum[8], wsq[8];
    int row = blockIdx.x, t = threadIdx.x;
    const float4* xr = (const float4*)(x + (size_t)row * DIM);
    float4 v = xr[t];
    float s  = v.x + v.y + v.z + v.w;
    float ss = v.x*v.x + v.y*v.y + v.z*v.z + v.w*v.w;
    #pragma unroll
    for (int o = 16; o; o >>= 1) {
        s  += __shfl_xor_sync(0xffffffffu, s,  o);
        ss += __shfl_xor_sync(0xffffffffu, ss, o);
    }
    if ((t & 31) == 0) { wsum[t >> 5] = s; wsq[t >> 5] = ss; }
    __syncthreads();
    float S = 0.f, SS = 0.f;
    #pragma unroll
    for (int i = 0; i < 8; i++) { S += wsum[i]; SS += wsq[i]; }
    float mean = S * (1.0f / DIM);
    float var  = SS * (1.0f / DIM) - mean * mean;
    float rstd = rsqrtf(var + 1e-5f);
    float4 sc = ((const float4*)scale)[t];
    float4 bi = ((const float4*)bias)[t];
    float4 o4;
    o4.x = tf32r((v.x - mean) * rstd * sc.x + bi.x);
    o4.y = tf32r((v.y - mean) * rstd * sc.y + bi.y);
    o4.z = tf32r((v.z - mean) * rstd * sc.z + bi.z);
    o4.w = tf32r((v.w - mean) * rstd * sc.w + bi.w);
    ((float4*)(out + (size_t)row * DIM))[t] = o4;
}

__device__ __forceinline__ float gelu_exact(float v) {
    return 0.5f * v * (1.0f + erff(v * 0.70710678118654752f));
}

// ---------------- BM=64/BN=256 GEMM, BK=16, 4 stages, 2 CTA/SM ----------------
// For QKV (EPI 0: C = tf32r(acc)) and FF1 (EPI 2: C = tf32r(gelu(acc+bias)))
#define Q_STAGES 4
#define Q_APAD 20
#define Q_A_ST (64*Q_APAD)            // 1280
#define Q_BPAD 264
#define Q_B_ST (16*Q_BPAD)            // 4224
#define Q_ST   (Q_A_ST + Q_B_ST)      // 5504
#define Q_SMEM (Q_STAGES * Q_ST * 4)  // 88064 B

template<int EPI>
__global__ __launch_bounds__(256, 2)
void tc_gemmQ(const float* __restrict__ A, const float* __restrict__ B,
              const float* __restrict__ bias, float* __restrict__ C,
              int N, int K)
{
    extern __shared__ float smf[];
    const uint32_t sb = smem_u32(smf);
    const int tid  = threadIdx.x;
    const int lane = tid & 31, wid = tid >> 5;
    const int wm = wid & 1, wn = wid >> 1;
    const int m0 = blockIdx.y * 64;
    const int n0 = blockIdx.x * 256;

    auto fill = [&](int s, int k0) {
        uint32_t ab = sb + (uint32_t)(s * Q_ST) * 4;
        uint32_t bb = ab + Q_A_ST * 4;
        {   // A: 64 rows x 16 cols = 256 float4
            int r = tid >> 2, sg = tid & 3;
            cp16(ab + (uint32_t)(r * Q_APAD + sg * 4) * 4,
                 A + (size_t)(m0 + r) * K + k0 + sg * 4);
        }
        #pragma unroll
        for (int it = 0; it < 4; it++) {   // B: 16 rows x 256 cols = 1024 float4
            int idx = it * 256 + tid;
            int kk = idx >> 6, sg = idx & 63;
            cp16(bb + (uint32_t)(kk * Q_BPAD + sg * 4) * 4,
                 B + (size_t)(k0 + kk) * N + n0 + sg * 4);
        }
    };

    float acc[2][8][4];
    #pragma unroll
    for (int i = 0; i < 2; i++)
        #pragma unroll
        for (int j = 0; j < 8; j++)
            #pragma unroll
            for (int q = 0; q < 4; q++) acc[i][j][q] = 0.f;

    const int NK = K >> 4;

    #pragma unroll
    for (int p = 0; p < Q_STAGES - 1; p++) { fill(p, p * 16); cp_commit(); }

    const int fr = lane >> 2, fc = lane & 3;

    for (int i = 0; i < NK; i++) {
        cp_wait<Q_STAGES - 2>();
        __syncthreads();
        if (i + Q_STAGES - 1 < NK)
            fill((i + Q_STAGES - 1) & (Q_STAGES - 1), (i + Q_STAGES - 1) * 16);
        cp_commit();

        const float* As = smf + (i & (Q_STAGES - 1)) * Q_ST;
        const float* Bs = As + Q_A_ST;

        #pragma unroll
        for (int ks = 0; ks < 2; ks++) {
            uint32_t af[2][4], bf[8][2];
            #pragma unroll
            for (int mt = 0; mt < 2; mt++) {
                const float* ap = As + (wm * 32 + mt * 16 + fr) * Q_APAD + ks * 8 + fc;
                af[mt][0] = __float_as_uint(ap[0]);
                af[mt][1] = __float_as_uint(ap[8 * Q_APAD]);
                af[mt][2] = __float_as_uint(ap[4]);
                af[mt][3] = __float_as_uint(ap[8 * Q_APAD + 4]);
            }
            #pragma unroll
            for (int nt = 0; nt < 8; nt++) {
                const float* bp = Bs + (ks * 8 + fc) * Q_BPAD + wn * 64 + nt * 8 + fr;
                bf[nt][0] = __float_as_uint(bp[0]);
                bf[nt][1] = __float_as_uint(bp[4 * Q_BPAD]);
            }
            #pragma unroll
            for (int mt = 0; mt < 2; mt++)
                #pragma unroll
                for (int nt = 0; nt < 8; nt++)
                    mma_tf32(acc[mt][nt], af[mt], bf[nt]);
        }
    }

    #pragma unroll
    for (int mt = 0; mt < 2; mt++) {
        int row = m0 + wm * 32 + mt * 16 + fr;
        #pragma unroll
        for (int nt = 0; nt < 8; nt++) {
            int col = n0 + wn * 64 + nt * 8 + fc * 2;
            float* d = acc[mt][nt];
            size_t i0 = (size_t)row * N + col;
            size_t i1 = (size_t)(row + 8) * N + col;
            float o0 = d[0], o1 = d[1], o2 = d[2], o3 = d[3];
            if (EPI == 0) {
                o0 = tf32r(o0); o1 = tf32r(o1); o2 = tf32r(o2); o3 = tf32r(o3);
            }
            if (EPI == 2) {
                float bx = bias[col], by = bias[col + 1];
                o0 = tf32r(gelu_exact(o0 + bx)); o1 = tf32r(gelu_exact(o1 + by));
                o2 = tf32r(gelu_exact(o2 + bx)); o3 = tf32r(gelu_exact(o3 + by));
            }
            *(float2*)(C + i0) = make_float2(o0, o1);
            *(float2*)(C + i1) = make_float2(o2, o3);
        }
    }
}

// ---------------- BM=64/BN=128 GEMM, BK=32, 3 stages, 2 CTA/SM (R10) ---------
#define STAGES 3
#define APAD 36
#define G64_A_ST (64*APAD)
#define G64_BPAD 136
#define G64_B_ST (32*G64_BPAD)
#define G64_ST   (G64_A_ST + G64_B_ST)
#define G64_SMEM (STAGES * G64_ST * 4)       // 79872 B

__global__ __launch_bounds__(256, 2)
void tc_gemm64(const float* __restrict__ A, const float* __restrict__ B,
               const float* __restrict__ bias, const float* __restrict__ resid,
               float* __restrict__ C, int N, int K)
{
    extern __shared__ float smf[];
    const uint32_t sb = smem_u32(smf);
    const int tid  = threadIdx.x;
    const int lane = tid & 31, wid = tid >> 5;
    const int wm = wid & 1, wn = wid >> 1;
    const int m0 = blockIdx.y * 64;
    const int n0 = blockIdx.x * 128;

    auto fill = [&](int s, int k0) {
        uint32_t ab = sb + (uint32_t)(s * G64_ST) * 4;
        uint32_t bb = ab + G64_A_ST * 4;
        #pragma unroll
        for (int it = 0; it < 2; it++) {
            int idx = it * 256 + tid;
            int r = idx >> 3, sg = idx & 7;
            cp16(ab + (uint32_t)(r * APAD + sg * 4) * 4,
                 A + (size_t)(m0 + r) * K + k0 + sg * 4);
        }
        #pragma unroll
        for (int it = 0; it < 4; it++) {
            int idx = it * 256 + tid;
            int kk = idx >> 5, sg = idx & 31;
            cp16(bb + (uint32_t)(kk * G64_BPAD + sg * 4) * 4,
                 B + (size_t)(k0 + kk) * N + n0 + sg * 4);
        }
    };

    float acc[2][4][4];
    #pragma unroll
    for (int i = 0; i < 2; i++)
        #pragma unroll
        for (int j = 0; j < 4; j++)
            #pragma unroll
            for (int q = 0; q < 4; q++) acc[i][j][q] = 0.f;

    const int NK = K >> 5;

    fill(0, 0);  cp_commit();
    fill(1, 32); cp_commit();

    const int fr = lane >> 2, fc = lane & 3;
    int rs = 0, fs = 2;

    for (int i = 0; i < NK; i++) {
        cp_wait<1>();
        __syncthreads();
        if (i + 2 < NK) fill(fs, (i + 2) * 32);
        cp_commit();

        const float* As = smf + rs * G64_ST;
        const float* Bs = As + G64_A_ST;

        #pragma unroll
        for (int ks = 0; ks < 4; ks++) {
            uint32_t af[2][4], bf[4][2];
            #pragma unroll
            for (int mt = 0; mt < 2; mt++) {
                const float* ap = As + (wm * 32 + mt * 16 + fr) * APAD + ks * 8 + fc;
                af[mt][0] = __float_as_uint(ap[0]);
                af[mt][1] = __float_as_uint(ap[8 * APAD]);
                af[mt][2] = __float_as_uint(ap[4]);
                af[mt][3] = __float_as_uint(ap[8 * APAD + 4]);
            }
            #pragma unroll
            for (int nt = 0; nt < 4; nt++) {
                const float* bp = Bs + (ks * 8 + fc) * G64_BPAD + wn * 32 + nt * 8 + fr;
                bf[nt][0] = __float_as_uint(bp[0]);
                bf[nt][1] = __float_as_uint(bp[4 * G64_BPAD]);
            }
            #pragma unroll
            for (int mt = 0; mt < 2; mt++)
                #pragma unroll
                for (int nt = 0; nt < 4; nt++)
                    mma_tf32(acc[mt][nt], af[mt], bf[nt]);
        }
        rs = (rs + 1 == STAGES) ? 0 : rs + 1;
        fs = (fs + 1 == STAGES) ? 0 : fs + 1;
    }

    #pragma unroll
    for (int mt = 0; mt < 2; mt++) {
        int row = m0 + wm * 32 + mt * 16 + fr;
        #pragma unroll
        for (int nt = 0; nt < 4; nt++) {
            int col = n0 + wn * 32 + nt * 8 + fc * 2;
            float* d = acc[mt][nt];
            size_t i0 = (size_t)row * N + col;
            size_t i1 = (size_t)(row + 8) * N + col;
            float bx = bias[col], by = bias[col + 1];
            float o0 = d[0] + bx + resid[i0];
            float o1 = d[1] + by + resid[i0 + 1];
            float o2 = d[2] + bx + resid[i1];
            float o3 = d[3] + by + resid[i1 + 1];
            *(float2*)(C + i0) = make_float2(o0, o1);
            *(float2*)(C + i1) = make_float2(o2, o3);
        }
    }
}

// ---------------- Flash attention (validated; zero in-loop cvt) --------------
#define FA_PAD 72
#define FA_TILE (64*FA_PAD)
#define FA_SMEM (6*FA_TILE*4)      // 110592 B

__global__ __launch_bounds__(128) void fattn_kernel(
    const float* __restrict__ qkv, float* __restrict__ o)
{
    extern __shared__ float sm[];
    float* Qs = sm;
    float* Ps = Qs + FA_TILE;
    float* Ks = Ps + FA_TILE;
    float* Vs = Ks + 2*FA_TILE;
    const uint32_t sb = smem_u32(sm);
    const uint32_t Qb = sb;
    const uint32_t Kb = sb + (uint32_t)(2*FA_TILE)*4;
    const uint32_t Vb = sb + (uint32_t)(4*FA_TILE)*4;

    const int tid = threadIdx.x, lane = tid & 31, w = tid >> 5;
    const int fr = lane >> 2, fc = lane & 3;
    const int bh = blockIdx.y;
    const int b = bh >> 4, h = bh & 15;
    const int q0 = blockIdx.x * 64;

    const float* qbase = qkv + (size_t)(b * SEQ) * (3 * ID) + h * DHEAD;
    const float* kbase = qbase + ID;
    const float* vbase = qbase + 2 * ID;

    #pragma unroll
    for (int it = 0; it < 8; it++) {
        int idx = it * 128 + tid;
        int r = idx >> 4, s4 = idx & 15;
        cp16(Qb + (uint32_t)(r * FA_PAD + s4 * 4) * 4,
             qbase + (size_t)(q0 + r) * 3072 + s4 * 4);
    }
    auto fillKV = [&](int c, int buf) {
        #pragma unroll
        for (int it = 0; it < 8; it++) {
            int idx = it * 128 + tid;
            int r = idx >> 4, s4 = idx & 15;
            cp16(Kb + (uint32_t)((buf * 64 + r) * FA_PAD + s4 * 4) * 4,
                 kbase + (size_t)(c * 64 + r) * 3072 + s4 * 4);
            cp16(Vb + (uint32_t)((buf * 64 + r) * FA_PAD + s4 * 4) * 4,
                 vbase + (size_t)(c * 64 + r) * 3072 + s4 * 4);
        }
    };
    fillKV(0, 0); cp_commit();

    float accO[8][4];
    #pragma unroll
    for (int nt = 0; nt < 8; nt++)
        #pragma unroll
        for (int q = 0; q < 4; q++) accO[nt][q] = 0.f;
    float M0 = -1e30f, M1 = -1e30f, L0 = 0.f, L1 = 0.f;

    const float* Prow0 = Ps + (w * 16 + fr) * FA_PAD;
    const int prow0_off = (w * 16 + fr) * FA_PAD;

    for (int c = 0; c < SEQ / 64; c++) {
        cp_wait<0>();
        __syncthreads();
        if (c + 1 < SEQ / 64) { fillKV(c + 1, (c + 1) & 1); cp_commit(); }

        const float* Kc = Ks + (c & 1) * FA_TILE;
        const float* Vc = Vs + (c & 1) * FA_TILE;

        float sacc[8][4];
        #pragma unroll
        for (int nt = 0; nt < 8; nt++)
            #pragma unroll
            for (int q = 0; q < 4; q++) sacc[nt][q] = 0.f;
        #pragma unroll
        for (int ks = 0; ks < 8; ks++) {
            uint32_t af[4];
            const float* qp = Qs + (w * 16 + fr) * FA_PAD + ks * 8 + fc;
            af[0] = __float_as_uint(qp[0]);
            af[1] = __float_as_uint(qp[8 * FA_PAD]);
            af[2] = __float_as_uint(qp[4]);
            af[3] = __float_as_uint(qp[8 * FA_PAD + 4]);
            #pragma unroll
            for (int nt = 0; nt < 8; nt++) {
                const float* kp = Kc + (nt * 8 + fr) * FA_PAD + ks * 8 + fc;
                uint32_t bf[2] = { __float_as_uint(kp[0]), __float_as_uint(kp[4]) };
                mma_tf32(sacc[nt], af, bf);
            }
        }

        float mx0 = -1e30f, mx1 = -1e30f;
        #pragma unroll
        for (int nt = 0; nt < 8; nt++) {
            sacc[nt][0] *= 0.125f; sacc[nt][1] *= 0.125f;
            sacc[nt][2] *= 0.125f; sacc[nt][3] *= 0.125f;
            mx0 = fmaxf(mx0, fmaxf(sacc[nt][0], sacc[nt][1]));
            mx1 = fmaxf(mx1, fmaxf(sacc[nt][2], sacc[nt][3]));
        }
        mx0 = fmaxf(mx0, __shfl_xor_sync(0xffffffffu, mx0, 1));
        mx0 = fmaxf(mx0, __shfl_xor_sync(0xffffffffu, mx0, 2));
        mx1 = fmaxf(mx1, __shfl_xor_sync(0xffffffffu, mx1, 1));
        mx1 = fmaxf(mx1, __shfl_xor_sync(0xffffffffu, mx1, 2));
        float Mn0 = fmaxf(M0, mx0), Mn1 = fmaxf(M1, mx1);
        float a0 = __expf(M0 - Mn0), a1 = __expf(M1 - Mn1);
        float s0 = 0.f, s1 = 0.f;
        #pragma unroll
        for (int nt = 0; nt < 8; nt++) {
            float p0 = __expf(sacc[nt][0] - Mn0), p1 = __expf(sacc[nt][1] - Mn0);
            float p2 = __expf(sacc[nt][2] - Mn1), p3 = __expf(sacc[nt][3] - Mn1);
            s0 += p0 + p1; s1 += p2 + p3;
            *(float2*)(Ps + prow0_off + nt * 8 + 2 * fc) =
                make_float2(tf32r(p0), tf32r(p1));
            *(float2*)(Ps + prow0_off + 8 * FA_PAD + nt * 8 + 2 * fc) =
                make_float2(tf32r(p2), tf32r(p3));
            accO[nt][0] *= a0; accO[nt][1] *= a0;
            accO[nt][2] *= a1; accO[nt][3] *= a1;
        }
        s0 += __shfl_xor_sync(0xffffffffu, s0, 1);
        s0 += __shfl_xor_sync(0xffffffffu, s0, 2);
        s1 += __shfl_xor_sync(0xffffffffu, s1, 1);
        s1 += __shfl_xor_sync(0xffffffffu, s1, 2);
        L0 = L0 * a0 + s0; L1 = L1 * a1 + s1;
        M0 = Mn0; M1 = Mn1;
        __syncwarp();

        #pragma unroll
        for (int ks = 0; ks < 8; ks++) {
            uint32_t af[4];
            const float* pp = Prow0 + ks * 8 + fc;
            af[0] = __float_as_uint(pp[0]);
            af[1] = __float_as_uint(pp[8 * FA_PAD]);
            af[2] = __float_as_uint(pp[4]);
            af[3] = __float_as_uint(pp[8 * FA_PAD + 4]);
            #pragma unroll
            for (int nt = 0; nt < 8; nt++) {
                const float* vp = Vc + (ks * 8 + fc) * FA_PAD + nt * 8 + fr;
                uint32_t bf[2] = { __float_as_uint(vp[0]), __float_as_uint(vp[4 * FA_PAD]) };
                mma_tf32(accO[nt], af, bf);
            }
        }
    }

    float inv0 = 1.0f / L0, inv1 = 1.0f / L1;
    size_t t0 = (size_t)(b * SEQ + q0 + w * 16 + fr);
    #pragma unroll
    for (int nt = 0; nt < 8; nt++) {
        int col = h * DHEAD + nt * 8 + 2 * fc;
        *(float2*)(o + t0 * ID + col) =
            make_float2(tf32r(accO[nt][0] * inv0), tf32r(accO[nt][1] * inv0));
        *(float2*)(o + (t0 + 8) * ID + col) =
            make_float2(tf32r(accO[nt][2] * inv1), tf32r(accO[nt][3] * inv1));
    }
}

// ---------------- driver ----------------
extern "C" void kernel_launch(void* const* d_in, const int* in_sizes, int n_in,
                              void* d_out, int out_size)
{
    const float* x_in = (const float*)d_in[0];
    const float* ln1s = (const float*)d_in[1];
    const float* ln1b = (const float*)d_in[2];
    const float* wqkv = (const float*)d_in[3];
    const float* wout = (const float*)d_in[4];
    const float* bout = (const float*)d_in[5];
    const float* ln2s = (const float*)d_in[6];
    const float* ln2b = (const float*)d_in[7];
    const float* w1   = (const float*)d_in[8];
    const float* b1   = (const float*)d_in[9];
    const float* w2   = (const float*)d_in[10];
    const float* b2   = (const float*)d_in[11];
    float* x = (float*)d_out;

    void* p;
    cudaGetSymbolAddress(&p, g_h);   float* gh   = (float*)p;
    cudaGetSymbolAddress(&p, g_qkv); float* gqkv = (float*)p;
    cudaGetSymbolAddress(&p, g_o);   float* go   = (float*)p;
    cudaGetSymbolAddress(&p, g_a);   float* ga   = (float*)p;
    cudaGetSymbolAddress(&p, g_wr);  float* gwr  = (float*)p;

    float* rw_qkv = gwr;
    float* rw_out = rw_qkv + W_QKV_FLOATS;
    float* rw_1   = rw_out + W_OUT_FLOATS;
    float* rw_2   = rw_1   + W_1_FLOATS;

    cudaFuncSetAttribute(tc_gemmQ<0>, cudaFuncAttributeMaxDynamicSharedMemorySize, Q_SMEM);
    cudaFuncSetAttribute(tc_gemmQ<2>, cudaFuncAttributeMaxDynamicSharedMemorySize, Q_SMEM);
    cudaFuncSetAttribute(tc_gemm64, cudaFuncAttributeMaxDynamicSharedMemorySize, G64_SMEM);
    cudaFuncSetAttribute(fattn_kernel, cudaFuncAttributeMaxDynamicSharedMemorySize, FA_SMEM);

    // pre-round all weights to tf32 (idempotent; DRAM-bound)
    round_kernel<<<2048, 256>>>(wqkv, rw_qkv, (int)(W_QKV_FLOATS / 4));
    round_kernel<<<2048, 256>>>(wout, rw_out, (int)(W_OUT_FLOATS / 4));
    round_kernel<<<2048, 256>>>(w1,   rw_1,   (int)(W_1_FLOATS   / 4));
    round_kernel<<<2048, 256>>>(w2,   rw_2,   (int)(W_2_FLOATS   / 4));

    cudaMemcpyAsync(x, x_in, (size_t)TOKENS * DIM * sizeof(float),
                    cudaMemcpyDeviceToDevice);

    for (int l = 0; l < LAYERS; l++) {
        const float* l1s = ln1s + l * DIM;
        const float* l1b = ln1b + l * DIM;
        const float* wq  = rw_qkv + (size_t)l * DIM * (3 * ID);
        const float* wo  = rw_out + (size_t)l * ID * DIM;
        const float* bo  = bout + l * DIM;
        const float* l2s = ln2s + l * DIM;
        const float* l2b = ln2b + l * DIM;
        const float* w1l = rw_1 + (size_t)l * DIM * FFN;
        const float* b1l = b1 + l * FFN;
        const float* w2l = rw_2 + (size_t)l * FFN * DIM;
        const float* b2l = b2 + l * DIM;

        // h = LN1(x)  (tf32-rounded)
        ln_kernel<<<TOKENS, 256>>>(x, l1s, l1b, gh);
        // qkv = tf32r(h @ wqkv)   (BM=64/BN=256, 2 CTA/SM)
        tc_gemmQ<0><<<dim3(3 * ID / 256, TOKENS / 64), 256, Q_SMEM>>>(
            gh, wq, nullptr, gqkv, 3 * ID, DIM);
        // attention (tf32 flash; output rounded)
        fattn_kernel<<<dim3(SEQ / 64, BATCH * HEADS), 128, FA_SMEM>>>(gqkv, go);
        // x = x + o @ wo + bo
        tc_gemm64<<<dim3(DIM / 128, TOKENS / 64), 256, G64_SMEM>>>(
            go, wo, bo, x, x, DIM, ID);
        // h = LN2(x)  (tf32-rounded)
        ln_kernel<<<TOKENS, 256>>>(x, l2s, l2b, gh);
        // a = tf32r(gelu(h @ w1 + b1))   (BM=64/BN=256, 2 CTA/SM)
        tc_gemmQ<2><<<dim3(FFN / 256, TOKENS / 64), 256, Q_SMEM>>>(
            gh, w1l, b1l, ga, FFN, DIM);
        // x = x + a @ w2 + b2
        tc_gemm64<<<dim3(DIM / 128, TOKENS / 64), 256, G64_SMEM>>>(
            ga, w2l, b2l, x, x, DIM, FFN);
    }
}

// round 15
// speedup vs baseline: 2.2580x; 1.4154x over previous
#include <cuda_runtime.h>
#include <cuda_fp16.h>
#include <math.h>
#include <stdint.h>

#define LAYERS 6
#define BATCH  4
#define SEQ    512
#define DIM    1024
#define HEADS  16
#define DHEAD  64
#define FFN    4096
#define TOKENS (BATCH*SEQ)          // 2048
#define ID     (HEADS*DHEAD)        // 1024

#define W_QKV_ELT ((size_t)LAYERS*DIM*3*ID)
#define W_OUT_ELT ((size_t)LAYERS*ID*DIM)
#define W_1_ELT   ((size_t)LAYERS*DIM*FFN)
#define W_2_ELT   ((size_t)LAYERS*FFN*DIM)

// ---------------- scratch (allocation-guard safe) ----------------
__device__ __half g_h  [TOKENS*DIM];
__device__ float  g_qkv[TOKENS*3*ID];
__device__ __half g_o  [TOKENS*ID];
__device__ __half g_a  [(size_t)TOKENS*FFN];
__device__ __half g_wh [W_QKV_ELT + W_OUT_ELT + W_1_ELT + W_2_ELT];  // ~151MB

// ---------------- small PTX helpers ----------------
__device__ __forceinline__ uint32_t smem_u32(const void* p) {
    uint32_t a;
    asm("{ .reg .u64 t; cvta.to.shared.u64 t, %1; cvt.u32.u64 %0, t; }" : "=r"(a) : "l"(p));
    return a;
}
__device__ __forceinline__ void cp16(uint32_t dst, const void* src) {
    asm volatile("cp.async.cg.shared.global [%0], [%1], 16;" :: "r"(dst), "l"(src));
}
__device__ __forceinline__ void cp_commit() {
    asm volatile("cp.async.commit_group;" ::: "memory");
}
template<int N> __device__ __forceinline__ void cp_wait() {
    asm volatile("cp.async.wait_group %0;" :: "n"(N) : "memory");
}
__device__ __forceinline__ uint32_t f2tf(float x) {
    uint32_t u; asm("cvt.rna.tf32.f32 %0, %1;" : "=r"(u) : "f"(x)); return u;
}
__device__ __forceinline__ float tf32r(float x) { return __uint_as_float(f2tf(x)); }
__device__ __forceinline__ void mma_tf32(float* d, const uint32_t* a, const uint32_t* b) {
    asm volatile(
        "mma.sync.aligned.m16n8k8.row.col.f32.tf32.tf32.f32 "
        "{%0,%1,%2,%3}, {%4,%5,%6,%7}, {%8,%9}, {%0,%1,%2,%3};"
        : "+f"(d[0]), "+f"(d[1]), "+f"(d[2]), "+f"(d[3])
        : "r"(a[0]), "r"(a[1]), "r"(a[2]), "r"(a[3]), "r"(b[0]), "r"(b[1]));
}
__device__ __forceinline__ void mma_f16(float* d, const uint32_t* a, const uint32_t* b) {
    asm volatile(
        "mma.sync.aligned.m16n8k16.row.col.f32.f16.f16.f32 "
        "{%0,%1,%2,%3}, {%4,%5,%6,%7}, {%8,%9}, {%0,%1,%2,%3};"
        : "+f"(d[0]), "+f"(d[1]), "+f"(d[2]), "+f"(d[3])
        : "r"(a[0]), "r"(a[1]), "r"(a[2]), "r"(a[3]), "r"(b[0]), "r"(b[1]));
}

// ---------------- weight convert + transpose: out[n][k] = half(in[k][n]) ----
__global__ __launch_bounds__(256) void cvt_t_kernel(
    const float* __restrict__ in, __half* __restrict__ out, int K, int N)
{
    __shared__ float tile[32][33];
    in  += (size_t)blockIdx.z * K * N;
    out += (size_t)blockIdx.z * K * N;
    int n0 = blockIdx.x * 32, k0 = blockIdx.y * 32;
    int tx = threadIdx.x, ty = threadIdx.y;
    #pragma unroll
    for (int i = 0; i < 4; i++)
        tile[ty + i * 8][tx] = in[(size_t)(k0 + ty + i * 8) * N + n0 + tx];
    __syncthreads();
    #pragma unroll
    for (int i = 0; i < 4; i++)
        out[(size_t)(n0 + ty + i * 8) * K + k0 + tx] =
            __float2half_rn(tile[tx][ty + i * 8]);
}

// ---------------- LayerNorm (fp16 output) ----------------
__global__ __launch_bounds__(256) void ln_kernel(
    const float* __restrict__ x, const float* __restrict__ scale,
    const float* __restrict__ bias, __half* __restrict__ out)
{
    __shared__ float wsum[8], wsq[8];
    int row = blockIdx.x, t = threadIdx.x;
    const float4* xr = (const float4*)(x + (size_t)row * DIM);
    float4 v = xr[t];
    float s  = v.x + v.y + v.z + v.w;
    float ss = v.x*v.x + v.y*v.y + v.z*v.z + v.w*v.w;
    #pragma unroll
    for (int o = 16; o; o >>= 1) {
        s  += __shfl_xor_sync(0xffffffffu, s,  o);
        ss += __shfl_xor_sync(0xffffffffu, ss, o);
    }
    if ((t & 31) == 0) { wsum[t >> 5] = s; wsq[t >> 5] = ss; }
    __syncthreads();
    float S = 0.f, SS = 0.f;
    #pragma unroll
    for (int i = 0; i < 8; i++) { S += wsum[i]; SS += wsq[i]; }
    float mean = S * (1.0f / DIM);
    float var  = SS * (1.0f / DIM) - mean * mean;
    float rstd = rsqrtf(var + 1e-5f);
    float4 sc = ((const float4*)scale)[t];
    float4 bi = ((const float4*)bias)[t];
    __half* orow = out + (size_t)row * DIM + t * 4;
    *(__half2*)(orow)     = __floats2half2_rn((v.x - mean) * rstd * sc.x + bi.x,
                                              (v.y - mean) * rstd * sc.y + bi.y);
    *(__half2*)(orow + 2) = __floats2half2_rn((v.z - mean) * rstd * sc.z + bi.z,
                                              (v.w - mean) * rstd * sc.w + bi.w);
}

__device__ __forceinline__ float gelu_exact(float v) {
    return 0.5f * v * (1.0f + erff(v * 0.70710678118654752f));
}

// ---------------- fp16 GEMM BM=64/BN=256, BK=32, 4 stages, 2 CTA/SM ----------
// A[M,K] half row-major, Bt[N,K] half (transposed weights).
// EPI 0: Cf = tf32r(acc)  (fp32 out, for attention)
// EPI 2: Ch = half(gelu(acc + bias))
#define PADH 40                         // halves per row (32 data + 8 pad)
#define QH_A_ST (64*PADH)               // 2560 halves
#define QH_B_ST (256*PADH)              // 10240 halves
#define QH_ST   (QH_A_ST + QH_B_ST)     // 12800 halves
#define QH_SMEM (4 * QH_ST * 2)         // 102400 B

template<int EPI>
__global__ __launch_bounds__(256, 2)
void tc_gemmH(const __half* __restrict__ A, const __half* __restrict__ Bt,
              const float* __restrict__ bias, float* __restrict__ Cf,
              __half* __restrict__ Ch, int N, int K)
{
    extern __shared__ __half smh[];
    const uint32_t sb = smem_u32(smh);
    const int tid  = threadIdx.x;
    const int lane = tid & 31, wid = tid >> 5;
    const int wm = wid & 1, wn = wid >> 1;
    const int m0 = blockIdx.y * 64;
    const int n0 = blockIdx.x * 256;

    auto fill = [&](int s, int k0) {
        uint32_t ab = sb + (uint32_t)(s * QH_ST) * 2;
        uint32_t bb = ab + QH_A_ST * 2;
        {   // A: 64 rows x 32 halves = 256 chunks of 16B
            int r = tid >> 2, sg = tid & 3;
            cp16(ab + (uint32_t)(r * PADH + sg * 8) * 2,
                 A + (size_t)(m0 + r) * K + k0 + sg * 8);
        }
        #pragma unroll
        for (int it = 0; it < 4; it++) {   // B: 256 rows x 32 halves
            int idx = it * 256 + tid;
            int r = idx >> 2, sg = idx & 3;
            cp16(bb + (uint32_t)(r * PADH + sg * 8) * 2,
                 Bt + (size_t)(n0 + r) * K + k0 + sg * 8);
        }
    };

    float acc[2][8][4];
    #pragma unroll
    for (int i = 0; i < 2; i++)
        #pragma unroll
        for (int j = 0; j < 8; j++)
            #pragma unroll
            for (int q = 0; q < 4; q++) acc[i][j][q] = 0.f;

    const int NK = K >> 5;

    #pragma unroll
    for (int p = 0; p < 3; p++) { fill(p, p * 32); cp_commit(); }

    const int fr = lane >> 2, fc = lane & 3;

    for (int i = 0; i < NK; i++) {
        cp_wait<2>();
        __syncthreads();
        if (i + 3 < NK) fill((i + 3) & 3, (i + 3) * 32);
        cp_commit();

        const __half* As = smh + (i & 3) * QH_ST;
        const __half* Bs = As + QH_A_ST;

        #pragma unroll
        for (int ks = 0; ks < 2; ks++) {
            uint32_t af[2][4], bf[8][2];
            #pragma unroll
            for (int mt = 0; mt < 2; mt++) {
                const __half* ap = As + (wm * 32 + mt * 16 + fr) * PADH + ks * 16 + 2 * fc;
                af[mt][0] = *(const uint32_t*)(ap);
                af[mt][1] = *(const uint32_t*)(ap + 8 * PADH);
                af[mt][2] = *(const uint32_t*)(ap + 8);
                af[mt][3] = *(const uint32_t*)(ap + 8 * PADH + 8);
            }
            #pragma unroll
            for (int nt = 0; nt < 8; nt++) {
                const __half* bp = Bs + (wn * 64 + nt * 8 + fr) * PADH + ks * 16 + 2 * fc;
                bf[nt][0] = *(const uint32_t*)(bp);
                bf[nt][1] = *(const uint32_t*)(bp + 8);
            }
            #pragma unroll
            for (int mt = 0; mt < 2; mt++)
                #pragma unroll
                for (int nt = 0; nt < 8; nt++)
                    mma_f16(acc[mt][nt], af[mt], bf[nt]);
        }
    }

    #pragma unroll
    for (int mt = 0; mt < 2; mt++) {
        int row = m0 + wm * 32 + mt * 16 + fr;
        #pragma unroll
        for (int nt = 0; nt < 8; nt++) {
            int col = n0 + wn * 64 + nt * 8 + fc * 2;
            float* d = acc[mt][nt];
            size_t i0 = (size_t)row * N + col;
            size_t i1 = (size_t)(row + 8) * N + col;
            if (EPI == 0) {
                *(float2*)(Cf + i0) = make_float2(tf32r(d[0]), tf32r(d[1]));
                *(float2*)(Cf + i1) = make_float2(tf32r(d[2]), tf32r(d[3]));
            }
            if (EPI == 2) {
                float bx = bias[col], by = bias[col + 1];
                *(__half2*)(Ch + i0) = __floats2half2_rn(gelu_exact(d[0] + bx),
                                                         gelu_exact(d[1] + by));
                *(__half2*)(Ch + i1) = __floats2half2_rn(gelu_exact(d[2] + bx),
                                                         gelu_exact(d[3] + by));
            }
        }
    }
}

// ---------------- fp16 GEMM BM=64/BN=128, BK=32, 4 stages, 2 CTA/SM ----------
// C = acc + bias + resid  (fp32, in-place safe on x)
#define GH_A_ST (64*PADH)               // 2560 halves
#define GH_B_ST (128*PADH)              // 5120 halves
#define GH_ST   (GH_A_ST + GH_B_ST)     // 7680 halves
#define GH_SMEM (4 * GH_ST * 2)         // 61440 B

__global__ __launch_bounds__(256, 2)
void tc_gemm64H(const __half* __restrict__ A, const __half* __restrict__ Bt,
                const float* __restrict__ bias, const float* __restrict__ resid,
                float* __restrict__ C, int N, int K)
{
    extern __shared__ __half smh[];
    const uint32_t sb = smem_u32(smh);
    const int tid  = threadIdx.x;
    const int lane = tid & 31, wid = tid >> 5;
    const int wm = wid & 1, wn = wid >> 1;
    const int m0 = blockIdx.y * 64;
    const int n0 = blockIdx.x * 128;

    auto fill = [&](int s, int k0) {
        uint32_t ab = sb + (uint32_t)(s * GH_ST) * 2;
        uint32_t bb = ab + GH_A_ST * 2;
        {
            int r = tid >> 2, sg = tid & 3;
            cp16(ab + (uint32_t)(r * PADH + sg * 8) * 2,
                 A + (size_t)(m0 + r) * K + k0 + sg * 8);
        }
        #pragma unroll
        for (int it = 0; it < 2; it++) {
            int idx = it * 256 + tid;
            int r = idx >> 2, sg = idx & 3;
            cp16(bb + (uint32_t)(r * PADH + sg * 8) * 2,
                 Bt + (size_t)(n0 + r) * K + k0 + sg * 8);
        }
    };

    float acc[2][4][4];
    #pragma unroll
    for (int i = 0; i < 2; i++)
        #pragma unroll
        for (int j = 0; j < 4; j++)
            #pragma unroll
            for (int q = 0; q < 4; q++) acc[i][j][q] = 0.f;

    const int NK = K >> 5;

    #pragma unroll
    for (int p = 0; p < 3; p++) { fill(p, p * 32); cp_commit(); }

    const int fr = lane >> 2, fc = lane & 3;

    for (int i = 0; i < NK; i++) {
        cp_wait<2>();
        __syncthreads();
        if (i + 3 < NK) fill((i + 3) & 3, (i + 3) * 32);
        cp_commit();

        const __half* As = smh + (i & 3) * GH_ST;
        const __half* Bs = As + GH_A_ST;

        #pragma unroll
        for (int ks = 0; ks < 2; ks++) {
            uint32_t af[2][4], bf[4][2];
            #pragma unroll
            for (int mt = 0; mt < 2; mt++) {
                const __half* ap = As + (wm * 32 + mt * 16 + fr) * PADH + ks * 16 + 2 * fc;
                af[mt][0] = *(const uint32_t*)(ap);
                af[mt][1] = *(const uint32_t*)(ap + 8 * PADH);
                af[mt][2] = *(const uint32_t*)(ap + 8);
                af[mt][3] = *(const uint32_t*)(ap + 8 * PADH + 8);
            }
            #pragma unroll
            for (int nt = 0; nt < 4; nt++) {
                const __half* bp = Bs + (wn * 32 + nt * 8 + fr) * PADH + ks * 16 + 2 * fc;
                bf[nt][0] = *(const uint32_t*)(bp);
                bf[nt][1] = *(const uint32_t*)(bp + 8);
            }
            #pragma unroll
            for (int mt = 0; mt < 2; mt++)
                #pragma unroll
                for (int nt = 0; nt < 4; nt++)
                    mma_f16(acc[mt][nt], af[mt], bf[nt]);
        }
    }

    #pragma unroll
    for (int mt = 0; mt < 2; mt++) {
        int row = m0 + wm * 32 + mt * 16 + fr;
        #pragma unroll
        for (int nt = 0; nt < 4; nt++) {
            int col = n0 + wn * 32 + nt * 8 + fc * 2;
            float* d = acc[mt][nt];
            size_t i0 = (size_t)row * N + col;
            size_t i1 = (size_t)(row + 8) * N + col;
            float bx = bias[col], by = bias[col + 1];
            *(float2*)(C + i0) = make_float2(d[0] + bx + resid[i0],
                                            d[1] + by + resid[i0 + 1]);
            *(float2*)(C + i1) = make_float2(d[2] + bx + resid[i1],
                                            d[3] + by + resid[i1 + 1]);
        }
    }
}

// ---------------- Flash attention (tf32, validated; fp16 output) -------------
#define FA_PAD 72
#define FA_TILE (64*FA_PAD)
#define FA_SMEM (6*FA_TILE*4)      // 110592 B

__global__ __launch_bounds__(128) void fattn_kernel(
    const float* __restrict__ qkv, __half* __restrict__ o)
{
    extern __shared__ float sm[];
    float* Qs = sm;
    float* Ps = Qs + FA_TILE;
    float* Ks = Ps + FA_TILE;
    float* Vs = Ks + 2*FA_TILE;
    const uint32_t sb = smem_u32(sm);
    const uint32_t Qb = sb;
    const uint32_t Kb = sb + (uint32_t)(2*FA_TILE)*4;
    const uint32_t Vb = sb + (uint32_t)(4*FA_TILE)*4;

    const int tid = threadIdx.x, lane = tid & 31, w = tid >> 5;
    const int fr = lane >> 2, fc = lane & 3;
    const int bh = blockIdx.y;
    const int b = bh >> 4, h = bh & 15;
    const int q0 = blockIdx.x * 64;

    const float* qbase = qkv + (size_t)(b * SEQ) * (3 * ID) + h * DHEAD;
    const float* kbase = qbase + ID;
    const float* vbase = qbase + 2 * ID;

    #pragma unroll
    for (int it = 0; it < 8; it++) {
        int idx = it * 128 + tid;
        int r = idx >> 4, s4 = idx & 15;
        cp16(Qb + (uint32_t)(r * FA_PAD + s4 * 4) * 4,
             qbase + (size_t)(q0 + r) * 3072 + s4 * 4);
    }
    auto fillKV = [&](int c, int buf) {
        #pragma unroll
        for (int it = 0; it < 8; it++) {
            int idx = it * 128 + tid;
            int r = idx >> 4, s4 = idx & 15;
            cp16(Kb + (uint32_t)((buf * 64 + r) * FA_PAD + s4 * 4) * 4,
                 kbase + (size_t)(c * 64 + r) * 3072 + s4 * 4);
            cp16(Vb + (uint32_t)((buf * 64 + r) * FA_PAD + s4 * 4) * 4,
                 vbase + (size_t)(c * 64 + r) * 3072 + s4 * 4);
        }
    };
    fillKV(0, 0); cp_commit();

    float accO[8][4];
    #pragma unroll
    for (int nt = 0; nt < 8; nt++)
        #pragma unroll
        for (int q = 0; q < 4; q++) accO[nt][q] = 0.f;
    float M0 = -1e30f, M1 = -1e30f, L0 = 0.f, L1 = 0.f;

    const float* Prow0 = Ps + (w * 16 + fr) * FA_PAD;
    const int prow0_off = (w * 16 + fr) * FA_PAD;

    for (int c = 0; c < SEQ / 64; c++) {
        cp_wait<0>();
        __syncthreads();
        if (c + 1 < SEQ / 64) { fillKV(c + 1, (c + 1) & 1); cp_commit(); }

        const float* Kc = Ks + (c & 1) * FA_TILE;
        const float* Vc = Vs + (c & 1) * FA_TILE;

        float sacc[8][4];
        #pragma unroll
        for (int nt = 0; nt < 8; nt++)
            #pragma unroll
            for (int q = 0; q < 4; q++) sacc[nt][q] = 0.f;
        #pragma unroll
        for (int ks = 0; ks < 8; ks++) {
            uint32_t af[4];
            const float* qp = Qs + (w * 16 + fr) * FA_PAD + ks * 8 + fc;
            af[0] = __float_as_uint(qp[0]);
            af[1] = __float_as_uint(qp[8 * FA_PAD]);
            af[2] = __float_as_uint(qp[4]);
            af[3] = __float_as_uint(qp[8 * FA_PAD + 4]);
            #pragma unroll
            for (int nt = 0; nt < 8; nt++) {
                const float* kp = Kc + (nt * 8 + fr) * FA_PAD + ks * 8 + fc;
                uint32_t bf[2] = { __float_as_uint(kp[0]), __float_as_uint(kp[4]) };
                mma_tf32(sacc[nt], af, bf);
            }
        }

        float mx0 = -1e30f, mx1 = -1e30f;
        #pragma unroll
        for (int nt = 0; nt < 8; nt++) {
            sacc[nt][0] *= 0.125f; sacc[nt][1] *= 0.125f;
            sacc[nt][2] *= 0.125f; sacc[nt][3] *= 0.125f;
            mx0 = fmaxf(mx0, fmaxf(sacc[nt][0], sacc[nt][1]));
            mx1 = fmaxf(mx1, fmaxf(sacc[nt][2], sacc[nt][3]));
        }
        mx0 = fmaxf(mx0, __shfl_xor_sync(0xffffffffu, mx0, 1));
        mx0 = fmaxf(mx0, __shfl_xor_sync(0xffffffffu, mx0, 2));
        mx1 = fmaxf(mx1, __shfl_xor_sync(0xffffffffu, mx1, 1));
        mx1 = fmaxf(mx1, __shfl_xor_sync(0xffffffffu, mx1, 2));
        float Mn0 = fmaxf(M0, mx0), Mn1 = fmaxf(M1, mx1);
        float a0 = __expf(M0 - Mn0), a1 = __expf(M1 - Mn1);
        float s0 = 0.f, s1 = 0.f;
        #pragma unroll
        for (int nt = 0; nt < 8; nt++) {
            float p0 = __expf(sacc[nt][0] - Mn0), p1 = __expf(sacc[nt][1] - Mn0);
            float p2 = __expf(sacc[nt][2] - Mn1), p3 = __expf(sacc[nt][3] - Mn1);
            s0 += p0 + p1; s1 += p2 + p3;
            *(float2*)(Ps + prow0_off + nt * 8 + 2 * fc) =
                make_float2(tf32r(p0), tf32r(p1));
            *(float2*)(Ps + prow0_off + 8 * FA_PAD + nt * 8 + 2 * fc) =
                make_float2(tf32r(p2), tf32r(p3));
            accO[nt][0] *= a0; accO[nt][1] *= a0;
            accO[nt][2] *= a1; accO[nt][3] *= a1;
        }
        s0 += __shfl_xor_sync(0xffffffffu, s0, 1);
        s0 += __shfl_xor_sync(0xffffffffu, s0, 2);
        s1 += __shfl_xor_sync(0xffffffffu, s1, 1);
        s1 += __shfl_xor_sync(0xffffffffu, s1, 2);
        L0 = L0 * a0 + s0; L1 = L1 * a1 + s1;
        M0 = Mn0; M1 = Mn1;
        __syncwarp();

        #pragma unroll
        for (int ks = 0; ks < 8; ks++) {
            uint32_t af[4];
            const float* pp = Prow0 + ks * 8 + fc;
            af[0] = __float_as_uint(pp[0]);
            af[1] = __float_as_uint(pp[8 * FA_PAD]);
            af[2] = __float_as_uint(pp[4]);
            af[3] = __float_as_uint(pp[8 * FA_PAD + 4]);
            #pragma unroll
            for (int nt = 0; nt < 8; nt++) {
                const float* vp = Vc + (ks * 8 + fc) * FA_PAD + nt * 8 + fr;
                uint32_t bf[2] = { __float_as_uint(vp[0]), __float_as_uint(vp[4 * FA_PAD]) };
                mma_tf32(accO[nt], af, bf);
            }
        }
    }

    float inv0 = 1.0f / L0, inv1 = 1.0f / L1;
    size_t t0 = (size_t)(b * SEQ + q0 + w * 16 + fr);
    #pragma unroll
    for (int nt = 0; nt < 8; nt++) {
        int col = h * DHEAD + nt * 8 + 2 * fc;
        *(__half2*)(o + t0 * ID + col) =
            __floats2half2_rn(accO[nt][0] * inv0, accO[nt][1] * inv0);
        *(__half2*)(o + (t0 + 8) * ID + col) =
            __floats2half2_rn(accO[nt][2] * inv1, accO[nt][3] * inv1);
    }
}

// ---------------- driver ----------------
extern "C" void kernel_launch(void* const* d_in, const int* in_sizes, int n_in,
                              void* d_out, int out_size)
{
    const float* x_in = (const float*)d_in[0];
    const float* ln1s = (const float*)d_in[1];
    const float* ln1b = (const float*)d_in[2];
    const float* wqkv = (const float*)d_in[3];
    const float* wout = (const float*)d_in[4];
    const float* bout = (const float*)d_in[5];
    const float* ln2s = (const float*)d_in[6];
    const float* ln2b = (const float*)d_in[7];
    const float* w1   = (const float*)d_in[8];
    const float* b1   = (const float*)d_in[9];
    const float* w2   = (const float*)d_in[10];
    const float* b2   = (const float*)d_in[11];
    float* x = (float*)d_out;

    void* p;
    cudaGetSymbolAddress(&p, g_h);   __half* gh   = (__half*)p;
    cudaGetSymbolAddress(&p, g_qkv); float*  gqkv = (float*)p;
    cudaGetSymbolAddress(&p, g_o);   __half* go   = (__half*)p;
    cudaGetSymbolAddress(&p, g_a);   __half* ga   = (__half*)p;
    cudaGetSymbolAddress(&p, g_wh);  __half* gwh  = (__half*)p;

    __half* wh_qkv = gwh;
    __half* wh_out = wh_qkv + W_QKV_ELT;
    __half* wh_1   = wh_out + W_OUT_ELT;
    __half* wh_2   = wh_1   + W_1_ELT;

    cudaFuncSetAttribute(tc_gemmH<0>, cudaFuncAttributeMaxDynamicSharedMemorySize, QH_SMEM);
    cudaFuncSetAttribute(tc_gemmH<2>, cudaFuncAttributeMaxDynamicSharedMemorySize, QH_SMEM);
    cudaFuncSetAttribute(tc_gemm64H, cudaFuncAttributeMaxDynamicSharedMemorySize, GH_SMEM);
    cudaFuncSetAttribute(fattn_kernel, cudaFuncAttributeMaxDynamicSharedMemorySize, FA_SMEM);

    // convert + transpose all weights to fp16 [N][K]
    dim3 tb(32, 8);
    cvt_t_kernel<<<dim3(3*ID/32, DIM/32, LAYERS), tb>>>(wqkv, wh_qkv, DIM, 3*ID);
    cvt_t_kernel<<<dim3(DIM/32, ID/32, LAYERS), tb>>>(wout, wh_out, ID, DIM);
    cvt_t_kernel<<<dim3(FFN/32, DIM/32, LAYERS), tb>>>(w1, wh_1, DIM, FFN);
    cvt_t_kernel<<<dim3(DIM/32, FFN/32, LAYERS), tb>>>(w2, wh_2, FFN, DIM);

    cudaMemcpyAsync(x, x_in, (size_t)TOKENS * DIM * sizeof(float),
                    cudaMemcpyDeviceToDevice);

    for (int l = 0; l < LAYERS; l++) {
        const float* l1s = ln1s + l * DIM;
        const float* l1b = ln1b + l * DIM;
        const float* bo  = bout + l * DIM;
        const float* l2s = ln2s + l * DIM;
        const float* l2b = ln2b + l * DIM;
        const float* b1l = b1 + l * FFN;
        const float* b2l = b2 + l * DIM;
        const __half* wq  = wh_qkv + (size_t)l * DIM * 3 * ID;
        const __half* wo  = wh_out + (size_t)l * ID * DIM;
        const __half* w1l = wh_1 + (size_t)l * DIM * FFN;
        const __half* w2l = wh_2 + (size_t)l * FFN * DIM;

        // h = half(LN1(x))
        ln_kernel<<<TOKENS, 256>>>(x, l1s, l1b, gh);
        // qkv = tf32r(h @ wqkv)   (fp16 mma, fp32 out)
        tc_gemmH<0><<<dim3(3 * ID / 256, TOKENS / 64), 256, QH_SMEM>>>(
            gh, wq, nullptr, gqkv, nullptr, 3 * ID, DIM);
        // attention (tf32 flash; fp16 out)
        fattn_kernel<<<dim3(SEQ / 64, BATCH * HEADS), 128, FA_SMEM>>>(gqkv, go);
        // x = x + o @ wo + bo
        tc_gemm64H<<<dim3(DIM / 128, TOKENS / 64), 256, GH_SMEM>>>(
            go, wo, bo, x, x, DIM, ID);
        // h = half(LN2(x))
        ln_kernel<<<TOKENS, 256>>>(x, l2s, l2b, gh);
        // a = half(gelu(h @ w1 + b1))
        tc_gemmH<2><<<dim3(FFN / 256, TOKENS / 64), 256, QH_SMEM>>>(
            gh, w1l, b1l, nullptr, ga, FFN, DIM);
        // x = x + a @ w2 + b2
        tc_gemm64H<<<dim3(DIM / 128, TOKENS / 64), 256, GH_SMEM>>>(
            ga, w2l, b2l, x, x, DIM, FFN);
    }
}

// round 16
// speedup vs baseline: 2.6216x; 1.1610x over previous
#include <cuda_runtime.h>
#include <cuda_fp16.h>
#include <math.h>
#include <stdint.h>

#define LAYERS 6
#define BATCH  4
#define SEQ    512
#define DIM    1024
#define HEADS  16
#define DHEAD  64
#define FFN    4096
#define TOKENS (BATCH*SEQ)          // 2048
#define ID     (HEADS*DHEAD)        // 1024

#define W_QKV_ELT ((size_t)LAYERS*DIM*3*ID)
#define W_OUT_ELT ((size_t)LAYERS*ID*DIM)
#define W_1_ELT   ((size_t)LAYERS*DIM*FFN)
#define W_2_ELT   ((size_t)LAYERS*FFN*DIM)

// ---------------- scratch (allocation-guard safe) ----------------
__device__ __half g_h  [TOKENS*DIM];
__device__ float  g_qkv[TOKENS*3*ID];
__device__ __half g_o  [TOKENS*ID];
__device__ __half g_a  [(size_t)TOKENS*FFN];
__device__ __half g_wh [W_QKV_ELT + W_OUT_ELT + W_1_ELT + W_2_ELT];  // ~151MB

// ---------------- small PTX helpers ----------------
__device__ __forceinline__ uint32_t smem_u32(const void* p) {
    uint32_t a;
    asm("{ .reg .u64 t; cvta.to.shared.u64 t, %1; cvt.u32.u64 %0, t; }" : "=r"(a) : "l"(p));
    return a;
}
__device__ __forceinline__ void cp16(uint32_t dst, const void* src) {
    asm volatile("cp.async.cg.shared.global [%0], [%1], 16;" :: "r"(dst), "l"(src));
}
__device__ __forceinline__ void cp_commit() {
    asm volatile("cp.async.commit_group;" ::: "memory");
}
template<int N> __device__ __forceinline__ void cp_wait() {
    asm volatile("cp.async.wait_group %0;" :: "n"(N) : "memory");
}
__device__ __forceinline__ uint32_t f2tf(float x) {
    uint32_t u; asm("cvt.rna.tf32.f32 %0, %1;" : "=r"(u) : "f"(x)); return u;
}
__device__ __forceinline__ float tf32r(float x) { return __uint_as_float(f2tf(x)); }
__device__ __forceinline__ void mma_tf32(float* d, const uint32_t* a, const uint32_t* b) {
    asm volatile(
        "mma.sync.aligned.m16n8k8.row.col.f32.tf32.tf32.f32 "
        "{%0,%1,%2,%3}, {%4,%5,%6,%7}, {%8,%9}, {%0,%1,%2,%3};"
        : "+f"(d[0]), "+f"(d[1]), "+f"(d[2]), "+f"(d[3])
        : "r"(a[0]), "r"(a[1]), "r"(a[2]), "r"(a[3]), "r"(b[0]), "r"(b[1]));
}
__device__ __forceinline__ void mma_f16(float* d, const uint32_t* a, const uint32_t* b) {
    asm volatile(
        "mma.sync.aligned.m16n8k16.row.col.f32.f16.f16.f32 "
        "{%0,%1,%2,%3}, {%4,%5,%6,%7}, {%8,%9}, {%0,%1,%2,%3};"
        : "+f"(d[0]), "+f"(d[1]), "+f"(d[2]), "+f"(d[3])
        : "r"(a[0]), "r"(a[1]), "r"(a[2]), "r"(a[3]), "r"(b[0]), "r"(b[1]));
}
__device__ __forceinline__ void ldsm4(uint32_t& r0, uint32_t& r1, uint32_t& r2,
                                      uint32_t& r3, uint32_t addr) {
    asm volatile("ldmatrix.sync.aligned.m8n8.x4.shared.b16 {%0,%1,%2,%3}, [%4];"
                 : "=r"(r0), "=r"(r1), "=r"(r2), "=r"(r3) : "r"(addr));
}

// ---------------- weight convert + transpose: out[n][k] = half(in[k][n]) ----
__global__ __launch_bounds__(256) void cvt_t_kernel(
    const float* __restrict__ in, __half* __restrict__ out, int K, int N)
{
    __shared__ float tile[32][33];
    in  += (size_t)blockIdx.z * K * N;
    out += (size_t)blockIdx.z * K * N;
    int n0 = blockIdx.x * 32, k0 = blockIdx.y * 32;
    int tx = threadIdx.x, ty = threadIdx.y;
    #pragma unroll
    for (int i = 0; i < 4; i++)
        tile[ty + i * 8][tx] = in[(size_t)(k0 + ty + i * 8) * N + n0 + tx];
    __syncthreads();
    #pragma unroll
    for (int i = 0; i < 4; i++)
        out[(size_t)(n0 + ty + i * 8) * K + k0 + tx] =
            __float2half_rn(tile[tx][ty + i * 8]);
}

// ---------------- LayerNorm (fp16 output) ----------------
__global__ __launch_bounds__(256) void ln_kernel(
    const float* __restrict__ x, const float* __restrict__ scale,
    const float* __restrict__ bias, __half* __restrict__ out)
{
    __shared__ float wsum[8], wsq[8];
    int row = blockIdx.x, t = threadIdx.x;
    const float4* xr = (const float4*)(x + (size_t)row * DIM);
    float4 v = xr[t];
    float s  = v.x + v.y + v.z + v.w;
    float ss = v.x*v.x + v.y*v.y + v.z*v.z + v.w*v.w;
    #pragma unroll
    for (int o = 16; o; o >>= 1) {
        s  += __shfl_xor_sync(0xffffffffu, s,  o);
        ss += __shfl_xor_sync(0xffffffffu, ss, o);
    }
    if ((t & 31) == 0) { wsum[t >> 5] = s; wsq[t >> 5] = ss; }
    __syncthreads();
    float S = 0.f, SS = 0.f;
    #pragma unroll
    for (int i = 0; i < 8; i++) { S += wsum[i]; SS += wsq[i]; }
    float mean = S * (1.0f / DIM);
    float var  = SS * (1.0f / DIM) - mean * mean;
    float rstd = rsqrtf(var + 1e-5f);
    float4 sc = ((const float4*)scale)[t];
    float4 bi = ((const float4*)bias)[t];
    __half* orow = out + (size_t)row * DIM + t * 4;
    *(__half2*)(orow)     = __floats2half2_rn((v.x - mean) * rstd * sc.x + bi.x,
                                              (v.y - mean) * rstd * sc.y + bi.y);
    *(__half2*)(orow + 2) = __floats2half2_rn((v.z - mean) * rstd * sc.z + bi.z,
                                              (v.w - mean) * rstd * sc.w + bi.w);
}

__device__ __forceinline__ float gelu_exact(float v) {
    return 0.5f * v * (1.0f + erff(v * 0.70710678118654752f));
}

// ---------------- fp16 GEMM BM=64/BN=256, BK=32, 4 stages, 2 CTA/SM ----------
// ldmatrix fragment loads. A[M,K] half row-major, Bt[N,K] half (transposed).
// EPI 0: Cf = tf32r(acc) ; EPI 2: Ch = half(gelu(acc + bias))
#define PADH 40                         // halves per row (32 data + 8 pad)
#define QH_A_ST (64*PADH)               // 2560 halves
#define QH_B_ST (256*PADH)              // 10240 halves
#define QH_ST   (QH_A_ST + QH_B_ST)     // 12800 halves
#define QH_SMEM (4 * QH_ST * 2)         // 102400 B

template<int EPI>
__global__ __launch_bounds__(256, 2)
void tc_gemmH(const __half* __restrict__ A, const __half* __restrict__ Bt,
              const float* __restrict__ bias, float* __restrict__ Cf,
              __half* __restrict__ Ch, int N, int K)
{
    extern __shared__ __half smh[];
    const uint32_t sb = smem_u32(smh);
    const int tid  = threadIdx.x;
    const int lane = tid & 31, wid = tid >> 5;
    const int wm = wid & 1, wn = wid >> 1;
    const int m0 = blockIdx.y * 64;
    const int n0 = blockIdx.x * 256;

    auto fill = [&](int s, int k0) {
        uint32_t ab = sb + (uint32_t)(s * QH_ST) * 2;
        uint32_t bb = ab + QH_A_ST * 2;
        {
            int r = tid >> 2, sg = tid & 3;
            cp16(ab + (uint32_t)(r * PADH + sg * 8) * 2,
                 A + (size_t)(m0 + r) * K + k0 + sg * 8);
        }
        #pragma unroll
        for (int it = 0; it < 4; it++) {
            int idx = it * 256 + tid;
            int r = idx >> 2, sg = idx & 3;
            cp16(bb + (uint32_t)(r * PADH + sg * 8) * 2,
                 Bt + (size_t)(n0 + r) * K + k0 + sg * 8);
        }
    };

    float acc[2][8][4];
    #pragma unroll
    for (int i = 0; i < 2; i++)
        #pragma unroll
        for (int j = 0; j < 8; j++)
            #pragma unroll
            for (int q = 0; q < 4; q++) acc[i][j][q] = 0.f;

    const int NK = K >> 5;

    #pragma unroll
    for (int p = 0; p < 3; p++) { fill(p, p * 32); cp_commit(); }

    // ldmatrix per-thread row addresses (byte offsets within a stage)
    const uint32_t aOff = (uint32_t)((wm * 32 + (lane & 15)) * PADH
                                     + (lane >> 4) * 8) * 2;
    const uint32_t bOff = (uint32_t)((wn * 64 + ((lane >> 4) & 1) * 8 + (lane & 7)) * PADH
                                     + ((lane >> 3) & 1) * 8) * 2;

    for (int i = 0; i < NK; i++) {
        cp_wait<2>();
        __syncthreads();
        if (i + 3 < NK) fill((i + 3) & 3, (i + 3) * 32);
        cp_commit();

        const uint32_t abase = sb + (uint32_t)((i & 3) * QH_ST) * 2;
        const uint32_t bbase = abase + QH_A_ST * 2;

        #pragma unroll
        for (int ks = 0; ks < 2; ks++) {
            uint32_t af[2][4], bf[8][2];
            #pragma unroll
            for (int mt = 0; mt < 2; mt++)
                ldsm4(af[mt][0], af[mt][1], af[mt][2], af[mt][3],
                      abase + aOff + ks * 32 + (uint32_t)(mt * 16 * PADH) * 2);
            #pragma unroll
            for (int ntp = 0; ntp < 4; ntp++)
                ldsm4(bf[2*ntp][0], bf[2*ntp][1], bf[2*ntp+1][0], bf[2*ntp+1][1],
                      bbase + bOff + ks * 32 + (uint32_t)(ntp * 16 * PADH) * 2);
            #pragma unroll
            for (int mt = 0; mt < 2; mt++)
                #pragma unroll
                for (int nt = 0; nt < 8; nt++)
                    mma_f16(acc[mt][nt], af[mt], bf[nt]);
        }
    }

    const int fr = lane >> 2, fc = lane & 3;
    #pragma unroll
    for (int mt = 0; mt < 2; mt++) {
        int row = m0 + wm * 32 + mt * 16 + fr;
        #pragma unroll
        for (int nt = 0; nt < 8; nt++) {
            int col = n0 + wn * 64 + nt * 8 + fc * 2;
            float* d = acc[mt][nt];
            size_t i0 = (size_t)row * N + col;
            size_t i1 = (size_t)(row + 8) * N + col;
            if (EPI == 0) {
                *(float2*)(Cf + i0) = make_float2(tf32r(d[0]), tf32r(d[1]));
                *(float2*)(Cf + i1) = make_float2(tf32r(d[2]), tf32r(d[3]));
            }
            if (EPI == 2) {
                float bx = bias[col], by = bias[col + 1];
                *(__half2*)(Ch + i0) = __floats2half2_rn(gelu_exact(d[0] + bx),
                                                         gelu_exact(d[1] + by));
                *(__half2*)(Ch + i1) = __floats2half2_rn(gelu_exact(d[2] + bx),
                                                         gelu_exact(d[3] + by));
            }
        }
    }
}

// ---------------- fp16 GEMM BM=64/BN=128, BK=32, 4 stages, 2 CTA/SM ----------
#define GH_A_ST (64*PADH)               // 2560 halves
#define GH_B_ST (128*PADH)              // 5120 halves
#define GH_ST   (GH_A_ST + GH_B_ST)     // 7680 halves
#define GH_SMEM (4 * GH_ST * 2)         // 61440 B

__global__ __launch_bounds__(256, 2)
void tc_gemm64H(const __half* __restrict__ A, const __half* __restrict__ Bt,
                const float* __restrict__ bias, const float* __restrict__ resid,
                float* __restrict__ C, int N, int K)
{
    extern __shared__ __half smh[];
    const uint32_t sb = smem_u32(smh);
    const int tid  = threadIdx.x;
    const int lane = tid & 31, wid = tid >> 5;
    const int wm = wid & 1, wn = wid >> 1;
    const int m0 = blockIdx.y * 64;
    const int n0 = blockIdx.x * 128;

    auto fill = [&](int s, int k0) {
        uint32_t ab = sb + (uint32_t)(s * GH_ST) * 2;
        uint32_t bb = ab + GH_A_ST * 2;
        {
            int r = tid >> 2, sg = tid & 3;
            cp16(ab + (uint32_t)(r * PADH + sg * 8) * 2,
                 A + (size_t)(m0 + r) * K + k0 + sg * 8);
        }
        #pragma unroll
        for (int it = 0; it < 2; it++) {
            int idx = it * 256 + tid;
            int r = idx >> 2, sg = idx & 3;
            cp16(bb + (uint32_t)(r * PADH + sg * 8) * 2,
                 Bt + (size_t)(n0 + r) * K + k0 + sg * 8);
        }
    };

    float acc[2][4][4];
    #pragma unroll
    for (int i = 0; i < 2; i++)
        #pragma unroll
        for (int j = 0; j < 4; j++)
            #pragma unroll
            for (int q = 0; q < 4; q++) acc[i][j][q] = 0.f;

    const int NK = K >> 5;

    #pragma unroll
    for (int p = 0; p < 3; p++) { fill(p, p * 32); cp_commit(); }

    const uint32_t aOff = (uint32_t)((wm * 32 + (lane & 15)) * PADH
                                     + (lane >> 4) * 8) * 2;
    const uint32_t bOff = (uint32_t)((wn * 32 + ((lane >> 4) & 1) * 8 + (lane & 7)) * PADH
                                     + ((lane >> 3) & 1) * 8) * 2;

    for (int i = 0; i < NK; i++) {
        cp_wait<2>();
        __syncthreads();
        if (i + 3 < NK) fill((i + 3) & 3, (i + 3) * 32);
        cp_commit();

        const uint32_t abase = sb + (uint32_t)((i & 3) * GH_ST) * 2;
        const uint32_t bbase = abase + GH_A_ST * 2;

        #pragma unroll
        for (int ks = 0; ks < 2; ks++) {
            uint32_t af[2][4], bf[4][2];
            #pragma unroll
            for (int mt = 0; mt < 2; mt++)
                ldsm4(af[mt][0], af[mt][1], af[mt][2], af[mt][3],
                      abase + aOff + ks * 32 + (uint32_t)(mt * 16 * PADH) * 2);
            #pragma unroll
            for (int ntp = 0; ntp < 2; ntp++)
                ldsm4(bf[2*ntp][0], bf[2*ntp][1], bf[2*ntp+1][0], bf[2*ntp+1][1],
                      bbase + bOff + ks * 32 + (uint32_t)(ntp * 16 * PADH) * 2);
            #pragma unroll
            for (int mt = 0; mt < 2; mt++)
                #pragma unroll
                for (int nt = 0; nt < 4; nt++)
                    mma_f16(acc[mt][nt], af[mt], bf[nt]);
        }
    }

    const int fr = lane >> 2, fc = lane & 3;
    #pragma unroll
    for (int mt = 0; mt < 2; mt++) {
        int row = m0 + wm * 32 + mt * 16 + fr;
        #pragma unroll
        for (int nt = 0; nt < 4; nt++) {
            int col = n0 + wn * 32 + nt * 8 + fc * 2;
            float* d = acc[mt][nt];
            size_t i0 = (size_t)row * N + col;
            size_t i1 = (size_t)(row + 8) * N + col;
            float bx = bias[col], by = bias[col + 1];
            *(float2*)(C + i0) = make_float2(d[0] + bx + resid[i0],
                                            d[1] + by + resid[i0 + 1]);
            *(float2*)(C + i1) = make_float2(d[2] + bx + resid[i1],
                                            d[3] + by + resid[i1 + 1]);
        }
    }
}

// ---------------- Flash attention (tf32, validated; fp16 output) -------------
#define FA_PAD 72
#define FA_TILE (64*FA_PAD)
#define FA_SMEM (6*FA_TILE*4)      // 110592 B

__global__ __launch_bounds__(128) void fattn_kernel(
    const float* __restrict__ qkv, __half* __restrict__ o)
{
    extern __shared__ float sm[];
    float* Qs = sm;
    float* Ps = Qs + FA_TILE;
    float* Ks = Ps + FA_TILE;
    float* Vs = Ks + 2*FA_TILE;
    const uint32_t sb = smem_u32(sm);
    const uint32_t Qb = sb;
    const uint32_t Kb = sb + (uint32_t)(2*FA_TILE)*4;
    const uint32_t Vb = sb + (uint32_t)(4*FA_TILE)*4;

    const int tid = threadIdx.x, lane = tid & 31, w = tid >> 5;
    const int fr = lane >> 2, fc = lane & 3;
    const int bh = blockIdx.y;
    const int b = bh >> 4, h = bh & 15;
    const int q0 = blockIdx.x * 64;

    const float* qbase = qkv + (size_t)(b * SEQ) * (3 * ID) + h * DHEAD;
    const float* kbase = qbase + ID;
    const float* vbase = qbase + 2 * ID;

    #pragma unroll
    for (int it = 0; it < 8; it++) {
        int idx = it * 128 + tid;
        int r = idx >> 4, s4 = idx & 15;
        cp16(Qb + (uint32_t)(r * FA_PAD + s4 * 4) * 4,
             qbase + (size_t)(q0 + r) * 3072 + s4 * 4);
    }
    auto fillKV = [&](int c, int buf) {
        #pragma unroll
        for (int it = 0; it < 8; it++) {
            int idx = it * 128 + tid;
            int r = idx >> 4, s4 = idx & 15;
            cp16(Kb + (uint32_t)((buf * 64 + r) * FA_PAD + s4 * 4) * 4,
                 kbase + (size_t)(c * 64 + r) * 3072 + s4 * 4);
            cp16(Vb + (uint32_t)((buf * 64 + r) * FA_PAD + s4 * 4) * 4,
                 vbase + (size_t)(c * 64 + r) * 3072 + s4 * 4);
        }
    };
    fillKV(0, 0); cp_commit();

    float accO[8][4];
    #pragma unroll
    for (int nt = 0; nt < 8; nt++)
        #pragma unroll
        for (int q = 0; q < 4; q++) accO[nt][q] = 0.f;
    float M0 = -1e30f, M1 = -1e30f, L0 = 0.f, L1 = 0.f;

    const float* Prow0 = Ps + (w * 16 + fr) * FA_PAD;
    const int prow0_off = (w * 16 + fr) * FA_PAD;

    for (int c = 0; c < SEQ / 64; c++) {
        cp_wait<0>();
        __syncthreads();
        if (c + 1 < SEQ / 64) { fillKV(c + 1, (c + 1) & 1); cp_commit(); }

        const float* Kc = Ks + (c & 1) * FA_TILE;
        const float* Vc = Vs + (c & 1) * FA_TILE;

        float sacc[8][4];
        #pragma unroll
        for (int nt = 0; nt < 8; nt++)
            #pragma unroll
            for (int q = 0; q < 4; q++) sacc[nt][q] = 0.f;
        #pragma unroll
        for (int ks = 0; ks < 8; ks++) {
            uint32_t af[4];
            const float* qp = Qs + (w * 16 + fr) * FA_PAD + ks * 8 + fc;
            af[0] = __float_as_uint(qp[0]);
            af[1] = __float_as_uint(qp[8 * FA_PAD]);
            af[2] = __float_as_uint(qp[4]);
            af[3] = __float_as_uint(qp[8 * FA_PAD + 4]);
            #pragma unroll
            for (int nt = 0; nt < 8; nt++) {
                const float* kp = Kc + (nt * 8 + fr) * FA_PAD + ks * 8 + fc;
                uint32_t bf[2] = { __float_as_uint(kp[0]), __float_as_uint(kp[4]) };
                mma_tf32(sacc[nt], af, bf);
            }
        }

        float mx0 = -1e30f, mx1 = -1e30f;
        #pragma unroll
        for (int nt = 0; nt < 8; nt++) {
            sacc[nt][0] *= 0.125f; sacc[nt][1] *= 0.125f;
            sacc[nt][2] *= 0.125f; sacc[nt][3] *= 0.125f;
            mx0 = fmaxf(mx0, fmaxf(sacc[nt][0], sacc[nt][1]));
            mx1 = fmaxf(mx1, fmaxf(sacc[nt][2], sacc[nt][3]));
        }
        mx0 = fmaxf(mx0, __shfl_xor_sync(0xffffffffu, mx0, 1));
        mx0 = fmaxf(mx0, __shfl_xor_sync(0xffffffffu, mx0, 2));
        mx1 = fmaxf(mx1, __shfl_xor_sync(0xffffffffu, mx1, 1));
        mx1 = fmaxf(mx1, __shfl_xor_sync(0xffffffffu, mx1, 2));
        float Mn0 = fmaxf(M0, mx0), Mn1 = fmaxf(M1, mx1);
        float a0 = __expf(M0 - Mn0), a1 = __expf(M1 - Mn1);
        float s0 = 0.f, s1 = 0.f;
        #pragma unroll
        for (int nt = 0; nt < 8; nt++) {
            float p0 = __expf(sacc[nt][0] - Mn0), p1 = __expf(sacc[nt][1] - Mn0);
            float p2 = __expf(sacc[nt][2] - Mn1), p3 = __expf(sacc[nt][3] - Mn1);
            s0 += p0 + p1; s1 += p2 + p3;
            *(float2*)(Ps + prow0_off + nt * 8 + 2 * fc) =
                make_float2(tf32r(p0), tf32r(p1));
            *(float2*)(Ps + prow0_off + 8 * FA_PAD + nt * 8 + 2 * fc) =
                make_float2(tf32r(p2), tf32r(p3));
            accO[nt][0] *= a0; accO[nt][1] *= a0;
            accO[nt][2] *= a1; accO[nt][3] *= a1;
        }
        s0 += __shfl_xor_sync(0xffffffffu, s0, 1);
        s0 += __shfl_xor_sync(0xffffffffu, s0, 2);
        s1 += __shfl_xor_sync(0xffffffffu, s1, 1);
        s1 += __shfl_xor_sync(0xffffffffu, s1, 2);
        L0 = L0 * a0 + s0; L1 = L1 * a1 + s1;
        M0 = Mn0; M1 = Mn1;
        __syncwarp();

        #pragma unroll
        for (int ks = 0; ks < 8; ks++) {
            uint32_t af[4];
            const float* pp = Prow0 + ks * 8 + fc;
            af[0] = __float_as_uint(pp[0]);
            af[1] = __float_as_uint(pp[8 * FA_PAD]);
            af[2] = __float_as_uint(pp[4]);
            af[3] = __float_as_uint(pp[8 * FA_PAD + 4]);
            #pragma unroll
            for (int nt = 0; nt < 8; nt++) {
                const float* vp = Vc + (ks * 8 + fc) * FA_PAD + nt * 8 + fr;
                uint32_t bf[2] = { __float_as_uint(vp[0]), __float_as_uint(vp[4 * FA_PAD]) };
                mma_tf32(accO[nt], af, bf);
            }
        }
    }

    float inv0 = 1.0f / L0, inv1 = 1.0f / L1;
    size_t t0 = (size_t)(b * SEQ + q0 + w * 16 + fr);
    #pragma unroll
    for (int nt = 0; nt < 8; nt++) {
        int col = h * DHEAD + nt * 8 + 2 * fc;
        *(__half2*)(o + t0 * ID + col) =
            __floats2half2_rn(accO[nt][0] * inv0, accO[nt][1] * inv0);
        *(__half2*)(o + (t0 + 8) * ID + col) =
            __floats2half2_rn(accO[nt][2] * inv1, accO[nt][3] * inv1);
    }
}

// ---------------- driver ----------------
extern "C" void kernel_launch(void* const* d_in, const int* in_sizes, int n_in,
                              void* d_out, int out_size)
{
    const float* x_in = (const float*)d_in[0];
    const float* ln1s = (const float*)d_in[1];
    const float* ln1b = (const float*)d_in[2];
    const float* wqkv = (const float*)d_in[3];
    const float* wout = (const float*)d_in[4];
    const float* bout = (const float*)d_in[5];
    const float* ln2s = (const float*)d_in[6];
    const float* ln2b = (const float*)d_in[7];
    const float* w1   = (const float*)d_in[8];
    const float* b1   = (const float*)d_in[9];
    const float* w2   = (const float*)d_in[10];
    const float* b2   = (const float*)d_in[11];
    float* x = (float*)d_out;

    void* p;
    cudaGetSymbolAddress(&p, g_h);   __half* gh   = (__half*)p;
    cudaGetSymbolAddress(&p, g_qkv); float*  gqkv = (float*)p;
    cudaGetSymbolAddress(&p, g_o);   __half* go   = (__half*)p;
    cudaGetSymbolAddress(&p, g_a);   __half* ga   = (__half*)p;
    cudaGetSymbolAddress(&p, g_wh);  __half* gwh  = (__half*)p;

    __half* wh_qkv = gwh;
    __half* wh_out = wh_qkv + W_QKV_ELT;
    __half* wh_1   = wh_out + W_OUT_ELT;
    __half* wh_2   = wh_1   + W_1_ELT;

    cudaFuncSetAttribute(tc_gemmH<0>, cudaFuncAttributeMaxDynamicSharedMemorySize, QH_SMEM);
    cudaFuncSetAttribute(tc_gemmH<2>, cudaFuncAttributeMaxDynamicSharedMemorySize, QH_SMEM);
    cudaFuncSetAttribute(tc_gemm64H, cudaFuncAttributeMaxDynamicSharedMemorySize, GH_SMEM);
    cudaFuncSetAttribute(fattn_kernel, cudaFuncAttributeMaxDynamicSharedMemorySize, FA_SMEM);

    // convert + transpose all weights to fp16 [N][K]
    dim3 tb(32, 8);
    cvt_t_kernel<<<dim3(3*ID/32, DIM/32, LAYERS), tb>>>(wqkv, wh_qkv, DIM, 3*ID);
    cvt_t_kernel<<<dim3(DIM/32, ID/32, LAYERS), tb>>>(wout, wh_out, ID, DIM);
    cvt_t_kernel<<<dim3(FFN/32, DIM/32, LAYERS), tb>>>(w1, wh_1, DIM, FFN);
    cvt_t_kernel<<<dim3(DIM/32, FFN/32, LAYERS), tb>>>(w2, wh_2, FFN, DIM);

    cudaMemcpyAsync(x, x_in, (size_t)TOKENS * DIM * sizeof(float),
                    cudaMemcpyDeviceToDevice);

    for (int l = 0; l < LAYERS; l++) {
        const float* l1s = ln1s + l * DIM;
        const float* l1b = ln1b + l * DIM;
        const float* bo  = bout + l * DIM;
        const float* l2s = ln2s + l * DIM;
        const float* l2b = ln2b + l * DIM;
        const float* b1l = b1 + l * FFN;
        const float* b2l = b2 + l * DIM;
        const __half* wq  = wh_qkv + (size_t)l * DIM * 3 * ID;
        const __half* wo  = wh_out + (size_t)l * ID * DIM;
        const __half* w1l = wh_1 + (size_t)l * DIM * FFN;
        const __half* w2l = wh_2 + (size_t)l * FFN * DIM;

        // h = half(LN1(x))
        ln_kernel<<<TOKENS, 256>>>(x, l1s, l1b, gh);
        // qkv = tf32r(h @ wqkv)
        tc_gemmH<0><<<dim3(3 * ID / 256, TOKENS / 64), 256, QH_SMEM>>>(
            gh, wq, nullptr, gqkv, nullptr, 3 * ID, DIM);
        // attention (tf32 flash; fp16 out)
        fattn_kernel<<<dim3(SEQ / 64, BATCH * HEADS), 128, FA_SMEM>>>(gqkv, go);
        // x = x + o @ wo + bo
        tc_gemm64H<<<dim3(DIM / 128, TOKENS / 64), 256, GH_SMEM>>>(
            go, wo, bo, x, x, DIM, ID);
        // h = half(LN2(x))
        ln_kernel<<<TOKENS, 256>>>(x, l2s, l2b, gh);
        // a = half(gelu(h @ w1 + b1))
        tc_gemmH<2><<<dim3(FFN / 256, TOKENS / 64), 256, QH_SMEM>>>(
            gh, w1l, b1l, nullptr, ga, FFN, DIM);
        // x = x + a @ w2 + b2
        tc_gemm64H<<<dim3(DIM / 128, TOKENS / 64), 256, GH_SMEM>>>(
            ga, w2l, b2l, x, x, DIM, FFN);
    }
}

// round 17
// speedup vs baseline: 2.8894x; 1.1021x over previous
#include <cuda_runtime.h>
#include <cuda_fp16.h>
#include <math.h>
#include <stdint.h>

#define LAYERS 6
#define BATCH  4
#define SEQ    512
#define DIM    1024
#define HEADS  16
#define DHEAD  64
#define FFN    4096
#define TOKENS (BATCH*SEQ)          // 2048
#define ID     (HEADS*DHEAD)        // 1024

#define W_QKV_ELT ((size_t)LAYERS*DIM*3*ID)
#define W_OUT_ELT ((size_t)LAYERS*ID*DIM)
#define W_1_ELT   ((size_t)LAYERS*DIM*FFN)
#define W_2_ELT   ((size_t)LAYERS*FFN*DIM)

// ---------------- scratch (allocation-guard safe) ----------------
__device__ __half g_h  [TOKENS*DIM];
__device__ __half g_qkv[TOKENS*3*ID];
__device__ __half g_o  [TOKENS*ID];
__device__ __half g_a  [(size_t)TOKENS*FFN];
__device__ __half g_wh [W_QKV_ELT + W_OUT_ELT + W_1_ELT + W_2_ELT];  // ~151MB

// ---------------- small PTX helpers ----------------
__device__ __forceinline__ uint32_t smem_u32(const void* p) {
    uint32_t a;
    asm("{ .reg .u64 t; cvta.to.shared.u64 t, %1; cvt.u32.u64 %0, t; }" : "=r"(a) : "l"(p));
    return a;
}
__device__ __forceinline__ void cp16(uint32_t dst, const void* src) {
    asm volatile("cp.async.cg.shared.global [%0], [%1], 16;" :: "r"(dst), "l"(src));
}
__device__ __forceinline__ void cp_commit() {
    asm volatile("cp.async.commit_group;" ::: "memory");
}
template<int N> __device__ __forceinline__ void cp_wait() {
    asm volatile("cp.async.wait_group %0;" :: "n"(N) : "memory");
}
__device__ __forceinline__ void mma_f16(float* d, const uint32_t* a, const uint32_t* b) {
    asm volatile(
        "mma.sync.aligned.m16n8k16.row.col.f32.f16.f16.f32 "
        "{%0,%1,%2,%3}, {%4,%5,%6,%7}, {%8,%9}, {%0,%1,%2,%3};"
        : "+f"(d[0]), "+f"(d[1]), "+f"(d[2]), "+f"(d[3])
        : "r"(a[0]), "r"(a[1]), "r"(a[2]), "r"(a[3]), "r"(b[0]), "r"(b[1]));
}
__device__ __forceinline__ void ldsm4(uint32_t& r0, uint32_t& r1, uint32_t& r2,
                                      uint32_t& r3, uint32_t addr) {
    asm volatile("ldmatrix.sync.aligned.m8n8.x4.shared.b16 {%0,%1,%2,%3}, [%4];"
                 : "=r"(r0), "=r"(r1), "=r"(r2), "=r"(r3) : "r"(addr));
}
__device__ __forceinline__ void ldsm4t(uint32_t& r0, uint32_t& r1, uint32_t& r2,
                                       uint32_t& r3, uint32_t addr) {
    asm volatile("ldmatrix.sync.aligned.m8n8.x4.trans.shared.b16 {%0,%1,%2,%3}, [%4];"
                 : "=r"(r0), "=r"(r1), "=r"(r2), "=r"(r3) : "r"(addr));
}

// ---------------- weight convert + transpose: out[n][k] = half(in[k][n]) ----
__global__ __launch_bounds__(256) void cvt_t_kernel(
    const float* __restrict__ in, __half* __restrict__ out, int K, int N)
{
    __shared__ float tile[32][33];
    in  += (size_t)blockIdx.z * K * N;
    out += (size_t)blockIdx.z * K * N;
    int n0 = blockIdx.x * 32, k0 = blockIdx.y * 32;
    int tx = threadIdx.x, ty = threadIdx.y;
    #pragma unroll
    for (int i = 0; i < 4; i++)
        tile[ty + i * 8][tx] = in[(size_t)(k0 + ty + i * 8) * N + n0 + tx];
    __syncthreads();
    #pragma unroll
    for (int i = 0; i < 4; i++)
        out[(size_t)(n0 + ty + i * 8) * K + k0 + tx] =
            __float2half_rn(tile[tx][ty + i * 8]);
}

// ---------------- LayerNorm (fp16 output) ----------------
__global__ __launch_bounds__(256) void ln_kernel(
    const float* __restrict__ x, const float* __restrict__ scale,
    const float* __restrict__ bias, __half* __restrict__ out)
{
    __shared__ float wsum[8], wsq[8];
    int row = blockIdx.x, t = threadIdx.x;
    const float4* xr = (const float4*)(x + (size_t)row * DIM);
    float4 v = xr[t];
    float s  = v.x + v.y + v.z + v.w;
    float ss = v.x*v.x + v.y*v.y + v.z*v.z + v.w*v.w;
    #pragma unroll
    for (int o = 16; o; o >>= 1) {
        s  += __shfl_xor_sync(0xffffffffu, s,  o);
        ss += __shfl_xor_sync(0xffffffffu, ss, o);
    }
    if ((t & 31) == 0) { wsum[t >> 5] = s; wsq[t >> 5] = ss; }
    __syncthreads();
    float S = 0.f, SS = 0.f;
    #pragma unroll
    for (int i = 0; i < 8; i++) { S += wsum[i]; SS += wsq[i]; }
    float mean = S * (1.0f / DIM);
    float var  = SS * (1.0f / DIM) - mean * mean;
    float rstd = rsqrtf(var + 1e-5f);
    float4 sc = ((const float4*)scale)[t];
    float4 bi = ((const float4*)bias)[t];
    __half* orow = out + (size_t)row * DIM + t * 4;
    *(__half2*)(orow)     = __floats2half2_rn((v.x - mean) * rstd * sc.x + bi.x,
                                              (v.y - mean) * rstd * sc.y + bi.y);
    *(__half2*)(orow + 2) = __floats2half2_rn((v.z - mean) * rstd * sc.z + bi.z,
                                              (v.w - mean) * rstd * sc.w + bi.w);
}

__device__ __forceinline__ float gelu_exact(float v) {
    return 0.5f * v * (1.0f + erff(v * 0.70710678118654752f));
}

// ---------------- fp16 GEMM BM=64/BN=256, BK=32, 4 stages, 2 CTA/SM ----------
// EPI 0: Ch = half(acc) ; EPI 2: Ch = half(gelu(acc + bias))
#define PADH 40
#define QH_A_ST (64*PADH)
#define QH_B_ST (256*PADH)
#define QH_ST   (QH_A_ST + QH_B_ST)
#define QH_SMEM (4 * QH_ST * 2)         // 102400 B

template<int EPI>
__global__ __launch_bounds__(256, 2)
void tc_gemmH(const __half* __restrict__ A, const __half* __restrict__ Bt,
              const float* __restrict__ bias, __half* __restrict__ Ch,
              int N, int K)
{
    extern __shared__ __half smh[];
    const uint32_t sb = smem_u32(smh);
    const int tid  = threadIdx.x;
    const int lane = tid & 31, wid = tid >> 5;
    const int wm = wid & 1, wn = wid >> 1;
    const int m0 = blockIdx.y * 64;
    const int n0 = blockIdx.x * 256;

    auto fill = [&](int s, int k0) {
        uint32_t ab = sb + (uint32_t)(s * QH_ST) * 2;
        uint32_t bb = ab + QH_A_ST * 2;
        {
            int r = tid >> 2, sg = tid & 3;
            cp16(ab + (uint32_t)(r * PADH + sg * 8) * 2,
                 A + (size_t)(m0 + r) * K + k0 + sg * 8);
        }
        #pragma unroll
        for (int it = 0; it < 4; it++) {
            int idx = it * 256 + tid;
            int r = idx >> 2, sg = idx & 3;
            cp16(bb + (uint32_t)(r * PADH + sg * 8) * 2,
                 Bt + (size_t)(n0 + r) * K + k0 + sg * 8);
        }
    };

    float acc[2][8][4];
    #pragma unroll
    for (int i = 0; i < 2; i++)
        #pragma unroll
        for (int j = 0; j < 8; j++)
            #pragma unroll
            for (int q = 0; q < 4; q++) acc[i][j][q] = 0.f;

    const int NK = K >> 5;

    #pragma unroll
    for (int p = 0; p < 3; p++) { fill(p, p * 32); cp_commit(); }

    const uint32_t aOff = (uint32_t)((wm * 32 + (lane & 15)) * PADH
                                     + (lane >> 4) * 8) * 2;
    const uint32_t bOff = (uint32_t)((wn * 64 + ((lane >> 4) & 1) * 8 + (lane & 7)) * PADH
                                     + ((lane >> 3) & 1) * 8) * 2;

    for (int i = 0; i < NK; i++) {
        cp_wait<2>();
        __syncthreads();
        if (i + 3 < NK) fill((i + 3) & 3, (i + 3) * 32);
        cp_commit();

        const uint32_t abase = sb + (uint32_t)((i & 3) * QH_ST) * 2;
        const uint32_t bbase = abase + QH_A_ST * 2;

        #pragma unroll
        for (int ks = 0; ks < 2; ks++) {
            uint32_t af[2][4], bf[8][2];
            #pragma unroll
            for (int mt = 0; mt < 2; mt++)
                ldsm4(af[mt][0], af[mt][1], af[mt][2], af[mt][3],
                      abase + aOff + ks * 32 + (uint32_t)(mt * 16 * PADH) * 2);
            #pragma unroll
            for (int ntp = 0; ntp < 4; ntp++)
                ldsm4(bf[2*ntp][0], bf[2*ntp][1], bf[2*ntp+1][0], bf[2*ntp+1][1],
                      bbase + bOff + ks * 32 + (uint32_t)(ntp * 16 * PADH) * 2);
            #pragma unroll
            for (int mt = 0; mt < 2; mt++)
                #pragma unroll
                for (int nt = 0; nt < 8; nt++)
                    mma_f16(acc[mt][nt], af[mt], bf[nt]);
        }
    }

    const int fr = lane >> 2, fc = lane & 3;
    #pragma unroll
    for (int mt = 0; mt < 2; mt++) {
        int row = m0 + wm * 32 + mt * 16 + fr;
        #pragma unroll
        for (int nt = 0; nt < 8; nt++) {
            int col = n0 + wn * 64 + nt * 8 + fc * 2;
            float* d = acc[mt][nt];
            size_t i0 = (size_t)row * N + col;
            size_t i1 = (size_t)(row + 8) * N + col;
            if (EPI == 0) {
                *(__half2*)(Ch + i0) = __floats2half2_rn(d[0], d[1]);
                *(__half2*)(Ch + i1) = __floats2half2_rn(d[2], d[3]);
            }
            if (EPI == 2) {
                float bx = bias[col], by = bias[col + 1];
                *(__half2*)(Ch + i0) = __floats2half2_rn(gelu_exact(d[0] + bx),
                                                         gelu_exact(d[1] + by));
                *(__half2*)(Ch + i1) = __floats2half2_rn(gelu_exact(d[2] + bx),
                                                         gelu_exact(d[3] + by));
            }
        }
    }
}

// ---------------- fp16 GEMM BM=64/BN=128, BK=32, 4 stages, 2 CTA/SM ----------
#define GH_A_ST (64*PADH)
#define GH_B_ST (128*PADH)
#define GH_ST   (GH_A_ST + GH_B_ST)
#define GH_SMEM (4 * GH_ST * 2)         // 61440 B

__global__ __launch_bounds__(256, 2)
void tc_gemm64H(const __half* __restrict__ A, const __half* __restrict__ Bt,
                const float* __restrict__ bias, const float* __restrict__ resid,
                float* __restrict__ C, int N, int K)
{
    extern __shared__ __half smh[];
    const uint32_t sb = smem_u32(smh);
    const int tid  = threadIdx.x;
    const int lane = tid & 31, wid = tid >> 5;
    const int wm = wid & 1, wn = wid >> 1;
    const int m0 = blockIdx.y * 64;
    const int n0 = blockIdx.x * 128;

    auto fill = [&](int s, int k0) {
        uint32_t ab = sb + (uint32_t)(s * GH_ST) * 2;
        uint32_t bb = ab + GH_A_ST * 2;
        {
            int r = tid >> 2, sg = tid & 3;
            cp16(ab + (uint32_t)(r * PADH + sg * 8) * 2,
                 A + (size_t)(m0 + r) * K + k0 + sg * 8);
        }
        #pragma unroll
        for (int it = 0; it < 2; it++) {
            int idx = it * 256 + tid;
            int r = idx >> 2, sg = idx & 3;
            cp16(bb + (uint32_t)(r * PADH + sg * 8) * 2,
                 Bt + (size_t)(n0 + r) * K + k0 + sg * 8);
        }
    };

    float acc[2][4][4];
    #pragma unroll
    for (int i = 0; i < 2; i++)
        #pragma unroll
        for (int j = 0; j < 4; j++)
            #pragma unroll
            for (int q = 0; q < 4; q++) acc[i][j][q] = 0.f;

    const int NK = K >> 5;

    #pragma unroll
    for (int p = 0; p < 3; p++) { fill(p, p * 32); cp_commit(); }

    const uint32_t aOff = (uint32_t)((wm * 32 + (lane & 15)) * PADH
                                     + (lane >> 4) * 8) * 2;
    const uint32_t bOff = (uint32_t)((wn * 32 + ((lane >> 4) & 1) * 8 + (lane & 7)) * PADH
                                     + ((lane >> 3) & 1) * 8) * 2;

    for (int i = 0; i < NK; i++) {
        cp_wait<2>();
        __syncthreads();
        if (i + 3 < NK) fill((i + 3) & 3, (i + 3) * 32);
        cp_commit();

        const uint32_t abase = sb + (uint32_t)((i & 3) * GH_ST) * 2;
        const uint32_t bbase = abase + GH_A_ST * 2;

        #pragma unroll
        for (int ks = 0; ks < 2; ks++) {
            uint32_t af[2][4], bf[4][2];
            #pragma unroll
            for (int mt = 0; mt < 2; mt++)
                ldsm4(af[mt][0], af[mt][1], af[mt][2], af[mt][3],
                      abase + aOff + ks * 32 + (uint32_t)(mt * 16 * PADH) * 2);
            #pragma unroll
            for (int ntp = 0; ntp < 2; ntp++)
                ldsm4(bf[2*ntp][0], bf[2*ntp][1], bf[2*ntp+1][0], bf[2*ntp+1][1],
                      bbase + bOff + ks * 32 + (uint32_t)(ntp * 16 * PADH) * 2);
            #pragma unroll
            for (int mt = 0; mt < 2; mt++)
                #pragma unroll
                for (int nt = 0; nt < 4; nt++)
                    mma_f16(acc[mt][nt], af[mt], bf[nt]);
        }
    }

    const int fr = lane >> 2, fc = lane & 3;
    #pragma unroll
    for (int mt = 0; mt < 2; mt++) {
        int row = m0 + wm * 32 + mt * 16 + fr;
        #pragma unroll
        for (int nt = 0; nt < 4; nt++) {
            int col = n0 + wn * 32 + nt * 8 + fc * 2;
            float* d = acc[mt][nt];
            size_t i0 = (size_t)row * N + col;
            size_t i1 = (size_t)(row + 8) * N + col;
            float bx = bias[col], by = bias[col + 1];
            *(float2*)(C + i0) = make_float2(d[0] + bx + resid[i0],
                                            d[1] + by + resid[i0 + 1]);
            *(float2*)(C + i1) = make_float2(d[2] + bx + resid[i1],
                                            d[3] + by + resid[i1 + 1]);
        }
    }
}

// ---------------- fp16 flash attention (ldmatrix + mma.f16) ------------------
// grid (SEQ/64, B*H), 128 threads (4 warps x 16 q-rows).
// Tiles fp16 stride 72 halves (144B rows -> conflict-free ldmatrix).
// S = Q K^T (K non-trans ldmatrix), O += P V (V trans ldmatrix).
#define FPAD 72
#define FTILE (64*FPAD)                  // halves
#define FA_SMEM (6*FTILE*2)              // Q,P + 2K + 2V = 55296 B

__global__ __launch_bounds__(128) void fattn_kernel(
    const __half* __restrict__ qkv, __half* __restrict__ o)
{
    extern __shared__ __half smA[];
    const uint32_t sb = smem_u32(smA);
    const uint32_t Qb = sb;
    const uint32_t Pb = sb + (uint32_t)FTILE * 2;
    const uint32_t Kb = sb + (uint32_t)(2 * FTILE) * 2;
    const uint32_t Vb = sb + (uint32_t)(4 * FTILE) * 2;

    const int tid = threadIdx.x, lane = tid & 31, w = tid >> 5;
    const int fr = lane >> 2, fc = lane & 3;
    const int bh = blockIdx.y;
    const int b = bh >> 4, h = bh & 15;
    const int q0 = blockIdx.x * 64;

    const __half* qbase = qkv + (size_t)(b * SEQ) * (3 * ID) + h * DHEAD;
    const __half* kbase = qbase + ID;
    const __half* vbase = qbase + 2 * ID;

    // Q fill: 64 rows x 64 halves = 512 chunks of 8 halves
    #pragma unroll
    for (int it = 0; it < 4; it++) {
        int idx = it * 128 + tid;
        int r = idx >> 3, sg = idx & 7;
        cp16(Qb + (uint32_t)(r * FPAD + sg * 8) * 2,
             qbase + (size_t)(q0 + r) * 3072 + sg * 8);
    }
    cp_commit();
    auto fillKV = [&](int c, int buf) {
        #pragma unroll
        for (int it = 0; it < 8; it++) {
            int idx = it * 128 + tid;
            int half_sel = idx >> 9;          // 0: K, 1: V
            int sub = idx & 511;
            int r = sub >> 3, sg = sub & 7;
            uint32_t base = half_sel ? Vb : Kb;
            const __half* src = half_sel ? vbase : kbase;
            cp16(base + (uint32_t)((buf * 64 + r) * FPAD + sg * 8) * 2,
                 src + (size_t)(c * 64 + r) * 3072 + sg * 8);
        }
    };
    fillKV(0, 0); cp_commit();

    cp_wait<0>();
    __syncthreads();

    // hoisted Q A-frags: 4 k16-chunks
    const uint32_t aRow = (uint32_t)((w * 16 + (lane & 15)) * FPAD
                                     + (lane >> 4) * 8) * 2;
    uint32_t qf[4][4];
    #pragma unroll
    for (int kc = 0; kc < 4; kc++)
        ldsm4(qf[kc][0], qf[kc][1], qf[kc][2], qf[kc][3], Qb + aRow + kc * 32);

    // K B-frag address (non-trans; rows = keys)
    const uint32_t kOff = (uint32_t)((((lane >> 4) & 1) * 8 + (lane & 7)) * FPAD
                                     + ((lane >> 3) & 1) * 8) * 2;
    // V B-frag address (trans; rows = keys, cols = d)
    const uint32_t vOff = (uint32_t)(((lane & 7) + ((lane >> 3) & 1) * 8) * FPAD
                                     + (lane >> 4) * 8) * 2;
    // P A-frag address
    const uint32_t pRow = aRow;   // same pattern, P tile at Pb

    float accO[8][4];
    #pragma unroll
    for (int nt = 0; nt < 8; nt++)
        #pragma unroll
        for (int q = 0; q < 4; q++) accO[nt][q] = 0.f;
    float M0 = -1e30f, M1 = -1e30f, L0 = 0.f, L1 = 0.f;

    const int prow0_off = (w * 16 + fr) * FPAD;

    for (int c = 0; c < SEQ / 64; c++) {
        if (c + 1 < SEQ / 64) { fillKV(c + 1, (c + 1) & 1); cp_commit(); }

        const uint32_t Kc = Kb + (uint32_t)((c & 1) * FTILE) * 2;
        const uint32_t Vc = Vb + (uint32_t)((c & 1) * FTILE) * 2;

        // ---- S = Q K^T ----
        float sacc[8][4];
        #pragma unroll
        for (int nt = 0; nt < 8; nt++)
            #pragma unroll
            for (int q = 0; q < 4; q++) sacc[nt][q] = 0.f;
        #pragma unroll
        for (int kc = 0; kc < 4; kc++) {
            uint32_t bf[8][2];
            #pragma unroll
            for (int ntp = 0; ntp < 4; ntp++)
                ldsm4(bf[2*ntp][0], bf[2*ntp][1], bf[2*ntp+1][0], bf[2*ntp+1][1],
                      Kc + kOff + kc * 32 + (uint32_t)(ntp * 16 * FPAD) * 2);
            #pragma unroll
            for (int nt = 0; nt < 8; nt++)
                mma_f16(sacc[nt], qf[kc], bf[nt]);
        }

        // ---- online softmax ----
        float mx0 = -1e30f, mx1 = -1e30f;
        #pragma unroll
        for (int nt = 0; nt < 8; nt++) {
            sacc[nt][0] *= 0.125f; sacc[nt][1] *= 0.125f;
            sacc[nt][2] *= 0.125f; sacc[nt][3] *= 0.125f;
            mx0 = fmaxf(mx0, fmaxf(sacc[nt][0], sacc[nt][1]));
            mx1 = fmaxf(mx1, fmaxf(sacc[nt][2], sacc[nt][3]));
        }
        mx0 = fmaxf(mx0, __shfl_xor_sync(0xffffffffu, mx0, 1));
        mx0 = fmaxf(mx0, __shfl_xor_sync(0xffffffffu, mx0, 2));
        mx1 = fmaxf(mx1, __shfl_xor_sync(0xffffffffu, mx1, 1));
        mx1 = fmaxf(mx1, __shfl_xor_sync(0xffffffffu, mx1, 2));
        float Mn0 = fmaxf(M0, mx0), Mn1 = fmaxf(M1, mx1);
        float a0 = __expf(M0 - Mn0), a1 = __expf(M1 - Mn1);
        float s0 = 0.f, s1 = 0.f;
        __half* Ph = smA + FTILE;
        #pragma unroll
        for (int nt = 0; nt < 8; nt++) {
            float p0 = __expf(sacc[nt][0] - Mn0), p1 = __expf(sacc[nt][1] - Mn0);
            float p2 = __expf(sacc[nt][2] - Mn1), p3 = __expf(sacc[nt][3] - Mn1);
            s0 += p0 + p1; s1 += p2 + p3;
            *(__half2*)(Ph + prow0_off + nt * 8 + 2 * fc) = __floats2half2_rn(p0, p1);
            *(__half2*)(Ph + prow0_off + 8 * FPAD + nt * 8 + 2 * fc) =
                __floats2half2_rn(p2, p3);
            accO[nt][0] *= a0; accO[nt][1] *= a0;
            accO[nt][2] *= a1; accO[nt][3] *= a1;
        }
        s0 += __shfl_xor_sync(0xffffffffu, s0, 1);
        s0 += __shfl_xor_sync(0xffffffffu, s0, 2);
        s1 += __shfl_xor_sync(0xffffffffu, s1, 1);
        s1 += __shfl_xor_sync(0xffffffffu, s1, 2);
        L0 = L0 * a0 + s0; L1 = L1 * a1 + s1;
        M0 = Mn0; M1 = Mn1;
        __syncwarp();

        // ---- O += P V  (V via trans ldmatrix) ----
        #pragma unroll
        for (int kc = 0; kc < 4; kc++) {
            uint32_t af[4], bf[8][2];
            ldsm4(af[0], af[1], af[2], af[3], Pb + pRow + kc * 32);
            #pragma unroll
            for (int ntp = 0; ntp < 4; ntp++)
                ldsm4t(bf[2*ntp][0], bf[2*ntp][1], bf[2*ntp+1][0], bf[2*ntp+1][1],
                       Vc + vOff + (uint32_t)(kc * 16 * FPAD) * 2 + ntp * 32);
            #pragma unroll
            for (int nt = 0; nt < 8; nt++)
                mma_f16(accO[nt], af, bf[nt]);
        }

        if (c + 1 < SEQ / 64) {
            cp_wait<0>();
            __syncthreads();
        }
    }

    float inv0 = 1.0f / L0, inv1 = 1.0f / L1;
    size_t t0 = (size_t)(b * SEQ + q0 + w * 16 + fr);
    #pragma unroll
    for (int nt = 0; nt < 8; nt++) {
        int col = h * DHEAD + nt * 8 + 2 * fc;
        *(__half2*)(o + t0 * ID + col) =
            __floats2half2_rn(accO[nt][0] * inv0, accO[nt][1] * inv0);
        *(__half2*)(o + (t0 + 8) * ID + col) =
            __floats2half2_rn(accO[nt][2] * inv1, accO[nt][3] * inv1);
    }
}

// ---------------- driver ----------------
extern "C" void kernel_launch(void* const* d_in, const int* in_sizes, int n_in,
                              void* d_out, int out_size)
{
    const float* x_in = (const float*)d_in[0];
    const float* ln1s = (const float*)d_in[1];
    const float* ln1b = (const float*)d_in[2];
    const float* wqkv = (const float*)d_in[3];
    const float* wout = (const float*)d_in[4];
    const float* bout = (const float*)d_in[5];
    const float* ln2s = (const float*)d_in[6];
    const float* ln2b = (const float*)d_in[7];
    const float* w1   = (const float*)d_in[8];
    const float* b1   = (const float*)d_in[9];
    const float* w2   = (const float*)d_in[10];
    const float* b2   = (const float*)d_in[11];
    float* x = (float*)d_out;

    void* p;
    cudaGetSymbolAddress(&p, g_h);   __half* gh   = (__half*)p;
    cudaGetSymbolAddress(&p, g_qkv); __half* gqkv = (__half*)p;
    cudaGetSymbolAddress(&p, g_o);   __half* go   = (__half*)p;
    cudaGetSymbolAddress(&p, g_a);   __half* ga   = (__half*)p;
    cudaGetSymbolAddress(&p, g_wh);  __half* gwh  = (__half*)p;

    __half* wh_qkv = gwh;
    __half* wh_out = wh_qkv + W_QKV_ELT;
    __half* wh_1   = wh_out + W_OUT_ELT;
    __half* wh_2   = wh_1   + W_1_ELT;

    cudaFuncSetAttribute(tc_gemmH<0>, cudaFuncAttributeMaxDynamicSharedMemorySize, QH_SMEM);
    cudaFuncSetAttribute(tc_gemmH<2>, cudaFuncAttributeMaxDynamicSharedMemorySize, QH_SMEM);
    cudaFuncSetAttribute(tc_gemm64H, cudaFuncAttributeMaxDynamicSharedMemorySize, GH_SMEM);
    cudaFuncSetAttribute(fattn_kernel, cudaFuncAttributeMaxDynamicSharedMemorySize, FA_SMEM);

    // convert + transpose all weights to fp16 [N][K]
    dim3 tb(32, 8);
    cvt_t_kernel<<<dim3(3*ID/32, DIM/32, LAYERS), tb>>>(wqkv, wh_qkv, DIM, 3*ID);
    cvt_t_kernel<<<dim3(DIM/32, ID/32, LAYERS), tb>>>(wout, wh_out, ID, DIM);
    cvt_t_kernel<<<dim3(FFN/32, DIM/32, LAYERS), tb>>>(w1, wh_1, DIM, FFN);
    cvt_t_kernel<<<dim3(DIM/32, FFN/32, LAYERS), tb>>>(w2, wh_2, FFN, DIM);

    cudaMemcpyAsync(x, x_in, (size_t)TOKENS * DIM * sizeof(float),
                    cudaMemcpyDeviceToDevice);

    for (int l = 0; l < LAYERS; l++) {
        const float* l1s = ln1s + l * DIM;
        const float* l1b = ln1b + l * DIM;
        const float* bo  = bout + l * DIM;
        const float* l2s = ln2s + l * DIM;
        const float* l2b = ln2b + l * DIM;
        const float* b1l = b1 + l * FFN;
        const float* b2l = b2 + l * DIM;
        const __half* wq  = wh_qkv + (size_t)l * DIM * 3 * ID;
        const __half* wo  = wh_out + (size_t)l * ID * DIM;
        const __half* w1l = wh_1 + (size_t)l * DIM * FFN;
        const __half* w2l = wh_2 + (size_t)l * FFN * DIM;

        // h = half(LN1(x))
        ln_kernel<<<TOKENS, 256>>>(x, l1s, l1b, gh);
        // qkv = half(h @ wqkv)
        tc_gemmH<0><<<dim3(3 * ID / 256, TOKENS / 64), 256, QH_SMEM>>>(
            gh, wq, nullptr, gqkv, 3 * ID, DIM);
        // attention (fp16 flash)
        fattn_kernel<<<dim3(SEQ / 64, BATCH * HEADS), 128, FA_SMEM>>>(gqkv, go);
        // x = x + o @ wo + bo
        tc_gemm64H<<<dim3(DIM / 128, TOKENS / 64), 256, GH_SMEM>>>(
            go, wo, bo, x, x, DIM, ID);
        // h = half(LN2(x))
        ln_kernel<<<TOKENS, 256>>>(x, l2s, l2b, gh);
        // a = half(gelu(h @ w1 + b1))
        tc_gemmH<2><<<dim3(FFN / 256, TOKENS / 64), 256, QH_SMEM>>>(
            gh, w1l, b1l, ga, FFN, DIM);
        // x = x + a @ w2 + b2
        tc_gemm64H<<<dim3(DIM / 128, TOKENS / 64), 256, GH_SMEM>>>(
            ga, w2l, b2l, x, x, DIM, FFN);
    }
}